// round 2
// baseline (speedup 1.0000x reference)
#include <cuda_runtime.h>
#include <cuda_bf16.h>
#include <math.h>

#define NNODE   50000
#define NEDGE   800000
#define ET      850000      // NEDGE + NNODE self loops
#define ECAND   200000
#define HEADS   4
#define FMAX    256

// ---------------- scratch (device globals; no allocation) ----------------
__device__ __align__(16) float  g_feat[NNODE * FMAX];   // activation input to layers 2,3
__device__ __align__(16) float  g_h[NNODE * FMAX];      // GEMM output (pre-aggregation)
__device__ __align__(16) float  g_out[NNODE * FMAX];    // aggregation accumulator
__device__ __align__(16) float  g_alpha_s[NNODE * 4];
__device__ __align__(16) float  g_alpha_d[NNODE * 4];
__device__ __align__(16) float  g_m[NNODE * 4];
__device__ __align__(16) float  g_denom[NNODE * 4];
__device__ __align__(16) float4 g_e[ET];                // per-edge e (pass A) then ex (pass B)
__device__ int    g_src[ET];
__device__ int    g_dst[ET];
__device__ __align__(16) float  g_z[NNODE * 32];
__device__ int    g_idx64_ei;    // 1 if edge_index is int64, 0 if int32
__device__ int    g_idx64_eli;   // same for edge_label_index

// ---------------- helpers ----------------
__device__ __forceinline__ float lrelu(float v) { return v > 0.f ? v : 0.2f * v; }

__device__ __forceinline__ void atomicMaxFloat(float* addr, float value) {
    if (value >= 0.f)
        atomicMax((int*)addr, __float_as_int(value));
    else
        atomicMin((unsigned int*)addr, __float_as_uint(value));
}

// ---------------- dtype detection (int64 vs int32 index tensors) ----------
// For int64 data with values < 2^31, every odd int32 word is the zero high
// half. For random int32 indices in [0,50000) the chance all 32 odd words
// are zero is ~0. Single thread, deterministic, graph-capturable.
__global__ void detect_dtype_kernel(const int* __restrict__ p, int* __restrict__ flag) {
    int ok = 1;
    #pragma unroll
    for (int i = 1; i < 64; i += 2)
        if (p[i] != 0) { ok = 0; break; }
    *flag = ok;
}

// ---------------- SGEMM: C[M,Nc] = A[M,K] @ B[K,Nc] ----------------
// BM=BN=64, BK=16, 256 threads, 4x4 per thread. K,Nc multiples of 16/64.
__global__ void sgemm_kernel(const float* __restrict__ A, const float* __restrict__ B,
                             float* __restrict__ C, int M, int Nc, int K) {
    __shared__ float As[16][65];
    __shared__ float Bs[16][64];
    const int tx = threadIdx.x & 15;
    const int ty = threadIdx.x >> 4;
    const int row0 = blockIdx.y * 64;
    const int col0 = blockIdx.x * 64;

    float acc[4][4] = {};
    for (int k0 = 0; k0 < K; k0 += 16) {
        #pragma unroll
        for (int i = 0; i < 4; i++) {
            int idx = threadIdx.x + i * 256;
            int k = idx & 15, m = idx >> 4;
            int gr = row0 + m;
            As[k][m] = (gr < M) ? A[(long)gr * K + k0 + k] : 0.f;
        }
        #pragma unroll
        for (int i = 0; i < 4; i++) {
            int idx = threadIdx.x + i * 256;
            int k = idx >> 6, n = idx & 63;
            Bs[k][n] = B[(long)(k0 + k) * Nc + col0 + n];
        }
        __syncthreads();
        #pragma unroll
        for (int kk = 0; kk < 16; kk++) {
            float a[4], b[4];
            #pragma unroll
            for (int i = 0; i < 4; i++) a[i] = As[kk][ty * 4 + i];
            #pragma unroll
            for (int j = 0; j < 4; j++) b[j] = Bs[kk][tx * 4 + j];
            #pragma unroll
            for (int i = 0; i < 4; i++)
                #pragma unroll
                for (int j = 0; j < 4; j++)
                    acc[i][j] += a[i] * b[j];
        }
        __syncthreads();
    }
    #pragma unroll
    for (int i = 0; i < 4; i++) {
        int gr = row0 + ty * 4 + i;
        if (gr < M) {
            #pragma unroll
            for (int j = 0; j < 4; j++)
                C[(long)gr * Nc + col0 + tx * 4 + j] = acc[i][j];
        }
    }
}

// ---------------- alpha_s / alpha_d per (node, head) ----------------
__global__ void calc_alpha_kernel(const float* __restrict__ a_s,
                                  const float* __restrict__ a_d, int C) {
    int t = blockIdx.x * blockDim.x + threadIdx.x;
    if (t >= NNODE * 4) return;
    int n = t >> 2, hh = t & 3;
    const float* hp = g_h + (long)n * (4 * C) + hh * C;
    const float* as = a_s + hh * C;
    const float* ad = a_d + hh * C;
    float ss = 0.f, sd = 0.f;
    for (int c = 0; c < C; c++) {
        float v = hp[c];
        ss += v * as[c];
        sd += v * ad[c];
    }
    g_alpha_s[t] = ss;
    g_alpha_d[t] = sd;
}

// ---------------- per-layer init: out=0, m=-inf, denom=0 ----------------
__global__ void init_kernel(int F) {
    int t = blockIdx.x * blockDim.x + threadIdx.x;
    int tot = NNODE * F;
    if (t < tot) g_out[t] = 0.f;
    if (t < NNODE * 4) {
        g_m[t] = -INFINITY;
        g_denom[t] = 0.f;
    }
}

// ---------------- pass A: e = lrelu(as[src]+ad[dst]); segment max ----------------
__global__ void edge_passA(const void* __restrict__ ei) {
    int e = blockIdx.x * blockDim.x + threadIdx.x;
    if (e >= ET) return;
    int src, dst;
    if (e < NEDGE) {
        if (g_idx64_ei) {
            const long long* p = (const long long*)ei;
            src = (int)p[e];
            dst = (int)p[NEDGE + e];
        } else {
            const int* p = (const int*)ei;
            src = p[e];
            dst = p[NEDGE + e];
        }
    } else {
        src = dst = e - NEDGE;
    }
    g_src[e] = src;
    g_dst[e] = dst;
    float4 a = ((const float4*)g_alpha_s)[src];
    float4 b = ((const float4*)g_alpha_d)[dst];
    float4 ee;
    ee.x = lrelu(a.x + b.x);
    ee.y = lrelu(a.y + b.y);
    ee.z = lrelu(a.z + b.z);
    ee.w = lrelu(a.w + b.w);
    g_e[e] = ee;
    float* mp = g_m + dst * 4;
    atomicMaxFloat(mp + 0, ee.x);
    atomicMaxFloat(mp + 1, ee.y);
    atomicMaxFloat(mp + 2, ee.z);
    atomicMaxFloat(mp + 3, ee.w);
}

// ---------------- pass B: ex = exp(e - m[dst]); segment sum ----------------
__global__ void edge_passB() {
    int e = blockIdx.x * blockDim.x + threadIdx.x;
    if (e >= ET) return;
    int dst = g_dst[e];
    float4 ee = g_e[e];
    float4 m4 = ((const float4*)g_m)[dst];
    float4 ex;
    ex.x = __expf(ee.x - m4.x);
    ex.y = __expf(ee.y - m4.y);
    ex.z = __expf(ee.z - m4.z);
    ex.w = __expf(ee.w - m4.w);
    g_e[e] = ex;
    float* dp = g_denom + dst * 4;
    atomicAdd(dp + 0, ex.x);
    atomicAdd(dp + 1, ex.y);
    atomicAdd(dp + 2, ex.z);
    atomicAdd(dp + 3, ex.w);
}

// ---------------- pass C: out[dst] += alpha * h[src] (warp per edge) ----------------
__global__ void edge_passC(int F, int C) {
    int w = (blockIdx.x * blockDim.x + threadIdx.x) >> 5;
    int lane = threadIdx.x & 31;
    if (w >= ET) return;
    int src = g_src[w], dst = g_dst[w];
    float4 ex = g_e[w];
    float4 dn = ((const float4*)g_denom)[dst];
    float al[4] = { ex.x / (dn.x + 1e-16f), ex.y / (dn.y + 1e-16f),
                    ex.z / (dn.z + 1e-16f), ex.w / (dn.w + 1e-16f) };
    const float4* hs = (const float4*)(g_h + (long)src * F);
    float* op = g_out + (long)dst * F;
    for (int f = lane * 4; f < F; f += 128) {
        float a = al[f / C];
        float4 v = hs[f >> 2];
        atomicAdd(op + f + 0, v.x * a);
        atomicAdd(op + f + 1, v.y * a);
        atomicAdd(op + f + 2, v.z * a);
        atomicAdd(op + f + 3, v.w * a);
    }
}

// ---------------- epilogue: feat = elu(out + b) ----------------
__global__ void epilogue_elu(const float* __restrict__ b, int F) {
    int t = blockIdx.x * blockDim.x + threadIdx.x;
    if (t >= NNODE * F) return;
    float v = g_out[t] + b[t % F];
    g_feat[t] = v > 0.f ? v : expm1f(v);
}

// ---------------- layer 3 finish: z = mean over heads + b3 ----------------
__global__ void mean_heads(const float* __restrict__ b3) {
    int t = blockIdx.x * blockDim.x + threadIdx.x;
    if (t >= NNODE * 32) return;
    int n = t >> 5, c = t & 31;
    const float* o = g_out + (long)n * 128;
    g_z[t] = 0.25f * (o[c] + o[32 + c] + o[64 + c] + o[96 + c]) + b3[c];
}

// ---------------- logits: dot over 32 dims, warp per candidate edge ----------------
__global__ void dot_kernel(const void* __restrict__ eli, float* __restrict__ out) {
    int w = (blockIdx.x * blockDim.x + threadIdx.x) >> 5;
    int lane = threadIdx.x & 31;
    if (w >= ECAND) return;
    int s, d;
    if (g_idx64_eli) {
        const long long* p = (const long long*)eli;
        s = (int)p[w];
        d = (int)p[ECAND + w];
    } else {
        const int* p = (const int*)eli;
        s = p[w];
        d = p[ECAND + w];
    }
    float p = g_z[(long)s * 32 + lane] * g_z[(long)d * 32 + lane];
    #pragma unroll
    for (int o = 16; o; o >>= 1) p += __shfl_xor_sync(0xffffffffu, p, o);
    if (lane == 0) out[w] = p;
}

// ---------------- host launch ----------------
extern "C" void kernel_launch(void* const* d_in, const int* in_sizes, int n_in,
                              void* d_out, int out_size) {
    const float* x   = (const float*)d_in[0];
    const void*  ei  = d_in[1];
    const void*  eli = d_in[2];
    const float* W1  = (const float*)d_in[3];
    const float* a1s = (const float*)d_in[4];
    const float* a1d = (const float*)d_in[5];
    const float* b1  = (const float*)d_in[6];
    const float* W2  = (const float*)d_in[7];
    const float* a2s = (const float*)d_in[8];
    const float* a2d = (const float*)d_in[9];
    const float* b2  = (const float*)d_in[10];
    const float* W3  = (const float*)d_in[11];
    const float* a3s = (const float*)d_in[12];
    const float* a3d = (const float*)d_in[13];
    const float* b3  = (const float*)d_in[14];
    float* out = (float*)d_out;

    float *p_feat, *p_h;
    cudaGetSymbolAddress((void**)&p_feat, g_feat);
    cudaGetSymbolAddress((void**)&p_h, g_h);
    int *p_f_ei, *p_f_eli;
    cudaGetSymbolAddress((void**)&p_f_ei, g_idx64_ei);
    cudaGetSymbolAddress((void**)&p_f_eli, g_idx64_eli);

    const int TB = 256;
    const int edgeBlocks  = (ET + TB - 1) / TB;
    const int warpBlocksC = (ET * 32 + TB - 1) / TB;

    detect_dtype_kernel<<<1, 1>>>((const int*)ei, p_f_ei);
    detect_dtype_kernel<<<1, 1>>>((const int*)eli, p_f_eli);

    auto run_layer = [&](const float* A, const float* W, const float* as,
                         const float* ad, int K, int F, int C) {
        dim3 ggrid(F / 64, (NNODE + 63) / 64);
        sgemm_kernel<<<ggrid, 256>>>(A, W, p_h, NNODE, F, K);
        calc_alpha_kernel<<<(NNODE * 4 + TB - 1) / TB, TB>>>(as, ad, C);
        init_kernel<<<(NNODE * F + TB - 1) / TB, TB>>>(F);
        edge_passA<<<edgeBlocks, TB>>>(ei);
        edge_passB<<<edgeBlocks, TB>>>();
        edge_passC<<<warpBlocksC, TB>>>(F, C);
    };

    // Layer 1: 384 -> 4x64, concat -> 256, elu
    run_layer(x, W1, a1s, a1d, 384, 256, 64);
    epilogue_elu<<<(NNODE * 256 + TB - 1) / TB, TB>>>(b1, 256);

    // Layer 2: 256 -> 4x16, concat -> 64, elu
    run_layer(p_feat, W2, a2s, a2d, 256, 64, 16);
    epilogue_elu<<<(NNODE * 64 + TB - 1) / TB, TB>>>(b2, 64);

    // Layer 3: 64 -> 4x32, mean over heads -> 32
    run_layer(p_feat, W3, a3s, a3d, 64, 128, 32);
    mean_heads<<<(NNODE * 32 + TB - 1) / TB, TB>>>(b3);

    // Candidate-edge logits
    dot_kernel<<<(ECAND * 32 + TB - 1) / TB, TB>>>(eli, out);
}

// round 3
// speedup vs baseline: 2.1884x; 2.1884x over previous
#include <cuda_runtime.h>
#include <cuda_bf16.h>
#include <math.h>

#define NNODE   50000
#define NEDGE   800000
#define ET      850000      // NEDGE + NNODE self loops
#define ECAND   200000
#define FMAX    256

// ---------------- scratch (device globals; no allocation) ----------------
__device__ __align__(16) float  g_feat[NNODE * FMAX];  // activations into layers 2,3
__device__ __align__(16) float  g_h[NNODE * FMAX];     // GEMM output
__device__ __align__(16) float  g_out[NNODE * FMAX];   // layer-3 raw output
__device__ float4 g_alpha_s[NNODE];
__device__ float4 g_alpha_d[NNODE];
__device__ float4 g_denom[NNODE];
__device__ float4 g_e[ET];           // per-edge e -> ex (CSR order)
__device__ int    g_esrc[ET];        // CSR: src node per edge, sorted by dst
__device__ int    g_rowoff[NNODE + 1];
__device__ int    g_cnt[NNODE];
__device__ int    g_cursor[NNODE];
__device__ __align__(16) float g_z[NNODE * 32];
__device__ int    g_idx64_ei;
__device__ int    g_idx64_eli;

// ---------------- helpers ----------------
__device__ __forceinline__ float lrelu(float v) { return v > 0.f ? v : 0.2f * v; }

__device__ __forceinline__ float sel4(float4 v, int h) {
    return h < 2 ? (h == 0 ? v.x : v.y) : (h == 2 ? v.z : v.w);
}

__device__ __forceinline__ int load_idx(const void* p, int use64, long long pos) {
    return use64 ? (int)((const long long*)p)[pos] : ((const int*)p)[pos];
}

// ---------------- dtype detection (int64 vs int32 index tensors) ----------
__global__ void detect_dtype_kernel(const int* __restrict__ p, int* __restrict__ flag) {
    int ok = 1;
    #pragma unroll
    for (int i = 1; i < 64; i += 2)
        if (p[i] != 0) { ok = 0; break; }
    *flag = ok;
}

// ================= CSR build =================
__global__ void hist_init() {
    int i = blockIdx.x * blockDim.x + threadIdx.x;
    if (i < NNODE) g_cnt[i] = 1;   // self loop pre-counted
}

__global__ void hist_edges(const void* __restrict__ ei) {
    int e = blockIdx.x * blockDim.x + threadIdx.x;
    if (e >= NEDGE) return;
    int dst = load_idx(ei, g_idx64_ei, (long long)NEDGE + e);
    atomicAdd(&g_cnt[dst], 1);
}

// single-block exclusive scan over g_cnt -> g_rowoff; cursor = rowoff+1;
// self loop placed at row start.
__global__ void scan_kernel() {
    __shared__ int warp_sums[32];
    __shared__ int carry_s;
    const int tid = threadIdx.x;
    const int lane = tid & 31, wid = tid >> 5;
    if (tid == 0) carry_s = 0;
    __syncthreads();
    for (int base = 0; base < NNODE; base += 1024) {
        int i = base + tid;
        int v = (i < NNODE) ? g_cnt[i] : 0;
        int x = v;
        #pragma unroll
        for (int o = 1; o < 32; o <<= 1) {
            int y = __shfl_up_sync(0xffffffffu, x, o);
            if (lane >= o) x += y;
        }
        if (lane == 31) warp_sums[wid] = x;
        __syncthreads();
        if (wid == 0) {
            int s = warp_sums[lane];
            #pragma unroll
            for (int o = 1; o < 32; o <<= 1) {
                int y = __shfl_up_sync(0xffffffffu, s, o);
                if (lane >= o) s += y;
            }
            warp_sums[lane] = s;
        }
        __syncthreads();
        int add = (wid > 0) ? warp_sums[wid - 1] : 0;
        int incl = x + add;
        int carry = carry_s;
        if (i < NNODE) {
            int ex = carry + incl - v;
            g_rowoff[i] = ex;
            g_cursor[i] = ex + 1;   // slot 0 of each row = self loop
            g_esrc[ex] = i;
        }
        __syncthreads();
        if (tid == 0) carry_s = carry + warp_sums[31];
        __syncthreads();
    }
    if (tid == 0) g_rowoff[NNODE] = carry_s;
}

__global__ void scatter_edges(const void* __restrict__ ei) {
    int e = blockIdx.x * blockDim.x + threadIdx.x;
    if (e >= NEDGE) return;
    int use64 = g_idx64_ei;
    int src = load_idx(ei, use64, e);
    int dst = load_idx(ei, use64, (long long)NEDGE + e);
    int pos = atomicAdd(&g_cursor[dst], 1);
    g_esrc[pos] = src;
}

// ---------------- SGEMM: C[M,Nc] = A[M,K] @ B[K,Nc] ----------------
__global__ void sgemm_kernel(const float* __restrict__ A, const float* __restrict__ B,
                             float* __restrict__ C, int M, int Nc, int K) {
    __shared__ float As[16][65];
    __shared__ float Bs[16][64];
    const int tx = threadIdx.x & 15;
    const int ty = threadIdx.x >> 4;
    const int row0 = blockIdx.y * 64;
    const int col0 = blockIdx.x * 64;

    float acc[4][4] = {};
    for (int k0 = 0; k0 < K; k0 += 16) {
        #pragma unroll
        for (int i = 0; i < 4; i++) {
            int idx = threadIdx.x + i * 256;
            int k = idx & 15, m = idx >> 4;
            int gr = row0 + m;
            As[k][m] = (gr < M) ? A[(long)gr * K + k0 + k] : 0.f;
        }
        #pragma unroll
        for (int i = 0; i < 4; i++) {
            int idx = threadIdx.x + i * 256;
            int k = idx >> 6, n = idx & 63;
            Bs[k][n] = B[(long)(k0 + k) * Nc + col0 + n];
        }
        __syncthreads();
        #pragma unroll
        for (int kk = 0; kk < 16; kk++) {
            float a[4], b[4];
            #pragma unroll
            for (int i = 0; i < 4; i++) a[i] = As[kk][ty * 4 + i];
            #pragma unroll
            for (int j = 0; j < 4; j++) b[j] = Bs[kk][tx * 4 + j];
            #pragma unroll
            for (int i = 0; i < 4; i++)
                #pragma unroll
                for (int j = 0; j < 4; j++)
                    acc[i][j] += a[i] * b[j];
        }
        __syncthreads();
    }
    #pragma unroll
    for (int i = 0; i < 4; i++) {
        int gr = row0 + ty * 4 + i;
        if (gr < M) {
            #pragma unroll
            for (int j = 0; j < 4; j++)
                C[(long)gr * Nc + col0 + tx * 4 + j] = acc[i][j];
        }
    }
}

// ---------------- alpha_s / alpha_d: warp per node, coalesced ----------------
template <int F, int C>
__global__ void calc_alpha2(const float* __restrict__ a_s, const float* __restrict__ a_d) {
    int w = (blockIdx.x * blockDim.x + threadIdx.x) >> 5;
    int lane = threadIdx.x & 31;
    if (w >= NNODE) return;
    const float4* hp  = (const float4*)(g_h + (long)w * F);
    const float4* as4 = (const float4*)a_s;
    const float4* ad4 = (const float4*)a_d;
    float s0 = 0, s1 = 0, s2 = 0, s3 = 0;
    float d0 = 0, d1 = 0, d2 = 0, d3 = 0;
    #pragma unroll
    for (int f4 = lane; f4 < F / 4; f4 += 32) {
        float4 hv = hp[f4];
        float4 sv = as4[f4];
        float4 dv = ad4[f4];
        float ps = hv.x * sv.x + hv.y * sv.y + hv.z * sv.z + hv.w * sv.w;
        float pd = hv.x * dv.x + hv.y * dv.y + hv.z * dv.z + hv.w * dv.w;
        int head = (f4 * 4) / C;
        if (head == 0)      { s0 += ps; d0 += pd; }
        else if (head == 1) { s1 += ps; d1 += pd; }
        else if (head == 2) { s2 += ps; d2 += pd; }
        else                { s3 += ps; d3 += pd; }
    }
    #pragma unroll
    for (int o = 16; o; o >>= 1) {
        s0 += __shfl_xor_sync(0xffffffffu, s0, o);
        s1 += __shfl_xor_sync(0xffffffffu, s1, o);
        s2 += __shfl_xor_sync(0xffffffffu, s2, o);
        s3 += __shfl_xor_sync(0xffffffffu, s3, o);
        d0 += __shfl_xor_sync(0xffffffffu, d0, o);
        d1 += __shfl_xor_sync(0xffffffffu, d1, o);
        d2 += __shfl_xor_sync(0xffffffffu, d2, o);
        d3 += __shfl_xor_sync(0xffffffffu, d3, o);
    }
    if (lane == 0) {
        g_alpha_s[w] = make_float4(s0, s1, s2, s3);
        g_alpha_d[w] = make_float4(d0, d1, d2, d3);
    }
}

// ---------------- E1: per-dst softmax (warp per dst, no atomics) ----------------
__global__ void edge_softmax() {
    int dstN = (blockIdx.x * blockDim.x + threadIdx.x) >> 5;
    int lane = threadIdx.x & 31;
    if (dstN >= NNODE) return;
    int r0 = g_rowoff[dstN];
    int r1 = g_rowoff[dstN + 1];
    float4 ad = g_alpha_d[dstN];

    float m0 = -INFINITY, m1 = -INFINITY, m2 = -INFINITY, m3 = -INFINITY;
    for (int e = r0 + lane; e < r1; e += 32) {
        int src = g_esrc[e];
        float4 s = g_alpha_s[src];
        float4 ee = make_float4(lrelu(s.x + ad.x), lrelu(s.y + ad.y),
                                lrelu(s.z + ad.z), lrelu(s.w + ad.w));
        g_e[e] = ee;
        m0 = fmaxf(m0, ee.x); m1 = fmaxf(m1, ee.y);
        m2 = fmaxf(m2, ee.z); m3 = fmaxf(m3, ee.w);
    }
    #pragma unroll
    for (int o = 16; o; o >>= 1) {
        m0 = fmaxf(m0, __shfl_xor_sync(0xffffffffu, m0, o));
        m1 = fmaxf(m1, __shfl_xor_sync(0xffffffffu, m1, o));
        m2 = fmaxf(m2, __shfl_xor_sync(0xffffffffu, m2, o));
        m3 = fmaxf(m3, __shfl_xor_sync(0xffffffffu, m3, o));
    }
    float x0 = 0, x1 = 0, x2 = 0, x3 = 0;
    for (int e = r0 + lane; e < r1; e += 32) {
        float4 ee = g_e[e];
        float4 ex = make_float4(__expf(ee.x - m0), __expf(ee.y - m1),
                                __expf(ee.z - m2), __expf(ee.w - m3));
        g_e[e] = ex;
        x0 += ex.x; x1 += ex.y; x2 += ex.z; x3 += ex.w;
    }
    #pragma unroll
    for (int o = 16; o; o >>= 1) {
        x0 += __shfl_xor_sync(0xffffffffu, x0, o);
        x1 += __shfl_xor_sync(0xffffffffu, x1, o);
        x2 += __shfl_xor_sync(0xffffffffu, x2, o);
        x3 += __shfl_xor_sync(0xffffffffu, x3, o);
    }
    if (lane == 0) g_denom[dstN] = make_float4(x0, x1, x2, x3);
}

// ---------------- E2: aggregation (warp per dst) + fused epilogue ----------------
// ELU: out = elu(agg + bias) -> dstbuf ; else raw agg -> dstbuf
template <int F, int C, bool ELU>
__global__ void edge_aggregate(const float* __restrict__ bias, float* __restrict__ dstbuf) {
    int dstN = (blockIdx.x * blockDim.x + threadIdx.x) >> 5;
    int lane = threadIdx.x & 31;
    if (dstN >= NNODE) return;
    int r0 = g_rowoff[dstN];
    int r1 = g_rowoff[dstN + 1];
    float4 dn = g_denom[dstN];
    float4 inv = make_float4(1.f / (dn.x + 1e-16f), 1.f / (dn.y + 1e-16f),
                             1.f / (dn.z + 1e-16f), 1.f / (dn.w + 1e-16f));

    if (F == 64) {
        // float2 per lane at f = lane*2
        int f = lane * 2;
        int head = f / C;
        float a0 = 0, a1 = 0;
        for (int e = r0; e < r1; e++) {
            int src = g_esrc[e];
            float al = sel4(g_e[e], head);
            const float2 hv = *(const float2*)(g_h + (long)src * F + f);
            a0 += hv.x * al; a1 += hv.y * al;
        }
        float iv = sel4(inv, head);
        a0 *= iv; a1 *= iv;
        if (ELU) {
            a0 += bias[f]; a1 += bias[f + 1];
            a0 = a0 > 0.f ? a0 : expm1f(a0);
            a1 = a1 > 0.f ? a1 : expm1f(a1);
        }
        *(float2*)(dstbuf + (long)dstN * F + f) = make_float2(a0, a1);
    } else {
        // float4 chunks at f = lane*4 (+128 for F=256)
        const int NCH = F / 128;   // 1 or 2
        float4 acc[NCH == 0 ? 1 : NCH];
        int heads[NCH == 0 ? 1 : NCH];
        #pragma unroll
        for (int c = 0; c < NCH; c++) {
            acc[c] = make_float4(0, 0, 0, 0);
            heads[c] = (lane * 4 + c * 128) / C;
        }
        for (int e = r0; e < r1; e++) {
            int src = g_esrc[e];
            float4 alv = g_e[e];
            const float4* hp = (const float4*)(g_h + (long)src * F);
            #pragma unroll
            for (int c = 0; c < NCH; c++) {
                float al = sel4(alv, heads[c]);
                float4 hv = hp[lane + c * 32];
                acc[c].x += hv.x * al; acc[c].y += hv.y * al;
                acc[c].z += hv.z * al; acc[c].w += hv.w * al;
            }
        }
        #pragma unroll
        for (int c = 0; c < NCH; c++) {
            int f = lane * 4 + c * 128;
            float iv = sel4(inv, heads[c]);
            float4 r = acc[c];
            r.x *= iv; r.y *= iv; r.z *= iv; r.w *= iv;
            if (ELU) {
                r.x += bias[f];     r.y += bias[f + 1];
                r.z += bias[f + 2]; r.w += bias[f + 3];
                r.x = r.x > 0.f ? r.x : expm1f(r.x);
                r.y = r.y > 0.f ? r.y : expm1f(r.y);
                r.z = r.z > 0.f ? r.z : expm1f(r.z);
                r.w = r.w > 0.f ? r.w : expm1f(r.w);
            }
            *(float4*)(dstbuf + (long)dstN * F + f) = r;
        }
    }
}

// ---------------- layer 3 finish: z = mean over heads + b3 ----------------
__global__ void mean_heads(const float* __restrict__ b3) {
    int t = blockIdx.x * blockDim.x + threadIdx.x;
    if (t >= NNODE * 32) return;
    int n = t >> 5, c = t & 31;
    const float* o = g_out + (long)n * 128;
    g_z[t] = 0.25f * (o[c] + o[32 + c] + o[64 + c] + o[96 + c]) + b3[c];
}

// ---------------- logits: dot over 32 dims, warp per candidate edge ----------------
__global__ void dot_kernel(const void* __restrict__ eli, float* __restrict__ out) {
    int w = (blockIdx.x * blockDim.x + threadIdx.x) >> 5;
    int lane = threadIdx.x & 31;
    if (w >= ECAND) return;
    int use64 = g_idx64_eli;
    int s = load_idx(eli, use64, w);
    int d = load_idx(eli, use64, (long long)ECAND + w);
    float p = g_z[(long)s * 32 + lane] * g_z[(long)d * 32 + lane];
    #pragma unroll
    for (int o = 16; o; o >>= 1) p += __shfl_xor_sync(0xffffffffu, p, o);
    if (lane == 0) out[w] = p;
}

// ---------------- host launch ----------------
extern "C" void kernel_launch(void* const* d_in, const int* in_sizes, int n_in,
                              void* d_out, int out_size) {
    const float* x   = (const float*)d_in[0];
    const void*  ei  = d_in[1];
    const void*  eli = d_in[2];
    const float* W1  = (const float*)d_in[3];
    const float* a1s = (const float*)d_in[4];
    const float* a1d = (const float*)d_in[5];
    const float* b1  = (const float*)d_in[6];
    const float* W2  = (const float*)d_in[7];
    const float* a2s = (const float*)d_in[8];
    const float* a2d = (const float*)d_in[9];
    const float* b2  = (const float*)d_in[10];
    const float* W3  = (const float*)d_in[11];
    const float* a3s = (const float*)d_in[12];
    const float* a3d = (const float*)d_in[13];
    const float* b3  = (const float*)d_in[14];
    float* out = (float*)d_out;

    float *p_feat, *p_h, *p_out;
    cudaGetSymbolAddress((void**)&p_feat, g_feat);
    cudaGetSymbolAddress((void**)&p_h, g_h);
    cudaGetSymbolAddress((void**)&p_out, g_out);
    int *p_f_ei, *p_f_eli;
    cudaGetSymbolAddress((void**)&p_f_ei, g_idx64_ei);
    cudaGetSymbolAddress((void**)&p_f_eli, g_idx64_eli);

    const int TB = 256;
    const int nodeWarpBlocks = (NNODE * 32 + TB - 1) / TB;   // warp per node

    detect_dtype_kernel<<<1, 1>>>((const int*)ei, p_f_ei);
    detect_dtype_kernel<<<1, 1>>>((const int*)eli, p_f_eli);

    // ---- CSR build (once; shared by all 3 layers) ----
    hist_init<<<(NNODE + TB - 1) / TB, TB>>>();
    hist_edges<<<(NEDGE + TB - 1) / TB, TB>>>(ei);
    scan_kernel<<<1, 1024>>>();
    scatter_edges<<<(NEDGE + TB - 1) / TB, TB>>>(ei);

    // ---- Layer 1: 384 -> 4x64, concat 256, elu ----
    sgemm_kernel<<<dim3(4, (NNODE + 63) / 64), 256>>>(x, W1, p_h, NNODE, 256, 384);
    calc_alpha2<256, 64><<<nodeWarpBlocks, TB>>>(a1s, a1d);
    edge_softmax<<<nodeWarpBlocks, TB>>>();
    edge_aggregate<256, 64, true><<<nodeWarpBlocks, TB>>>(b1, p_feat);

    // ---- Layer 2: 256 -> 4x16, concat 64, elu ----
    sgemm_kernel<<<dim3(1, (NNODE + 63) / 64), 256>>>(p_feat, W2, p_h, NNODE, 64, 256);
    calc_alpha2<64, 16><<<nodeWarpBlocks, TB>>>(a2s, a2d);
    edge_softmax<<<nodeWarpBlocks, TB>>>();
    edge_aggregate<64, 16, true><<<nodeWarpBlocks, TB>>>(b2, p_feat);

    // ---- Layer 3: 64 -> 4x32, mean heads -> 32 ----
    sgemm_kernel<<<dim3(2, (NNODE + 63) / 64), 256>>>(p_feat, W3, p_h, NNODE, 128, 64);
    calc_alpha2<128, 32><<<nodeWarpBlocks, TB>>>(a3s, a3d);
    edge_softmax<<<nodeWarpBlocks, TB>>>();
    edge_aggregate<128, 32, false><<<nodeWarpBlocks, TB>>>(nullptr, p_out);
    mean_heads<<<(NNODE * 32 + TB - 1) / TB, TB>>>(b3);

    // ---- Candidate-edge logits ----
    dot_kernel<<<(ECAND * 32 + TB - 1) / TB, TB>>>(eli, out);
}

// round 4
// speedup vs baseline: 2.9867x; 1.3648x over previous
#include <cuda_runtime.h>
#include <cuda_bf16.h>
#include <math.h>
#include <stdint.h>

#define NNODE   50000
#define NEDGE   800000
#define ET      850000      // NEDGE + NNODE self loops
#define ECAND   200000
#define FMAX    256

// ---------------- scratch (device globals; no allocation) ----------------
__device__ __align__(16) float  g_feat[NNODE * FMAX];  // activations into layers 2,3
__device__ __align__(16) float  g_h[NNODE * FMAX];     // GEMM output
__device__ __align__(16) float  g_out[NNODE * FMAX];   // layer-3 raw output
__device__ float4 g_alpha_s[NNODE];
__device__ float4 g_alpha_d[NNODE];
__device__ float4 g_denom[NNODE];
__device__ float4 g_e[ET];           // per-edge e -> ex (CSR order)
__device__ int    g_esrc[ET];        // CSR: src node per edge, sorted by dst
__device__ int    g_rowoff[NNODE + 1];
__device__ int    g_cnt[NNODE];
__device__ int    g_cursor[NNODE];
__device__ __align__(16) float g_z[NNODE * 32];
__device__ int    g_idx64_ei;
__device__ int    g_idx64_eli;

// ---------------- helpers ----------------
__device__ __forceinline__ float lrelu(float v) { return v > 0.f ? v : 0.2f * v; }

__device__ __forceinline__ float sel4(float4 v, int h) {
    return h < 2 ? (h == 0 ? v.x : v.y) : (h == 2 ? v.z : v.w);
}

__device__ __forceinline__ int load_idx(const void* p, int use64, long long pos) {
    return use64 ? (int)((const long long*)p)[pos] : ((const int*)p)[pos];
}

__device__ __forceinline__ void cvt_split(float v, __nv_bfloat16& h, __nv_bfloat16& l) {
    h = __float2bfloat16(v);
    l = __float2bfloat16(v - __bfloat162float(h));
}

// ---------------- dtype detection (int64 vs int32 index tensors) ----------
__global__ void detect_dtype_kernel(const int* __restrict__ p, int* __restrict__ flag) {
    int ok = 1;
    #pragma unroll
    for (int i = 1; i < 64; i += 2)
        if (p[i] != 0) { ok = 0; break; }
    *flag = ok;
}

// ================= CSR build =================
__global__ void hist_init() {
    int i = blockIdx.x * blockDim.x + threadIdx.x;
    if (i < NNODE) g_cnt[i] = 1;   // self loop pre-counted
}

__global__ void hist_edges(const void* __restrict__ ei) {
    int e = blockIdx.x * blockDim.x + threadIdx.x;
    if (e >= NEDGE) return;
    int dst = load_idx(ei, g_idx64_ei, (long long)NEDGE + e);
    atomicAdd(&g_cnt[dst], 1);
}

__global__ void scan_kernel() {
    __shared__ int warp_sums[32];
    __shared__ int carry_s;
    const int tid = threadIdx.x;
    const int lane = tid & 31, wid = tid >> 5;
    if (tid == 0) carry_s = 0;
    __syncthreads();
    for (int base = 0; base < NNODE; base += 1024) {
        int i = base + tid;
        int v = (i < NNODE) ? g_cnt[i] : 0;
        int x = v;
        #pragma unroll
        for (int o = 1; o < 32; o <<= 1) {
            int y = __shfl_up_sync(0xffffffffu, x, o);
            if (lane >= o) x += y;
        }
        if (lane == 31) warp_sums[wid] = x;
        __syncthreads();
        if (wid == 0) {
            int s = warp_sums[lane];
            #pragma unroll
            for (int o = 1; o < 32; o <<= 1) {
                int y = __shfl_up_sync(0xffffffffu, s, o);
                if (lane >= o) s += y;
            }
            warp_sums[lane] = s;
        }
        __syncthreads();
        int add = (wid > 0) ? warp_sums[wid - 1] : 0;
        int incl = x + add;
        int carry = carry_s;
        if (i < NNODE) {
            int ex = carry + incl - v;
            g_rowoff[i] = ex;
            g_cursor[i] = ex + 1;   // slot 0 of each row = self loop
            g_esrc[ex] = i;
        }
        __syncthreads();
        if (tid == 0) carry_s = carry + warp_sums[31];
        __syncthreads();
    }
    if (tid == 0) g_rowoff[NNODE] = carry_s;
}

__global__ void scatter_edges(const void* __restrict__ ei) {
    int e = blockIdx.x * blockDim.x + threadIdx.x;
    if (e >= NEDGE) return;
    int use64 = g_idx64_ei;
    int src = load_idx(ei, use64, e);
    int dst = load_idx(ei, use64, (long long)NEDGE + e);
    int pos = atomicAdd(&g_cursor[dst], 1);
    g_esrc[pos] = src;
}

// ================= split-bf16 tensor-core GEMM =================
// C[M,N] = A[M,K] @ B[K,N], fp32 in/out, 3x mma.sync bf16 (hi*hi+hi*lo+lo*hi).
// BM=128, BN=64, BK=32, 256 threads = 8 warps (4 along M x 2 along N),
// warp tile 32x32 = 2 m-frags x 4 n-frags of m16n8k16.
#define BKP 40   // BK + 8 pad (stride 20 words: conflict-free)

__device__ __forceinline__ void mma16816(float* c, const uint32_t* a, const uint32_t* b) {
    asm volatile(
        "mma.sync.aligned.m16n8k16.row.col.f32.bf16.bf16.f32 "
        "{%0,%1,%2,%3}, {%4,%5,%6,%7}, {%8,%9}, {%0,%1,%2,%3};\n"
        : "+f"(c[0]), "+f"(c[1]), "+f"(c[2]), "+f"(c[3])
        : "r"(a[0]), "r"(a[1]), "r"(a[2]), "r"(a[3]), "r"(b[0]), "r"(b[1]));
}

__global__ __launch_bounds__(256) void gemm_tc(const float* __restrict__ A,
                                               const float* __restrict__ B,
                                               float* __restrict__ C,
                                               int M, int N, int K) {
    __shared__ __nv_bfloat16 Ah[128][BKP], Al[128][BKP];
    __shared__ __nv_bfloat16 Bh[64][BKP],  Bl[64][BKP];

    const int tid  = threadIdx.x;
    const int lane = tid & 31;
    const int warp = tid >> 5;
    const int wm   = warp & 3;    // m-warp: 32 rows each
    const int wn   = warp >> 2;   // n-warp: 32 cols each
    const int tr   = lane >> 2;   // 0..7
    const int tc   = lane & 3;    // 0..3
    const int row0 = blockIdx.y * 128;
    const int col0 = blockIdx.x * 64;

    float acc[2][4][4] = {};

    for (int k0 = 0; k0 < K; k0 += 32) {
        // ---- stage A tile (128x32 fp32 -> hi/lo bf16) ----
        #pragma unroll
        for (int i = 0; i < 4; i++) {
            int idx = tid + i * 256;          // 0..1023 float4 slots
            int row = idx >> 3, c4 = idx & 7; // c4: which float4 in the 32-wide row
            int gr = row0 + row;
            float4 v = make_float4(0.f, 0.f, 0.f, 0.f);
            if (gr < M) v = *(const float4*)&A[(long)gr * K + k0 + c4 * 4];
            __nv_bfloat16 h0, h1, h2, h3, l0, l1, l2, l3;
            cvt_split(v.x, h0, l0); cvt_split(v.y, h1, l1);
            cvt_split(v.z, h2, l2); cvt_split(v.w, h3, l3);
            *(__nv_bfloat162*)&Ah[row][c4 * 4]     = __nv_bfloat162(h0, h1);
            *(__nv_bfloat162*)&Ah[row][c4 * 4 + 2] = __nv_bfloat162(h2, h3);
            *(__nv_bfloat162*)&Al[row][c4 * 4]     = __nv_bfloat162(l0, l1);
            *(__nv_bfloat162*)&Al[row][c4 * 4 + 2] = __nv_bfloat162(l2, l3);
        }
        // ---- stage B tile (32x64 fp32 -> transposed hi/lo bf16 [n][k]) ----
        #pragma unroll
        for (int i = 0; i < 4; i++) {
            int idx = tid + i * 256;          // 0..1023: (kpair, n)
            int n = idx & 63;
            int kp = (idx >> 6) * 2;          // even k
            float v0 = B[(long)(k0 + kp) * N + col0 + n];
            float v1 = B[(long)(k0 + kp + 1) * N + col0 + n];
            __nv_bfloat16 h0, h1, l0, l1;
            cvt_split(v0, h0, l0); cvt_split(v1, h1, l1);
            *(__nv_bfloat162*)&Bh[n][kp] = __nv_bfloat162(h0, h1);
            *(__nv_bfloat162*)&Bl[n][kp] = __nv_bfloat162(l0, l1);
        }
        __syncthreads();

        // ---- compute: 2 k-steps of 16 ----
        #pragma unroll
        for (int ks = 0; ks < 32; ks += 16) {
            uint32_t ah[2][4], al[2][4], bh[4][2], bl[4][2];
            #pragma unroll
            for (int f = 0; f < 2; f++) {
                int r = wm * 32 + f * 16 + tr;
                int kk = ks + tc * 2;
                ah[f][0] = *(const uint32_t*)&Ah[r][kk];
                ah[f][1] = *(const uint32_t*)&Ah[r + 8][kk];
                ah[f][2] = *(const uint32_t*)&Ah[r][kk + 8];
                ah[f][3] = *(const uint32_t*)&Ah[r + 8][kk + 8];
                al[f][0] = *(const uint32_t*)&Al[r][kk];
                al[f][1] = *(const uint32_t*)&Al[r + 8][kk];
                al[f][2] = *(const uint32_t*)&Al[r][kk + 8];
                al[f][3] = *(const uint32_t*)&Al[r + 8][kk + 8];
            }
            #pragma unroll
            for (int g = 0; g < 4; g++) {
                int n = wn * 32 + g * 8 + tr;
                int kk = ks + tc * 2;
                bh[g][0] = *(const uint32_t*)&Bh[n][kk];
                bh[g][1] = *(const uint32_t*)&Bh[n][kk + 8];
                bl[g][0] = *(const uint32_t*)&Bl[n][kk];
                bl[g][1] = *(const uint32_t*)&Bl[n][kk + 8];
            }
            #pragma unroll
            for (int f = 0; f < 2; f++)
                #pragma unroll
                for (int g = 0; g < 4; g++) {
                    mma16816(acc[f][g], ah[f], bh[g]);
                    mma16816(acc[f][g], ah[f], bl[g]);
                    mma16816(acc[f][g], al[f], bh[g]);
                }
        }
        __syncthreads();
    }

    // ---- store ----
    #pragma unroll
    for (int f = 0; f < 2; f++) {
        int r = row0 + wm * 32 + f * 16 + tr;
        #pragma unroll
        for (int g = 0; g < 4; g++) {
            int c = col0 + wn * 32 + g * 8 + tc * 2;
            if (r < M)
                *(float2*)&C[(long)r * N + c] = make_float2(acc[f][g][0], acc[f][g][1]);
            if (r + 8 < M)
                *(float2*)&C[(long)(r + 8) * N + c] = make_float2(acc[f][g][2], acc[f][g][3]);
        }
    }
}

// ---------------- alpha_s / alpha_d: warp per node, coalesced ----------------
template <int F, int C>
__global__ void calc_alpha2(const float* __restrict__ a_s, const float* __restrict__ a_d) {
    int w = (blockIdx.x * blockDim.x + threadIdx.x) >> 5;
    int lane = threadIdx.x & 31;
    if (w >= NNODE) return;
    const float4* hp  = (const float4*)(g_h + (long)w * F);
    const float4* as4 = (const float4*)a_s;
    const float4* ad4 = (const float4*)a_d;
    float s0 = 0, s1 = 0, s2 = 0, s3 = 0;
    float d0 = 0, d1 = 0, d2 = 0, d3 = 0;
    #pragma unroll
    for (int f4 = lane; f4 < F / 4; f4 += 32) {
        float4 hv = hp[f4];
        float4 sv = as4[f4];
        float4 dv = ad4[f4];
        float ps = hv.x * sv.x + hv.y * sv.y + hv.z * sv.z + hv.w * sv.w;
        float pd = hv.x * dv.x + hv.y * dv.y + hv.z * dv.z + hv.w * dv.w;
        int head = (f4 * 4) / C;
        if (head == 0)      { s0 += ps; d0 += pd; }
        else if (head == 1) { s1 += ps; d1 += pd; }
        else if (head == 2) { s2 += ps; d2 += pd; }
        else                { s3 += ps; d3 += pd; }
    }
    #pragma unroll
    for (int o = 16; o; o >>= 1) {
        s0 += __shfl_xor_sync(0xffffffffu, s0, o);
        s1 += __shfl_xor_sync(0xffffffffu, s1, o);
        s2 += __shfl_xor_sync(0xffffffffu, s2, o);
        s3 += __shfl_xor_sync(0xffffffffu, s3, o);
        d0 += __shfl_xor_sync(0xffffffffu, d0, o);
        d1 += __shfl_xor_sync(0xffffffffu, d1, o);
        d2 += __shfl_xor_sync(0xffffffffu, d2, o);
        d3 += __shfl_xor_sync(0xffffffffu, d3, o);
    }
    if (lane == 0) {
        g_alpha_s[w] = make_float4(s0, s1, s2, s3);
        g_alpha_d[w] = make_float4(d0, d1, d2, d3);
    }
}

// ---------------- E1: per-dst softmax (warp per dst, no atomics) ----------------
__global__ void edge_softmax() {
    int dstN = (blockIdx.x * blockDim.x + threadIdx.x) >> 5;
    int lane = threadIdx.x & 31;
    if (dstN >= NNODE) return;
    int r0 = g_rowoff[dstN];
    int r1 = g_rowoff[dstN + 1];
    float4 ad = g_alpha_d[dstN];

    float m0 = -INFINITY, m1 = -INFINITY, m2 = -INFINITY, m3 = -INFINITY;
    for (int e = r0 + lane; e < r1; e += 32) {
        int src = g_esrc[e];
        float4 s = g_alpha_s[src];
        float4 ee = make_float4(lrelu(s.x + ad.x), lrelu(s.y + ad.y),
                                lrelu(s.z + ad.z), lrelu(s.w + ad.w));
        g_e[e] = ee;
        m0 = fmaxf(m0, ee.x); m1 = fmaxf(m1, ee.y);
        m2 = fmaxf(m2, ee.z); m3 = fmaxf(m3, ee.w);
    }
    #pragma unroll
    for (int o = 16; o; o >>= 1) {
        m0 = fmaxf(m0, __shfl_xor_sync(0xffffffffu, m0, o));
        m1 = fmaxf(m1, __shfl_xor_sync(0xffffffffu, m1, o));
        m2 = fmaxf(m2, __shfl_xor_sync(0xffffffffu, m2, o));
        m3 = fmaxf(m3, __shfl_xor_sync(0xffffffffu, m3, o));
    }
    float x0 = 0, x1 = 0, x2 = 0, x3 = 0;
    for (int e = r0 + lane; e < r1; e += 32) {
        float4 ee = g_e[e];
        float4 ex = make_float4(__expf(ee.x - m0), __expf(ee.y - m1),
                                __expf(ee.z - m2), __expf(ee.w - m3));
        g_e[e] = ex;
        x0 += ex.x; x1 += ex.y; x2 += ex.z; x3 += ex.w;
    }
    #pragma unroll
    for (int o = 16; o; o >>= 1) {
        x0 += __shfl_xor_sync(0xffffffffu, x0, o);
        x1 += __shfl_xor_sync(0xffffffffu, x1, o);
        x2 += __shfl_xor_sync(0xffffffffu, x2, o);
        x3 += __shfl_xor_sync(0xffffffffu, x3, o);
    }
    if (lane == 0) g_denom[dstN] = make_float4(x0, x1, x2, x3);
}

// ---------------- E2: aggregation (warp per dst) + fused epilogue ----------------
template <int F, int C, bool ELU>
__global__ void edge_aggregate(const float* __restrict__ bias, float* __restrict__ dstbuf) {
    int dstN = (blockIdx.x * blockDim.x + threadIdx.x) >> 5;
    int lane = threadIdx.x & 31;
    if (dstN >= NNODE) return;
    int r0 = g_rowoff[dstN];
    int r1 = g_rowoff[dstN + 1];
    float4 dn = g_denom[dstN];
    float4 inv = make_float4(1.f / (dn.x + 1e-16f), 1.f / (dn.y + 1e-16f),
                             1.f / (dn.z + 1e-16f), 1.f / (dn.w + 1e-16f));

    if (F == 64) {
        int f = lane * 2;
        int head = f / C;
        float a0 = 0, a1 = 0;
        for (int e = r0; e < r1; e++) {
            int src = g_esrc[e];
            float al = sel4(g_e[e], head);
            const float2 hv = *(const float2*)(g_h + (long)src * F + f);
            a0 += hv.x * al; a1 += hv.y * al;
        }
        float iv = sel4(inv, head);
        a0 *= iv; a1 *= iv;
        if (ELU) {
            a0 += bias[f]; a1 += bias[f + 1];
            a0 = a0 > 0.f ? a0 : expm1f(a0);
            a1 = a1 > 0.f ? a1 : expm1f(a1);
        }
        *(float2*)(dstbuf + (long)dstN * F + f) = make_float2(a0, a1);
    } else {
        const int NCH = F / 128;   // 1 or 2
        float4 acc[NCH == 0 ? 1 : NCH];
        int heads[NCH == 0 ? 1 : NCH];
        #pragma unroll
        for (int c = 0; c < NCH; c++) {
            acc[c] = make_float4(0, 0, 0, 0);
            heads[c] = (lane * 4 + c * 128) / C;
        }
        for (int e = r0; e < r1; e++) {
            int src = g_esrc[e];
            float4 alv = g_e[e];
            const float4* hp = (const float4*)(g_h + (long)src * F);
            #pragma unroll
            for (int c = 0; c < NCH; c++) {
                float al = sel4(alv, heads[c]);
                float4 hv = hp[lane + c * 32];
                acc[c].x += hv.x * al; acc[c].y += hv.y * al;
                acc[c].z += hv.z * al; acc[c].w += hv.w * al;
            }
        }
        #pragma unroll
        for (int c = 0; c < NCH; c++) {
            int f = lane * 4 + c * 128;
            float iv = sel4(inv, heads[c]);
            float4 r = acc[c];
            r.x *= iv; r.y *= iv; r.z *= iv; r.w *= iv;
            if (ELU) {
                r.x += bias[f];     r.y += bias[f + 1];
                r.z += bias[f + 2]; r.w += bias[f + 3];
                r.x = r.x > 0.f ? r.x : expm1f(r.x);
                r.y = r.y > 0.f ? r.y : expm1f(r.y);
                r.z = r.z > 0.f ? r.z : expm1f(r.z);
                r.w = r.w > 0.f ? r.w : expm1f(r.w);
            }
            *(float4*)(dstbuf + (long)dstN * F + f) = r;
        }
    }
}

// ---------------- layer 3 finish: z = mean over heads + b3 ----------------
__global__ void mean_heads(const float* __restrict__ b3) {
    int t = blockIdx.x * blockDim.x + threadIdx.x;
    if (t >= NNODE * 32) return;
    int n = t >> 5, c = t & 31;
    const float* o = g_out + (long)n * 128;
    g_z[t] = 0.25f * (o[c] + o[32 + c] + o[64 + c] + o[96 + c]) + b3[c];
}

// ---------------- logits: dot over 32 dims, warp per candidate edge ----------------
__global__ void dot_kernel(const void* __restrict__ eli, float* __restrict__ out) {
    int w = (blockIdx.x * blockDim.x + threadIdx.x) >> 5;
    int lane = threadIdx.x & 31;
    if (w >= ECAND) return;
    int use64 = g_idx64_eli;
    int s = load_idx(eli, use64, w);
    int d = load_idx(eli, use64, (long long)ECAND + w);
    float p = g_z[(long)s * 32 + lane] * g_z[(long)d * 32 + lane];
    #pragma unroll
    for (int o = 16; o; o >>= 1) p += __shfl_xor_sync(0xffffffffu, p, o);
    if (lane == 0) out[w] = p;
}

// ---------------- host launch ----------------
extern "C" void kernel_launch(void* const* d_in, const int* in_sizes, int n_in,
                              void* d_out, int out_size) {
    const float* x   = (const float*)d_in[0];
    const void*  ei  = d_in[1];
    const void*  eli = d_in[2];
    const float* W1  = (const float*)d_in[3];
    const float* a1s = (const float*)d_in[4];
    const float* a1d = (const float*)d_in[5];
    const float* b1  = (const float*)d_in[6];
    const float* W2  = (const float*)d_in[7];
    const float* a2s = (const float*)d_in[8];
    const float* a2d = (const float*)d_in[9];
    const float* b2  = (const float*)d_in[10];
    const float* W3  = (const float*)d_in[11];
    const float* a3s = (const float*)d_in[12];
    const float* a3d = (const float*)d_in[13];
    const float* b3  = (const float*)d_in[14];
    float* out = (float*)d_out;

    float *p_feat, *p_h, *p_out;
    cudaGetSymbolAddress((void**)&p_feat, g_feat);
    cudaGetSymbolAddress((void**)&p_h, g_h);
    cudaGetSymbolAddress((void**)&p_out, g_out);
    int *p_f_ei, *p_f_eli;
    cudaGetSymbolAddress((void**)&p_f_ei, g_idx64_ei);
    cudaGetSymbolAddress((void**)&p_f_eli, g_idx64_eli);

    const int TB = 256;
    const int nodeWarpBlocks = (NNODE * 32 + TB - 1) / TB;   // warp per node
    const int MB = (NNODE + 127) / 128;                      // GEMM row blocks

    detect_dtype_kernel<<<1, 1>>>((const int*)ei, p_f_ei);
    detect_dtype_kernel<<<1, 1>>>((const int*)eli, p_f_eli);

    // ---- CSR build (once; shared by all 3 layers) ----
    hist_init<<<(NNODE + TB - 1) / TB, TB>>>();
    hist_edges<<<(NEDGE + TB - 1) / TB, TB>>>(ei);
    scan_kernel<<<1, 1024>>>();
    scatter_edges<<<(NEDGE + TB - 1) / TB, TB>>>(ei);

    // ---- Layer 1: 384 -> 4x64, concat 256, elu ----
    gemm_tc<<<dim3(4, MB), 256>>>(x, W1, p_h, NNODE, 256, 384);
    calc_alpha2<256, 64><<<nodeWarpBlocks, TB>>>(a1s, a1d);
    edge_softmax<<<nodeWarpBlocks, TB>>>();
    edge_aggregate<256, 64, true><<<nodeWarpBlocks, TB>>>(b1, p_feat);

    // ---- Layer 2: 256 -> 4x16, concat 64, elu ----
    gemm_tc<<<dim3(1, MB), 256>>>(p_feat, W2, p_h, NNODE, 64, 256);
    calc_alpha2<64, 16><<<nodeWarpBlocks, TB>>>(a2s, a2d);
    edge_softmax<<<nodeWarpBlocks, TB>>>();
    edge_aggregate<64, 16, true><<<nodeWarpBlocks, TB>>>(b2, p_feat);

    // ---- Layer 3: 64 -> 4x32, mean heads -> 32 ----
    gemm_tc<<<dim3(2, MB), 256>>>(p_feat, W3, p_h, NNODE, 128, 64);
    calc_alpha2<128, 32><<<nodeWarpBlocks, TB>>>(a3s, a3d);
    edge_softmax<<<nodeWarpBlocks, TB>>>();
    edge_aggregate<128, 32, false><<<nodeWarpBlocks, TB>>>(nullptr, p_out);
    mean_heads<<<(NNODE * 32 + TB - 1) / TB, TB>>>(b3);

    // ---- Candidate-edge logits ----
    dot_kernel<<<(ECAND * 32 + TB - 1) / TB, TB>>>(eli, out);
}

// round 6
// speedup vs baseline: 3.0702x; 1.0280x over previous
#include <cuda_runtime.h>
#include <cuda_bf16.h>
#include <math.h>
#include <stdint.h>

#define NNODE   50000
#define NEDGE   800000
#define ET      850000      // NEDGE + NNODE self loops
#define ECAND   200000
#define MPAD    50048       // ceil(NNODE/128)*128
#define KMAX    384

// ---------------- scratch (device globals; no allocation) ----------------
__device__ __align__(16) __nv_bfloat16 g_pAh[MPAD * KMAX];  // A hi plane
__device__ __align__(16) __nv_bfloat16 g_pAl[MPAD * KMAX];  // A lo plane
__device__ __align__(16) __nv_bfloat16 g_pBh[KMAX * 256];   // W hi plane, [N][K]
__device__ __align__(16) __nv_bfloat16 g_pBl[KMAX * 256];   // W lo plane, [N][K]
__device__ __align__(16) float  g_h[NNODE * 256];           // GEMM output (fp32)
__device__ float4 g_alpha_s[NNODE];
__device__ float4 g_alpha_d[NNODE];
__device__ float4 g_denom[NNODE];
__device__ float4 g_e[ET];           // per-edge e -> ex (CSR order)
__device__ int    g_esrc[ET];        // CSR: src node per edge, sorted by dst
__device__ int    g_rowoff[NNODE + 1];
__device__ int    g_cnt[NNODE];
__device__ int    g_cursor[NNODE];
__device__ __align__(16) float g_z[NNODE * 32];
__device__ int    g_idx64_ei;
__device__ int    g_idx64_eli;

// ---------------- helpers ----------------
__device__ __forceinline__ float lrelu(float v) { return v > 0.f ? v : 0.2f * v; }

__device__ __forceinline__ float sel4(float4 v, int h) {
    return h < 2 ? (h == 0 ? v.x : v.y) : (h == 2 ? v.z : v.w);
}

__device__ __forceinline__ int load_idx(const void* p, int use64, long long pos) {
    return use64 ? (int)((const long long*)p)[pos] : ((const int*)p)[pos];
}

__device__ __forceinline__ void cvt_split(float v, __nv_bfloat16& h, __nv_bfloat16& l) {
    h = __float2bfloat16(v);
    l = __float2bfloat16(v - __bfloat162float(h));
}

__device__ __forceinline__ void cp16(const __nv_bfloat16* s, const __nv_bfloat16* g) {
    uint32_t sa = (uint32_t)__cvta_generic_to_shared(s);
    asm volatile("cp.async.cg.shared.global [%0], [%1], 16;\n" :: "r"(sa), "l"(g));
}

// ---------------- dtype detection (int64 vs int32 index tensors) ----------
__global__ void detect_dtype_kernel(const int* __restrict__ p, int* __restrict__ flag) {
    int ok = 1;
    #pragma unroll
    for (int i = 1; i < 64; i += 2)
        if (p[i] != 0) { ok = 0; break; }
    *flag = ok;
}

// ================= operand splitting =================
__global__ void split_plane(const float* __restrict__ src, long n) {
    long i = (long)(blockIdx.x * blockDim.x + threadIdx.x) * 4;
    if (i >= n) return;
    float4 v = *(const float4*)(src + i);
    __nv_bfloat16 h0, h1, h2, h3, l0, l1, l2, l3;
    cvt_split(v.x, h0, l0); cvt_split(v.y, h1, l1);
    cvt_split(v.z, h2, l2); cvt_split(v.w, h3, l3);
    *(__nv_bfloat162*)&g_pAh[i]     = __nv_bfloat162(h0, h1);
    *(__nv_bfloat162*)&g_pAh[i + 2] = __nv_bfloat162(h2, h3);
    *(__nv_bfloat162*)&g_pAl[i]     = __nv_bfloat162(l0, l1);
    *(__nv_bfloat162*)&g_pAl[i + 2] = __nv_bfloat162(l2, l3);
}

// weights: W[K][N] fp32 -> transposed planes [N][K] bf16 (tiny)
__global__ void split_w_t(const float* __restrict__ W, int K, int N) {
    int i = blockIdx.x * blockDim.x + threadIdx.x;
    if (i >= K * N) return;
    int k = i / N, n = i % N;
    __nv_bfloat16 h, l;
    cvt_split(W[i], h, l);
    g_pBh[n * K + k] = h;
    g_pBl[n * K + k] = l;
}

// ================= CSR build =================
__global__ void hist_init() {
    int i = blockIdx.x * blockDim.x + threadIdx.x;
    if (i < NNODE) g_cnt[i] = 1;   // self loop pre-counted
}

__global__ void hist_edges(const void* __restrict__ ei) {
    int e = blockIdx.x * blockDim.x + threadIdx.x;
    if (e >= NEDGE) return;
    int dst = load_idx(ei, g_idx64_ei, (long long)NEDGE + e);
    atomicAdd(&g_cnt[dst], 1);
}

__global__ void scan_kernel() {
    __shared__ int warp_sums[32];
    __shared__ int carry_s;
    const int tid = threadIdx.x;
    const int lane = tid & 31, wid = tid >> 5;
    if (tid == 0) carry_s = 0;
    __syncthreads();
    for (int base = 0; base < NNODE; base += 1024) {
        int i = base + tid;
        int v = (i < NNODE) ? g_cnt[i] : 0;
        int x = v;
        #pragma unroll
        for (int o = 1; o < 32; o <<= 1) {
            int y = __shfl_up_sync(0xffffffffu, x, o);
            if (lane >= o) x += y;
        }
        if (lane == 31) warp_sums[wid] = x;
        __syncthreads();
        if (wid == 0) {
            int s = warp_sums[lane];
            #pragma unroll
            for (int o = 1; o < 32; o <<= 1) {
                int y = __shfl_up_sync(0xffffffffu, s, o);
                if (lane >= o) s += y;
            }
            warp_sums[lane] = s;
        }
        __syncthreads();
        int add = (wid > 0) ? warp_sums[wid - 1] : 0;
        int incl = x + add;
        int carry = carry_s;
        if (i < NNODE) {
            int ex = carry + incl - v;
            g_rowoff[i] = ex;
            g_cursor[i] = ex + 1;   // slot 0 of each row = self loop
            g_esrc[ex] = i;
        }
        __syncthreads();
        if (tid == 0) carry_s = carry + warp_sums[31];
        __syncthreads();
    }
    if (tid == 0) g_rowoff[NNODE] = carry_s;
}

__global__ void scatter_edges(const void* __restrict__ ei) {
    int e = blockIdx.x * blockDim.x + threadIdx.x;
    if (e >= NEDGE) return;
    int use64 = g_idx64_ei;
    int src = load_idx(ei, use64, e);
    int dst = load_idx(ei, use64, (long long)NEDGE + e);
    int pos = atomicAdd(&g_cursor[dst], 1);
    g_esrc[pos] = src;
}

// ================= split-bf16 tensor-core GEMM, cp.async double-buffered ===
#define BKP 40   // padded row stride in bf16 (80B: 16B-aligned, conflict-free)
#define A_SZ (128 * BKP)
#define B_SZ (64 * BKP)
#define STG  (2 * A_SZ + 2 * B_SZ)
#define GEMM_SMEM (2 * STG * 2)   // bytes

__device__ __forceinline__ void mma16816(float* c, const uint32_t* a, const uint32_t* b) {
    asm volatile(
        "mma.sync.aligned.m16n8k16.row.col.f32.bf16.bf16.f32 "
        "{%0,%1,%2,%3}, {%4,%5,%6,%7}, {%8,%9}, {%0,%1,%2,%3};\n"
        : "+f"(c[0]), "+f"(c[1]), "+f"(c[2]), "+f"(c[3])
        : "r"(a[0]), "r"(a[1]), "r"(a[2]), "r"(a[3]), "r"(b[0]), "r"(b[1]));
}

__global__ __launch_bounds__(256) void gemm_tc(const __nv_bfloat16* __restrict__ Ah,
                                               const __nv_bfloat16* __restrict__ Al,
                                               const __nv_bfloat16* __restrict__ Bth,
                                               const __nv_bfloat16* __restrict__ Btl,
                                               float* __restrict__ C,
                                               int M, int N, int K) {
    extern __shared__ __nv_bfloat16 sm[];
    const int tid  = threadIdx.x;
    const int lane = tid & 31;
    const int warp = tid >> 5;
    const int wm   = warp & 3;
    const int wn   = warp >> 2;
    const int tr   = lane >> 2;
    const int tc   = lane & 3;
    const int row0 = blockIdx.y * 128;
    const int col0 = blockIdx.x * 64;

    float acc[2][4][4] = {};

    auto stage_load = [&](int s, int k0) {
        __nv_bfloat16* sAh = sm + s * STG;
        __nv_bfloat16* sAl = sAh + A_SZ;
        __nv_bfloat16* sBh = sAl + A_SZ;
        __nv_bfloat16* sBl = sBh + B_SZ;
        #pragma unroll
        for (int i = 0; i < 2; i++) {
            int id = tid + i * 256;           // 0..511
            int row = id >> 2, c = id & 3;
            long gofs = (long)(row0 + row) * K + k0 + c * 8;
            cp16(sAh + row * BKP + c * 8, Ah + gofs);
            cp16(sAl + row * BKP + c * 8, Al + gofs);
        }
        {
            int n = tid >> 2, c = tid & 3;    // 256 chunks
            long gofs = (long)(col0 + n) * K + k0 + c * 8;
            cp16(sBh + n * BKP + c * 8, Bth + gofs);
            cp16(sBl + n * BKP + c * 8, Btl + gofs);
        }
        asm volatile("cp.async.commit_group;\n" ::: "memory");
    };

    auto compute = [&](int s) {
        const __nv_bfloat16* sAh = sm + s * STG;
        const __nv_bfloat16* sAl = sAh + A_SZ;
        const __nv_bfloat16* sBh = sAl + A_SZ;
        const __nv_bfloat16* sBl = sBh + B_SZ;
        #pragma unroll
        for (int ks = 0; ks < 32; ks += 16) {
            uint32_t ah[2][4], al[2][4], bh[4][2], bl[4][2];
            #pragma unroll
            for (int f = 0; f < 2; f++) {
                int r = wm * 32 + f * 16 + tr;
                int kk = ks + tc * 2;
                ah[f][0] = *(const uint32_t*)&sAh[r * BKP + kk];
                ah[f][1] = *(const uint32_t*)&sAh[(r + 8) * BKP + kk];
                ah[f][2] = *(const uint32_t*)&sAh[r * BKP + kk + 8];
                ah[f][3] = *(const uint32_t*)&sAh[(r + 8) * BKP + kk + 8];
                al[f][0] = *(const uint32_t*)&sAl[r * BKP + kk];
                al[f][1] = *(const uint32_t*)&sAl[(r + 8) * BKP + kk];
                al[f][2] = *(const uint32_t*)&sAl[r * BKP + kk + 8];
                al[f][3] = *(const uint32_t*)&sAl[(r + 8) * BKP + kk + 8];
            }
            #pragma unroll
            for (int g = 0; g < 4; g++) {
                int n = wn * 32 + g * 8 + tr;
                int kk = ks + tc * 2;
                bh[g][0] = *(const uint32_t*)&sBh[n * BKP + kk];
                bh[g][1] = *(const uint32_t*)&sBh[n * BKP + kk + 8];
                bl[g][0] = *(const uint32_t*)&sBl[n * BKP + kk];
                bl[g][1] = *(const uint32_t*)&sBl[n * BKP + kk + 8];
            }
            #pragma unroll
            for (int f = 0; f < 2; f++)
                #pragma unroll
                for (int g = 0; g < 4; g++) {
                    mma16816(acc[f][g], ah[f], bh[g]);
                    mma16816(acc[f][g], ah[f], bl[g]);
                    mma16816(acc[f][g], al[f], bh[g]);
                }
        }
    };

    const int KT = K / 32;
    stage_load(0, 0);
    asm volatile("cp.async.wait_group 0;\n" ::: "memory");
    __syncthreads();
    for (int kt = 0; kt < KT; kt++) {
        int cur = kt & 1;
        if (kt + 1 < KT) stage_load(cur ^ 1, (kt + 1) * 32);
        compute(cur);
        if (kt + 1 < KT) {
            asm volatile("cp.async.wait_group 0;\n" ::: "memory");
            __syncthreads();
        }
    }

    #pragma unroll
    for (int f = 0; f < 2; f++) {
        int r = row0 + wm * 32 + f * 16 + tr;
        #pragma unroll
        for (int g = 0; g < 4; g++) {
            int c = col0 + wn * 32 + g * 8 + tc * 2;
            if (r < M)
                *(float2*)&C[(long)r * N + c] = make_float2(acc[f][g][0], acc[f][g][1]);
            if (r + 8 < M)
                *(float2*)&C[(long)(r + 8) * N + c] = make_float2(acc[f][g][2], acc[f][g][3]);
        }
    }
}

// ---------------- alpha_s / alpha_d: warp per node, coalesced ----------------
template <int F, int C>
__global__ void calc_alpha2(const float* __restrict__ a_s, const float* __restrict__ a_d) {
    int w = (blockIdx.x * blockDim.x + threadIdx.x) >> 5;
    int lane = threadIdx.x & 31;
    if (w >= NNODE) return;
    const float4* hp  = (const float4*)(g_h + (long)w * F);
    const float4* as4 = (const float4*)a_s;
    const float4* ad4 = (const float4*)a_d;
    float s0 = 0, s1 = 0, s2 = 0, s3 = 0;
    float d0 = 0, d1 = 0, d2 = 0, d3 = 0;
    #pragma unroll
    for (int f4 = lane; f4 < F / 4; f4 += 32) {
        float4 hv = hp[f4];
        float4 sv = as4[f4];
        float4 dv = ad4[f4];
        float ps = hv.x * sv.x + hv.y * sv.y + hv.z * sv.z + hv.w * sv.w;
        float pd = hv.x * dv.x + hv.y * dv.y + hv.z * dv.z + hv.w * dv.w;
        int head = (f4 * 4) / C;
        if (head == 0)      { s0 += ps; d0 += pd; }
        else if (head == 1) { s1 += ps; d1 += pd; }
        else if (head == 2) { s2 += ps; d2 += pd; }
        else                { s3 += ps; d3 += pd; }
    }
    #pragma unroll
    for (int o = 16; o; o >>= 1) {
        s0 += __shfl_xor_sync(0xffffffffu, s0, o);
        s1 += __shfl_xor_sync(0xffffffffu, s1, o);
        s2 += __shfl_xor_sync(0xffffffffu, s2, o);
        s3 += __shfl_xor_sync(0xffffffffu, s3, o);
        d0 += __shfl_xor_sync(0xffffffffu, d0, o);
        d1 += __shfl_xor_sync(0xffffffffu, d1, o);
        d2 += __shfl_xor_sync(0xffffffffu, d2, o);
        d3 += __shfl_xor_sync(0xffffffffu, d3, o);
    }
    if (lane == 0) {
        g_alpha_s[w] = make_float4(s0, s1, s2, s3);
        g_alpha_d[w] = make_float4(d0, d1, d2, d3);
    }
}

// ---------------- E1: per-dst softmax (warp per dst, no atomics) ----------------
__global__ void edge_softmax() {
    int dstN = (blockIdx.x * blockDim.x + threadIdx.x) >> 5;
    int lane = threadIdx.x & 31;
    if (dstN >= NNODE) return;
    int r0 = g_rowoff[dstN];
    int r1 = g_rowoff[dstN + 1];
    float4 ad = g_alpha_d[dstN];

    float m0 = -INFINITY, m1 = -INFINITY, m2 = -INFINITY, m3 = -INFINITY;
    for (int e = r0 + lane; e < r1; e += 32) {
        int src = g_esrc[e];
        float4 s = g_alpha_s[src];
        float4 ee = make_float4(lrelu(s.x + ad.x), lrelu(s.y + ad.y),
                                lrelu(s.z + ad.z), lrelu(s.w + ad.w));
        g_e[e] = ee;
        m0 = fmaxf(m0, ee.x); m1 = fmaxf(m1, ee.y);
        m2 = fmaxf(m2, ee.z); m3 = fmaxf(m3, ee.w);
    }
    #pragma unroll
    for (int o = 16; o; o >>= 1) {
        m0 = fmaxf(m0, __shfl_xor_sync(0xffffffffu, m0, o));
        m1 = fmaxf(m1, __shfl_xor_sync(0xffffffffu, m1, o));
        m2 = fmaxf(m2, __shfl_xor_sync(0xffffffffu, m2, o));
        m3 = fmaxf(m3, __shfl_xor_sync(0xffffffffu, m3, o));
    }
    float x0 = 0, x1 = 0, x2 = 0, x3 = 0;
    for (int e = r0 + lane; e < r1; e += 32) {
        float4 ee = g_e[e];
        float4 ex = make_float4(__expf(ee.x - m0), __expf(ee.y - m1),
                                __expf(ee.z - m2), __expf(ee.w - m3));
        g_e[e] = ex;
        x0 += ex.x; x1 += ex.y; x2 += ex.z; x3 += ex.w;
    }
    #pragma unroll
    for (int o = 16; o; o >>= 1) {
        x0 += __shfl_xor_sync(0xffffffffu, x0, o);
        x1 += __shfl_xor_sync(0xffffffffu, x1, o);
        x2 += __shfl_xor_sync(0xffffffffu, x2, o);
        x3 += __shfl_xor_sync(0xffffffffu, x3, o);
    }
    if (lane == 0) g_denom[dstN] = make_float4(x0, x1, x2, x3);
}

// ---------------- E2a: aggregate + bias + ELU -> split bf16 planes ----------------
template <int F, int C>
__global__ void edge_aggregate_elu(const float* __restrict__ bias) {
    int dstN = (blockIdx.x * blockDim.x + threadIdx.x) >> 5;
    int lane = threadIdx.x & 31;
    if (dstN >= NNODE) return;
    int r0 = g_rowoff[dstN];
    int r1 = g_rowoff[dstN + 1];
    float4 dn = g_denom[dstN];
    float4 inv = make_float4(1.f / (dn.x + 1e-16f), 1.f / (dn.y + 1e-16f),
                             1.f / (dn.z + 1e-16f), 1.f / (dn.w + 1e-16f));

    if (F == 64) {
        int f = lane * 2;
        int head = f / C;
        float a0 = 0, a1 = 0;
        for (int e = r0; e < r1; e++) {
            int src = g_esrc[e];
            float al = sel4(g_e[e], head);
            const float2 hv = *(const float2*)(g_h + (long)src * F + f);
            a0 += hv.x * al; a1 += hv.y * al;
        }
        float iv = sel4(inv, head);
        a0 = a0 * iv + bias[f];
        a1 = a1 * iv + bias[f + 1];
        a0 = a0 > 0.f ? a0 : expm1f(a0);
        a1 = a1 > 0.f ? a1 : expm1f(a1);
        __nv_bfloat16 h0, h1, l0, l1;
        cvt_split(a0, h0, l0); cvt_split(a1, h1, l1);
        *(__nv_bfloat162*)&g_pAh[(long)dstN * F + f] = __nv_bfloat162(h0, h1);
        *(__nv_bfloat162*)&g_pAl[(long)dstN * F + f] = __nv_bfloat162(l0, l1);
    } else {
        const int NCH = (F >= 128) ? F / 128 : 1;   // clamp: dead branch for F=64
        float4 acc[NCH];
        int heads[NCH];
        #pragma unroll
        for (int c = 0; c < NCH; c++) {
            acc[c] = make_float4(0, 0, 0, 0);
            heads[c] = (lane * 4 + c * 128) / C;
        }
        for (int e = r0; e < r1; e++) {
            int src = g_esrc[e];
            float4 alv = g_e[e];
            const float4* hp = (const float4*)(g_h + (long)src * F);
            #pragma unroll
            for (int c = 0; c < NCH; c++) {
                float al = sel4(alv, heads[c]);
                float4 hv = hp[lane + c * 32];
                acc[c].x += hv.x * al; acc[c].y += hv.y * al;
                acc[c].z += hv.z * al; acc[c].w += hv.w * al;
            }
        }
        #pragma unroll
        for (int c = 0; c < NCH; c++) {
            int f = lane * 4 + c * 128;
            float iv = sel4(inv, heads[c]);
            float4 r = acc[c];
            r.x = r.x * iv + bias[f];
            r.y = r.y * iv + bias[f + 1];
            r.z = r.z * iv + bias[f + 2];
            r.w = r.w * iv + bias[f + 3];
            r.x = r.x > 0.f ? r.x : expm1f(r.x);
            r.y = r.y > 0.f ? r.y : expm1f(r.y);
            r.z = r.z > 0.f ? r.z : expm1f(r.z);
            r.w = r.w > 0.f ? r.w : expm1f(r.w);
            __nv_bfloat16 h0, h1, h2, h3, l0, l1, l2, l3;
            cvt_split(r.x, h0, l0); cvt_split(r.y, h1, l1);
            cvt_split(r.z, h2, l2); cvt_split(r.w, h3, l3);
            long o = (long)dstN * F + f;
            *(__nv_bfloat162*)&g_pAh[o]     = __nv_bfloat162(h0, h1);
            *(__nv_bfloat162*)&g_pAh[o + 2] = __nv_bfloat162(h2, h3);
            *(__nv_bfloat162*)&g_pAl[o]     = __nv_bfloat162(l0, l1);
            *(__nv_bfloat162*)&g_pAl[o + 2] = __nv_bfloat162(l2, l3);
        }
    }
}

// ---------------- E2b: layer-3 aggregate + fused head-mean + b3 -> g_z --------
__global__ void edge_aggregate_mean(const float* __restrict__ b3) {
    int dstN = (blockIdx.x * blockDim.x + threadIdx.x) >> 5;
    int lane = threadIdx.x & 31;
    if (dstN >= NNODE) return;
    int r0 = g_rowoff[dstN];
    int r1 = g_rowoff[dstN + 1];
    float4 dn = g_denom[dstN];
    int head = lane >> 3;
    float iv = 1.f / (sel4(dn, head) + 1e-16f);

    float4 acc = make_float4(0, 0, 0, 0);
    for (int e = r0; e < r1; e++) {
        int src = g_esrc[e];
        float al = sel4(g_e[e], head);
        float4 hv = ((const float4*)(g_h + (long)src * 128))[lane];
        acc.x += hv.x * al; acc.y += hv.y * al;
        acc.z += hv.z * al; acc.w += hv.w * al;
    }
    acc.x *= iv; acc.y *= iv; acc.z *= iv; acc.w *= iv;
    #pragma unroll
    for (int o = 8; o <= 16; o <<= 1) {
        acc.x += __shfl_xor_sync(0xffffffffu, acc.x, o);
        acc.y += __shfl_xor_sync(0xffffffffu, acc.y, o);
        acc.z += __shfl_xor_sync(0xffffffffu, acc.z, o);
        acc.w += __shfl_xor_sync(0xffffffffu, acc.w, o);
    }
    if (lane < 8) {
        int c = lane * 4;
        float4 z = make_float4(0.25f * acc.x + b3[c],     0.25f * acc.y + b3[c + 1],
                               0.25f * acc.z + b3[c + 2], 0.25f * acc.w + b3[c + 3]);
        *(float4*)&g_z[(long)dstN * 32 + c] = z;
    }
}

// ---------------- logits: dot over 32 dims, warp per candidate edge ----------------
__global__ void dot_kernel(const void* __restrict__ eli, float* __restrict__ out) {
    int w = (blockIdx.x * blockDim.x + threadIdx.x) >> 5;
    int lane = threadIdx.x & 31;
    if (w >= ECAND) return;
    int use64 = g_idx64_eli;
    int s = load_idx(eli, use64, w);
    int d = load_idx(eli, use64, (long long)ECAND + w);
    float p = g_z[(long)s * 32 + lane] * g_z[(long)d * 32 + lane];
    #pragma unroll
    for (int o = 16; o; o >>= 1) p += __shfl_xor_sync(0xffffffffu, p, o);
    if (lane == 0) out[w] = p;
}

// ---------------- host launch ----------------
extern "C" void kernel_launch(void* const* d_in, const int* in_sizes, int n_in,
                              void* d_out, int out_size) {
    const float* x   = (const float*)d_in[0];
    const void*  ei  = d_in[1];
    const void*  eli = d_in[2];
    const float* W1  = (const float*)d_in[3];
    const float* a1s = (const float*)d_in[4];
    const float* a1d = (const float*)d_in[5];
    const float* b1  = (const float*)d_in[6];
    const float* W2  = (const float*)d_in[7];
    const float* a2s = (const float*)d_in[8];
    const float* a2d = (const float*)d_in[9];
    const float* b2  = (const float*)d_in[10];
    const float* W3  = (const float*)d_in[11];
    const float* a3s = (const float*)d_in[12];
    const float* a3d = (const float*)d_in[13];
    const float* b3  = (const float*)d_in[14];
    float* out = (float*)d_out;

    float* p_h;
    cudaGetSymbolAddress((void**)&p_h, g_h);
    __nv_bfloat16 *p_Ah, *p_Al, *p_Bh, *p_Bl;
    cudaGetSymbolAddress((void**)&p_Ah, g_pAh);
    cudaGetSymbolAddress((void**)&p_Al, g_pAl);
    cudaGetSymbolAddress((void**)&p_Bh, g_pBh);
    cudaGetSymbolAddress((void**)&p_Bl, g_pBl);
    int *p_f_ei, *p_f_eli;
    cudaGetSymbolAddress((void**)&p_f_ei, g_idx64_ei);
    cudaGetSymbolAddress((void**)&p_f_eli, g_idx64_eli);

    static bool attr_done = false;
    if (!attr_done) {
        cudaFuncSetAttribute(gemm_tc, cudaFuncAttributeMaxDynamicSharedMemorySize, GEMM_SMEM);
        attr_done = true;
    }

    const int TB = 256;
    const int nodeWarpBlocks = (NNODE * 32 + TB - 1) / TB;   // warp per node
    const int MB = (NNODE + 127) / 128;                      // GEMM row blocks

    detect_dtype_kernel<<<1, 1>>>((const int*)ei, p_f_ei);
    detect_dtype_kernel<<<1, 1>>>((const int*)eli, p_f_eli);

    // ---- CSR build (once; shared by all 3 layers) ----
    hist_init<<<(NNODE + TB - 1) / TB, TB>>>();
    hist_edges<<<(NEDGE + TB - 1) / TB, TB>>>(ei);
    scan_kernel<<<1, 1024>>>();
    scatter_edges<<<(NEDGE + TB - 1) / TB, TB>>>(ei);

    // ---- split x and W1 ----
    {
        long n = (long)NNODE * 384;
        split_plane<<<(int)((n / 4 + TB - 1) / TB), TB>>>(x, n);
        split_w_t<<<(384 * 256 + TB - 1) / TB, TB>>>(W1, 384, 256);
    }

    // ---- Layer 1: 384 -> 4x64, concat 256, elu ----
    gemm_tc<<<dim3(4, MB), 256, GEMM_SMEM>>>(p_Ah, p_Al, p_Bh, p_Bl, p_h, NNODE, 256, 384);
    calc_alpha2<256, 64><<<nodeWarpBlocks, TB>>>(a1s, a1d);
    edge_softmax<<<nodeWarpBlocks, TB>>>();
    edge_aggregate_elu<256, 64><<<nodeWarpBlocks, TB>>>(b1);   // writes split planes

    // ---- Layer 2: 256 -> 4x16, concat 64, elu ----
    split_w_t<<<(256 * 64 + TB - 1) / TB, TB>>>(W2, 256, 64);
    gemm_tc<<<dim3(1, MB), 256, GEMM_SMEM>>>(p_Ah, p_Al, p_Bh, p_Bl, p_h, NNODE, 64, 256);
    calc_alpha2<64, 16><<<nodeWarpBlocks, TB>>>(a2s, a2d);
    edge_softmax<<<nodeWarpBlocks, TB>>>();
    edge_aggregate_elu<64, 16><<<nodeWarpBlocks, TB>>>(b2);    // writes split planes

    // ---- Layer 3: 64 -> 4x32, mean heads -> 32 (fused) ----
    split_w_t<<<(64 * 128 + TB - 1) / TB, TB>>>(W3, 64, 128);
    gemm_tc<<<dim3(2, MB), 256, GEMM_SMEM>>>(p_Ah, p_Al, p_Bh, p_Bl, p_h, NNODE, 128, 64);
    calc_alpha2<128, 32><<<nodeWarpBlocks, TB>>>(a3s, a3d);
    edge_softmax<<<nodeWarpBlocks, TB>>>();
    edge_aggregate_mean<<<nodeWarpBlocks, TB>>>(b3);

    // ---- Candidate-edge logits ----
    dot_kernel<<<(ECAND * 32 + TB - 1) / TB, TB>>>(eli, out);
}

// round 7
// speedup vs baseline: 3.4814x; 1.1339x over previous
#include <cuda_runtime.h>
#include <cuda_bf16.h>
#include <math.h>
#include <stdint.h>

#define NNODE   50000
#define NEDGE   800000
#define ET      850000      // NEDGE + NNODE self loops
#define ECAND   200000
#define MPAD    50048       // ceil(NNODE/128)*128
#define KMAX    384
#define NBLK    49          // ceil(NNODE/1024)

// ---------------- scratch (device globals; no allocation) ----------------
__device__ __align__(16) __nv_bfloat16 g_pAh[MPAD * KMAX];  // A hi plane
__device__ __align__(16) __nv_bfloat16 g_pAl[MPAD * KMAX];  // A lo plane
// packed W planes [N][K]: L1 @0 (384*256), L2 @98304 (256*64), L3 @114688 (64*128)
__device__ __align__(16) __nv_bfloat16 g_pBh[122880];
__device__ __align__(16) __nv_bfloat16 g_pBl[122880];
__device__ __align__(16) float  g_h[NNODE * 256];           // GEMM output (fp32)
__device__ float4 g_alpha_s[NNODE];
__device__ float4 g_alpha_d[NNODE];
__device__ float4 g_denom[NNODE];
__device__ float4 g_e[ET];           // per-edge e -> ex (CSR order)
__device__ int    g_esrc[ET];        // CSR: src node per edge, sorted by dst
__device__ int    g_rowoff[NNODE + 1];
__device__ int    g_cnt[NNODE];
__device__ int    g_cursor[NNODE];
__device__ int    g_bsum[64];
__device__ int    g_boff[64];
__device__ __align__(16) float g_z[NNODE * 32];
__device__ int    g_idx64_ei;
__device__ int    g_idx64_eli;

// ---------------- helpers ----------------
__device__ __forceinline__ float lrelu(float v) { return v > 0.f ? v : 0.2f * v; }

__device__ __forceinline__ float sel4(float4 v, int h) {
    return h < 2 ? (h == 0 ? v.x : v.y) : (h == 2 ? v.z : v.w);
}

__device__ __forceinline__ int load_idx(const void* p, int use64, long long pos) {
    return use64 ? (int)((const long long*)p)[pos] : ((const int*)p)[pos];
}

__device__ __forceinline__ void cvt_split(float v, __nv_bfloat16& h, __nv_bfloat16& l) {
    h = __float2bfloat16(v);
    l = __float2bfloat16(v - __bfloat162float(h));
}

__device__ __forceinline__ void cp16(const __nv_bfloat16* s, const __nv_bfloat16* g) {
    uint32_t sa = (uint32_t)__cvta_generic_to_shared(s);
    asm volatile("cp.async.cg.shared.global [%0], [%1], 16;\n" :: "r"(sa), "l"(g));
}

// ---------------- init: dtype detect + cnt=1 + alpha zero ----------------
__global__ void init_detect(const int* __restrict__ ei, const int* __restrict__ eli) {
    int i = blockIdx.x * blockDim.x + threadIdx.x;
    if (i < NNODE) {
        g_cnt[i] = 1;   // self loop pre-counted
        g_alpha_s[i] = make_float4(0, 0, 0, 0);
        g_alpha_d[i] = make_float4(0, 0, 0, 0);
    }
    if (i == 0) {
        int ok = 1;
        #pragma unroll
        for (int j = 1; j < 64; j += 2) if (ei[j] != 0) { ok = 0; break; }
        g_idx64_ei = ok;
        ok = 1;
        #pragma unroll
        for (int j = 1; j < 64; j += 2) if (eli[j] != 0) { ok = 0; break; }
        g_idx64_eli = ok;
    }
}

// ================= operand splitting =================
__global__ void split_plane(const float* __restrict__ src, long n) {
    long i = (long)(blockIdx.x * blockDim.x + threadIdx.x) * 4;
    if (i >= n) return;
    float4 v = *(const float4*)(src + i);
    __nv_bfloat16 h0, h1, h2, h3, l0, l1, l2, l3;
    cvt_split(v.x, h0, l0); cvt_split(v.y, h1, l1);
    cvt_split(v.z, h2, l2); cvt_split(v.w, h3, l3);
    *(__nv_bfloat162*)&g_pAh[i]     = __nv_bfloat162(h0, h1);
    *(__nv_bfloat162*)&g_pAh[i + 2] = __nv_bfloat162(h2, h3);
    *(__nv_bfloat162*)&g_pAl[i]     = __nv_bfloat162(l0, l1);
    *(__nv_bfloat162*)&g_pAl[i + 2] = __nv_bfloat162(l2, l3);
}

// all three weight matrices: W[K][N] fp32 -> transposed planes [N][K] bf16
__global__ void split_w_all(const float* __restrict__ W1, const float* __restrict__ W2,
                            const float* __restrict__ W3) {
    int i = blockIdx.x * blockDim.x + threadIdx.x;
    const float* W; int K, N, off, li;
    if (i < 98304)       { W = W1; K = 384; N = 256; off = 0;      li = i; }
    else if (i < 114688) { W = W2; K = 256; N = 64;  off = 98304;  li = i - 98304; }
    else if (i < 122880) { W = W3; K = 64;  N = 128; off = 114688; li = i - 114688; }
    else return;
    int k = li / N, n = li % N;
    __nv_bfloat16 h, l;
    cvt_split(W[li], h, l);
    g_pBh[off + n * K + k] = h;
    g_pBl[off + n * K + k] = l;
}

// ================= CSR build (parallel scan) =================
__global__ void hist_edges(const void* __restrict__ ei) {
    int e = blockIdx.x * blockDim.x + threadIdx.x;
    if (e >= NEDGE) return;
    int dst = load_idx(ei, g_idx64_ei, (long long)NEDGE + e);
    atomicAdd(&g_cnt[dst], 1);
}

__global__ void csr_s1() {   // per-block sums of g_cnt
    __shared__ int ws[32];
    int i = blockIdx.x * 1024 + threadIdx.x;
    int lane = threadIdx.x & 31, wid = threadIdx.x >> 5;
    int v = (i < NNODE) ? g_cnt[i] : 0;
    #pragma unroll
    for (int o = 16; o; o >>= 1) v += __shfl_xor_sync(0xffffffffu, v, o);
    if (lane == 0) ws[wid] = v;
    __syncthreads();
    if (threadIdx.x < 32) {
        int s = ws[threadIdx.x];
        #pragma unroll
        for (int o = 16; o; o >>= 1) s += __shfl_xor_sync(0xffffffffu, s, o);
        if (threadIdx.x == 0) g_bsum[blockIdx.x] = s;
    }
}

__global__ void csr_s2() {   // exclusive scan of NBLK block sums (1 block, 64 thr)
    __shared__ int w0tot;
    int t = threadIdx.x;
    int lane = t & 31, w = t >> 5;
    int v = (t < NBLK) ? g_bsum[t] : 0;
    int x = v;
    #pragma unroll
    for (int o = 1; o < 32; o <<= 1) {
        int y = __shfl_up_sync(0xffffffffu, x, o);
        if (lane >= o) x += y;
    }
    if (t == 31) w0tot = x;
    __syncthreads();
    if (w == 1) x += w0tot;
    if (t < NBLK) g_boff[t] = x - v;
}

__global__ void csr_s3() {   // final offsets + self-loop placement
    __shared__ int ws[32];
    int i = blockIdx.x * 1024 + threadIdx.x;
    int lane = threadIdx.x & 31, wid = threadIdx.x >> 5;
    int v = (i < NNODE) ? g_cnt[i] : 0;
    int x = v;
    #pragma unroll
    for (int o = 1; o < 32; o <<= 1) {
        int y = __shfl_up_sync(0xffffffffu, x, o);
        if (lane >= o) x += y;
    }
    if (lane == 31) ws[wid] = x;
    __syncthreads();
    if (wid == 0) {
        int s = ws[lane];
        #pragma unroll
        for (int o = 1; o < 32; o <<= 1) {
            int y = __shfl_up_sync(0xffffffffu, s, o);
            if (lane >= o) s += y;
        }
        ws[lane] = s;
    }
    __syncthreads();
    int ex = x - v + (wid ? ws[wid - 1] : 0) + g_boff[blockIdx.x];
    if (i < NNODE) {
        g_rowoff[i] = ex;
        g_cursor[i] = ex + 1;   // slot 0 of each row = self loop
        g_esrc[ex] = i;
        if (i == NNODE - 1) g_rowoff[NNODE] = ex + v;
    }
}

__global__ void scatter_edges(const void* __restrict__ ei) {
    int e = blockIdx.x * blockDim.x + threadIdx.x;
    if (e >= NEDGE) return;
    int use64 = g_idx64_ei;
    int src = load_idx(ei, use64, e);
    int dst = load_idx(ei, use64, (long long)NEDGE + e);
    int pos = atomicAdd(&g_cursor[dst], 1);
    g_esrc[pos] = src;
}

// ================= split-bf16 tensor-core GEMM + fused alpha epilogue =====
#define BKP 40
#define A_SZ (128 * BKP)
#define B_SZ (64 * BKP)
#define STG  (2 * A_SZ + 2 * B_SZ)
#define GEMM_SMEM (2 * STG * 2)   // bytes

__device__ __forceinline__ void mma16816(float* c, const uint32_t* a, const uint32_t* b) {
    asm volatile(
        "mma.sync.aligned.m16n8k16.row.col.f32.bf16.bf16.f32 "
        "{%0,%1,%2,%3}, {%4,%5,%6,%7}, {%8,%9}, {%0,%1,%2,%3};\n"
        : "+f"(c[0]), "+f"(c[1]), "+f"(c[2]), "+f"(c[3])
        : "r"(a[0]), "r"(a[1]), "r"(a[2]), "r"(a[3]), "r"(b[0]), "r"(b[1]));
}

__global__ __launch_bounds__(256) void gemm_tc(const __nv_bfloat16* __restrict__ Ah,
                                               const __nv_bfloat16* __restrict__ Al,
                                               const __nv_bfloat16* __restrict__ Bth,
                                               const __nv_bfloat16* __restrict__ Btl,
                                               float* __restrict__ C,
                                               const float* __restrict__ a_s,
                                               const float* __restrict__ a_d,
                                               int M, int N, int K, int Ch) {
    extern __shared__ __nv_bfloat16 sm[];
    const int tid  = threadIdx.x;
    const int lane = tid & 31;
    const int warp = tid >> 5;
    const int wm   = warp & 3;
    const int wn   = warp >> 2;
    const int tr   = lane >> 2;
    const int tc   = lane & 3;
    const int row0 = blockIdx.y * 128;
    const int col0 = blockIdx.x * 64;

    float acc[2][4][4] = {};

    auto stage_load = [&](int s, int k0) {
        __nv_bfloat16* sAh = sm + s * STG;
        __nv_bfloat16* sAl = sAh + A_SZ;
        __nv_bfloat16* sBh = sAl + A_SZ;
        __nv_bfloat16* sBl = sBh + B_SZ;
        #pragma unroll
        for (int i = 0; i < 2; i++) {
            int id = tid + i * 256;
            int row = id >> 2, c = id & 3;
            long gofs = (long)(row0 + row) * K + k0 + c * 8;
            cp16(sAh + row * BKP + c * 8, Ah + gofs);
            cp16(sAl + row * BKP + c * 8, Al + gofs);
        }
        {
            int n = tid >> 2, c = tid & 3;
            long gofs = (long)(col0 + n) * K + k0 + c * 8;
            cp16(sBh + n * BKP + c * 8, Bth + gofs);
            cp16(sBl + n * BKP + c * 8, Btl + gofs);
        }
        asm volatile("cp.async.commit_group;\n" ::: "memory");
    };

    auto compute = [&](int s) {
        const __nv_bfloat16* sAh = sm + s * STG;
        const __nv_bfloat16* sAl = sAh + A_SZ;
        const __nv_bfloat16* sBh = sAl + A_SZ;
        const __nv_bfloat16* sBl = sBh + B_SZ;
        #pragma unroll
        for (int ks = 0; ks < 32; ks += 16) {
            uint32_t ah[2][4], al[2][4], bh[4][2], bl[4][2];
            #pragma unroll
            for (int f = 0; f < 2; f++) {
                int r = wm * 32 + f * 16 + tr;
                int kk = ks + tc * 2;
                ah[f][0] = *(const uint32_t*)&sAh[r * BKP + kk];
                ah[f][1] = *(const uint32_t*)&sAh[(r + 8) * BKP + kk];
                ah[f][2] = *(const uint32_t*)&sAh[r * BKP + kk + 8];
                ah[f][3] = *(const uint32_t*)&sAh[(r + 8) * BKP + kk + 8];
                al[f][0] = *(const uint32_t*)&sAl[r * BKP + kk];
                al[f][1] = *(const uint32_t*)&sAl[(r + 8) * BKP + kk];
                al[f][2] = *(const uint32_t*)&sAl[r * BKP + kk + 8];
                al[f][3] = *(const uint32_t*)&sAl[(r + 8) * BKP + kk + 8];
            }
            #pragma unroll
            for (int g = 0; g < 4; g++) {
                int n = wn * 32 + g * 8 + tr;
                int kk = ks + tc * 2;
                bh[g][0] = *(const uint32_t*)&sBh[n * BKP + kk];
                bh[g][1] = *(const uint32_t*)&sBh[n * BKP + kk + 8];
                bl[g][0] = *(const uint32_t*)&sBl[n * BKP + kk];
                bl[g][1] = *(const uint32_t*)&sBl[n * BKP + kk + 8];
            }
            #pragma unroll
            for (int f = 0; f < 2; f++)
                #pragma unroll
                for (int g = 0; g < 4; g++) {
                    mma16816(acc[f][g], ah[f], bh[g]);
                    mma16816(acc[f][g], ah[f], bl[g]);
                    mma16816(acc[f][g], al[f], bh[g]);
                }
        }
    };

    const int KT = K / 32;
    stage_load(0, 0);
    asm volatile("cp.async.wait_group 0;\n" ::: "memory");
    __syncthreads();
    for (int kt = 0; kt < KT; kt++) {
        int cur = kt & 1;
        if (kt + 1 < KT) stage_load(cur ^ 1, (kt + 1) * 32);
        compute(cur);
        if (kt + 1 < KT) {
            asm volatile("cp.async.wait_group 0;\n" ::: "memory");
            __syncthreads();
        }
    }

    // ---- store C ----
    #pragma unroll
    for (int f = 0; f < 2; f++) {
        int r = row0 + wm * 32 + f * 16 + tr;
        #pragma unroll
        for (int g = 0; g < 4; g++) {
            int c = col0 + wn * 32 + g * 8 + tc * 2;
            if (r < M)
                *(float2*)&C[(long)r * N + c] = make_float2(acc[f][g][0], acc[f][g][1]);
            if (r + 8 < M)
                *(float2*)&C[(long)(r + 8) * N + c] = make_float2(acc[f][g][2], acc[f][g][3]);
        }
    }

    // ---- fused alpha epilogue ----
    // This warp's 32 columns cover 1 head (Ch>=32) or 2 heads (Ch==16).
    float asv[8], adv[8];
    #pragma unroll
    for (int g = 0; g < 4; g++) {
        int colg = col0 + wn * 32 + g * 8 + tc * 2;
        asv[g * 2] = __ldg(&a_s[colg]); asv[g * 2 + 1] = __ldg(&a_s[colg + 1]);
        adv[g * 2] = __ldg(&a_d[colg]); adv[g * 2 + 1] = __ldg(&a_d[colg + 1]);
    }
    const int hlo = (col0 + wn * 32) / Ch;
    const bool two_heads = (Ch == 16);
    #pragma unroll
    for (int f = 0; f < 2; f++) {
        #pragma unroll
        for (int half = 0; half < 2; half++) {
            int row = row0 + wm * 32 + f * 16 + tr + half * 8;
            float psg[4], pdg[4];
            #pragma unroll
            for (int g = 0; g < 4; g++) {
                float a0 = acc[f][g][half * 2], a1 = acc[f][g][half * 2 + 1];
                psg[g] = a0 * asv[g * 2] + a1 * asv[g * 2 + 1];
                pdg[g] = a0 * adv[g * 2] + a1 * adv[g * 2 + 1];
            }
            float s0 = psg[0] + psg[1], s1 = psg[2] + psg[3];
            float d0 = pdg[0] + pdg[1], d1 = pdg[2] + pdg[3];
            #pragma unroll
            for (int o = 1; o <= 2; o <<= 1) {
                s0 += __shfl_xor_sync(0xffffffffu, s0, o);
                s1 += __shfl_xor_sync(0xffffffffu, s1, o);
                d0 += __shfl_xor_sync(0xffffffffu, d0, o);
                d1 += __shfl_xor_sync(0xffffffffu, d1, o);
            }
            if (tc == 0 && row < M) {
                if (two_heads) {
                    atomicAdd(&((float*)g_alpha_s)[row * 4 + hlo], s0);
                    atomicAdd(&((float*)g_alpha_s)[row * 4 + hlo + 1], s1);
                    atomicAdd(&((float*)g_alpha_d)[row * 4 + hlo], d0);
                    atomicAdd(&((float*)g_alpha_d)[row * 4 + hlo + 1], d1);
                } else {
                    atomicAdd(&((float*)g_alpha_s)[row * 4 + hlo], s0 + s1);
                    atomicAdd(&((float*)g_alpha_d)[row * 4 + hlo], d0 + d1);
                }
            }
        }
    }
}

// ---------------- E1: per-dst softmax (warp per dst, no atomics) ----------------
__global__ void edge_softmax() {
    int dstN = (blockIdx.x * blockDim.x + threadIdx.x) >> 5;
    int lane = threadIdx.x & 31;
    if (dstN >= NNODE) return;
    int r0 = g_rowoff[dstN];
    int r1 = g_rowoff[dstN + 1];
    float4 ad = g_alpha_d[dstN];

    float m0 = -INFINITY, m1 = -INFINITY, m2 = -INFINITY, m3 = -INFINITY;
    for (int e = r0 + lane; e < r1; e += 32) {
        int src = g_esrc[e];
        float4 s = g_alpha_s[src];
        float4 ee = make_float4(lrelu(s.x + ad.x), lrelu(s.y + ad.y),
                                lrelu(s.z + ad.z), lrelu(s.w + ad.w));
        g_e[e] = ee;
        m0 = fmaxf(m0, ee.x); m1 = fmaxf(m1, ee.y);
        m2 = fmaxf(m2, ee.z); m3 = fmaxf(m3, ee.w);
    }
    #pragma unroll
    for (int o = 16; o; o >>= 1) {
        m0 = fmaxf(m0, __shfl_xor_sync(0xffffffffu, m0, o));
        m1 = fmaxf(m1, __shfl_xor_sync(0xffffffffu, m1, o));
        m2 = fmaxf(m2, __shfl_xor_sync(0xffffffffu, m2, o));
        m3 = fmaxf(m3, __shfl_xor_sync(0xffffffffu, m3, o));
    }
    float x0 = 0, x1 = 0, x2 = 0, x3 = 0;
    for (int e = r0 + lane; e < r1; e += 32) {
        float4 ee = g_e[e];
        float4 ex = make_float4(__expf(ee.x - m0), __expf(ee.y - m1),
                                __expf(ee.z - m2), __expf(ee.w - m3));
        g_e[e] = ex;
        x0 += ex.x; x1 += ex.y; x2 += ex.z; x3 += ex.w;
    }
    #pragma unroll
    for (int o = 16; o; o >>= 1) {
        x0 += __shfl_xor_sync(0xffffffffu, x0, o);
        x1 += __shfl_xor_sync(0xffffffffu, x1, o);
        x2 += __shfl_xor_sync(0xffffffffu, x2, o);
        x3 += __shfl_xor_sync(0xffffffffu, x3, o);
    }
    if (lane == 0) g_denom[dstN] = make_float4(x0, x1, x2, x3);
}

// ---------------- E2a: aggregate + bias + ELU -> split bf16 planes ----------------
// Also zeroes g_alpha for the next layer's fused-GEMM accumulation.
template <int F, int C>
__global__ void edge_aggregate_elu(const float* __restrict__ bias) {
    int dstN = (blockIdx.x * blockDim.x + threadIdx.x) >> 5;
    int lane = threadIdx.x & 31;
    if (dstN >= NNODE) return;
    int r0 = g_rowoff[dstN];
    int r1 = g_rowoff[dstN + 1];
    float4 dn = g_denom[dstN];
    float4 inv = make_float4(1.f / (dn.x + 1e-16f), 1.f / (dn.y + 1e-16f),
                             1.f / (dn.z + 1e-16f), 1.f / (dn.w + 1e-16f));

    if (F == 64) {
        int f = lane * 2;
        int head = f / C;
        float a0 = 0, a1 = 0;
        int e = r0;
        for (; e + 1 < r1; e += 2) {
            int s0i = g_esrc[e], s1i = g_esrc[e + 1];
            float al0 = sel4(g_e[e], head), al1 = sel4(g_e[e + 1], head);
            float2 h0 = *(const float2*)(g_h + (long)s0i * F + f);
            float2 h1 = *(const float2*)(g_h + (long)s1i * F + f);
            a0 += h0.x * al0 + h1.x * al1;
            a1 += h0.y * al0 + h1.y * al1;
        }
        if (e < r1) {
            int si = g_esrc[e];
            float al = sel4(g_e[e], head);
            float2 hv = *(const float2*)(g_h + (long)si * F + f);
            a0 += hv.x * al; a1 += hv.y * al;
        }
        float iv = sel4(inv, head);
        a0 = a0 * iv + bias[f];
        a1 = a1 * iv + bias[f + 1];
        a0 = a0 > 0.f ? a0 : expm1f(a0);
        a1 = a1 > 0.f ? a1 : expm1f(a1);
        __nv_bfloat16 h0, h1, l0, l1;
        cvt_split(a0, h0, l0); cvt_split(a1, h1, l1);
        *(__nv_bfloat162*)&g_pAh[(long)dstN * F + f] = __nv_bfloat162(h0, h1);
        *(__nv_bfloat162*)&g_pAl[(long)dstN * F + f] = __nv_bfloat162(l0, l1);
    } else {   // F == 256
        float4 acc0 = make_float4(0, 0, 0, 0), acc1 = make_float4(0, 0, 0, 0);
        int hd0 = (lane * 4) / C, hd1 = (lane * 4 + 128) / C;
        int e = r0;
        for (; e + 1 < r1; e += 2) {
            int s0i = g_esrc[e], s1i = g_esrc[e + 1];
            float4 av0 = g_e[e], av1 = g_e[e + 1];
            const float4* hp0 = (const float4*)(g_h + (long)s0i * F);
            const float4* hp1 = (const float4*)(g_h + (long)s1i * F);
            float a00 = sel4(av0, hd0), a01 = sel4(av0, hd1);
            float a10 = sel4(av1, hd0), a11 = sel4(av1, hd1);
            float4 v00 = hp0[lane],      v01 = hp0[lane + 32];
            float4 v10 = hp1[lane],      v11 = hp1[lane + 32];
            acc0.x += v00.x * a00 + v10.x * a10;  acc0.y += v00.y * a00 + v10.y * a10;
            acc0.z += v00.z * a00 + v10.z * a10;  acc0.w += v00.w * a00 + v10.w * a10;
            acc1.x += v01.x * a01 + v11.x * a11;  acc1.y += v01.y * a01 + v11.y * a11;
            acc1.z += v01.z * a01 + v11.z * a11;  acc1.w += v01.w * a01 + v11.w * a11;
        }
        if (e < r1) {
            int si = g_esrc[e];
            float4 av = g_e[e];
            const float4* hp = (const float4*)(g_h + (long)si * F);
            float a0 = sel4(av, hd0), a1 = sel4(av, hd1);
            float4 v0 = hp[lane], v1 = hp[lane + 32];
            acc0.x += v0.x * a0; acc0.y += v0.y * a0; acc0.z += v0.z * a0; acc0.w += v0.w * a0;
            acc1.x += v1.x * a1; acc1.y += v1.y * a1; acc1.z += v1.z * a1; acc1.w += v1.w * a1;
        }
        #pragma unroll
        for (int c = 0; c < 2; c++) {
            int f = lane * 4 + c * 128;
            float iv = sel4(inv, c == 0 ? hd0 : hd1);
            float4 r = c == 0 ? acc0 : acc1;
            r.x = r.x * iv + bias[f];
            r.y = r.y * iv + bias[f + 1];
            r.z = r.z * iv + bias[f + 2];
            r.w = r.w * iv + bias[f + 3];
            r.x = r.x > 0.f ? r.x : expm1f(r.x);
            r.y = r.y > 0.f ? r.y : expm1f(r.y);
            r.z = r.z > 0.f ? r.z : expm1f(r.z);
            r.w = r.w > 0.f ? r.w : expm1f(r.w);
            __nv_bfloat16 h0, h1, h2, h3, l0, l1, l2, l3;
            cvt_split(r.x, h0, l0); cvt_split(r.y, h1, l1);
            cvt_split(r.z, h2, l2); cvt_split(r.w, h3, l3);
            long o = (long)dstN * F + f;
            *(__nv_bfloat162*)&g_pAh[o]     = __nv_bfloat162(h0, h1);
            *(__nv_bfloat162*)&g_pAh[o + 2] = __nv_bfloat162(h2, h3);
            *(__nv_bfloat162*)&g_pAl[o]     = __nv_bfloat162(l0, l1);
            *(__nv_bfloat162*)&g_pAl[o + 2] = __nv_bfloat162(l2, l3);
        }
    }
    // zero alpha for next layer's fused-GEMM atomic accumulation
    if (lane == 0) {
        g_alpha_s[dstN] = make_float4(0, 0, 0, 0);
        g_alpha_d[dstN] = make_float4(0, 0, 0, 0);
    }
}

// ---------------- E2b: layer-3 aggregate + fused head-mean + b3 -> g_z --------
__global__ void edge_aggregate_mean(const float* __restrict__ b3) {
    int dstN = (blockIdx.x * blockDim.x + threadIdx.x) >> 5;
    int lane = threadIdx.x & 31;
    if (dstN >= NNODE) return;
    int r0 = g_rowoff[dstN];
    int r1 = g_rowoff[dstN + 1];
    float4 dn = g_denom[dstN];
    int head = lane >> 3;
    float iv = 1.f / (sel4(dn, head) + 1e-16f);

    float4 acc = make_float4(0, 0, 0, 0);
    int e = r0;
    for (; e + 1 < r1; e += 2) {
        int s0i = g_esrc[e], s1i = g_esrc[e + 1];
        float a0 = sel4(g_e[e], head), a1 = sel4(g_e[e + 1], head);
        float4 v0 = ((const float4*)(g_h + (long)s0i * 128))[lane];
        float4 v1 = ((const float4*)(g_h + (long)s1i * 128))[lane];
        acc.x += v0.x * a0 + v1.x * a1;  acc.y += v0.y * a0 + v1.y * a1;
        acc.z += v0.z * a0 + v1.z * a1;  acc.w += v0.w * a0 + v1.w * a1;
    }
    if (e < r1) {
        int si = g_esrc[e];
        float al = sel4(g_e[e], head);
        float4 hv = ((const float4*)(g_h + (long)si * 128))[lane];
        acc.x += hv.x * al; acc.y += hv.y * al;
        acc.z += hv.z * al; acc.w += hv.w * al;
    }
    acc.x *= iv; acc.y *= iv; acc.z *= iv; acc.w *= iv;
    #pragma unroll
    for (int o = 8; o <= 16; o <<= 1) {
        acc.x += __shfl_xor_sync(0xffffffffu, acc.x, o);
        acc.y += __shfl_xor_sync(0xffffffffu, acc.y, o);
        acc.z += __shfl_xor_sync(0xffffffffu, acc.z, o);
        acc.w += __shfl_xor_sync(0xffffffffu, acc.w, o);
    }
    if (lane < 8) {
        int c = lane * 4;
        float4 z = make_float4(0.25f * acc.x + b3[c],     0.25f * acc.y + b3[c + 1],
                               0.25f * acc.z + b3[c + 2], 0.25f * acc.w + b3[c + 3]);
        *(float4*)&g_z[(long)dstN * 32 + c] = z;
    }
}

// ---------------- logits: dot over 32 dims, warp per candidate edge ----------------
__global__ void dot_kernel(const void* __restrict__ eli, float* __restrict__ out) {
    int w = (blockIdx.x * blockDim.x + threadIdx.x) >> 5;
    int lane = threadIdx.x & 31;
    if (w >= ECAND) return;
    int use64 = g_idx64_eli;
    int s = load_idx(eli, use64, w);
    int d = load_idx(eli, use64, (long long)ECAND + w);
    float p = g_z[(long)s * 32 + lane] * g_z[(long)d * 32 + lane];
    #pragma unroll
    for (int o = 16; o; o >>= 1) p += __shfl_xor_sync(0xffffffffu, p, o);
    if (lane == 0) out[w] = p;
}

// ---------------- host launch ----------------
extern "C" void kernel_launch(void* const* d_in, const int* in_sizes, int n_in,
                              void* d_out, int out_size) {
    const float* x   = (const float*)d_in[0];
    const void*  ei  = d_in[1];
    const void*  eli = d_in[2];
    const float* W1  = (const float*)d_in[3];
    const float* a1s = (const float*)d_in[4];
    const float* a1d = (const float*)d_in[5];
    const float* b1  = (const float*)d_in[6];
    const float* W2  = (const float*)d_in[7];
    const float* a2s = (const float*)d_in[8];
    const float* a2d = (const float*)d_in[9];
    const float* b2  = (const float*)d_in[10];
    const float* W3  = (const float*)d_in[11];
    const float* a3s = (const float*)d_in[12];
    const float* a3d = (const float*)d_in[13];
    const float* b3  = (const float*)d_in[14];
    float* out = (float*)d_out;

    float* p_h;
    cudaGetSymbolAddress((void**)&p_h, g_h);
    __nv_bfloat16 *p_Ah, *p_Al, *p_Bh, *p_Bl;
    cudaGetSymbolAddress((void**)&p_Ah, g_pAh);
    cudaGetSymbolAddress((void**)&p_Al, g_pAl);
    cudaGetSymbolAddress((void**)&p_Bh, g_pBh);
    cudaGetSymbolAddress((void**)&p_Bl, g_pBl);

    static bool attr_done = false;
    if (!attr_done) {
        cudaFuncSetAttribute(gemm_tc, cudaFuncAttributeMaxDynamicSharedMemorySize, GEMM_SMEM);
        attr_done = true;
    }

    const int TB = 256;
    const int nodeWarpBlocks = (NNODE * 32 + TB - 1) / TB;   // warp per node
    const int MB = (NNODE + 127) / 128;                      // GEMM row blocks

    // ---- init (detect dtypes, cnt=1, alpha=0) + CSR build ----
    init_detect<<<(NNODE + TB - 1) / TB, TB>>>((const int*)ei, (const int*)eli);
    hist_edges<<<(NEDGE + TB - 1) / TB, TB>>>(ei);
    csr_s1<<<NBLK, 1024>>>();
    csr_s2<<<1, 64>>>();
    csr_s3<<<NBLK, 1024>>>();
    scatter_edges<<<(NEDGE + TB - 1) / TB, TB>>>(ei);

    // ---- split x + all weights ----
    {
        long n = (long)NNODE * 384;
        split_plane<<<(int)((n / 4 + TB - 1) / TB), TB>>>(x, n);
        split_w_all<<<(122880 + TB - 1) / TB, TB>>>(W1, W2, W3);
    }

    // ---- Layer 1: 384 -> 4x64, concat 256, elu ----
    gemm_tc<<<dim3(4, MB), 256, GEMM_SMEM>>>(p_Ah, p_Al, p_Bh, p_Bl, p_h,
                                             a1s, a1d, NNODE, 256, 384, 64);
    edge_softmax<<<nodeWarpBlocks, TB>>>();
    edge_aggregate_elu<256, 64><<<nodeWarpBlocks, TB>>>(b1);

    // ---- Layer 2: 256 -> 4x16, concat 64, elu ----
    gemm_tc<<<dim3(1, MB), 256, GEMM_SMEM>>>(p_Ah, p_Al, p_Bh + 98304, p_Bl + 98304, p_h,
                                             a2s, a2d, NNODE, 64, 256, 16);
    edge_softmax<<<nodeWarpBlocks, TB>>>();
    edge_aggregate_elu<64, 16><<<nodeWarpBlocks, TB>>>(b2);

    // ---- Layer 3: 64 -> 4x32, mean heads -> 32 (fused) ----
    gemm_tc<<<dim3(2, MB), 256, GEMM_SMEM>>>(p_Ah, p_Al, p_Bh + 114688, p_Bl + 114688, p_h,
                                             a3s, a3d, NNODE, 128, 64, 32);
    edge_softmax<<<nodeWarpBlocks, TB>>>();
    edge_aggregate_mean<<<nodeWarpBlocks, TB>>>(b3);

    // ---- Candidate-edge logits ----
    dot_kernel<<<(ECAND * 32 + TB - 1) / TB, TB>>>(eli, out);
}

// round 9
// speedup vs baseline: 3.5132x; 1.0092x over previous
#include <cuda_runtime.h>
#include <cuda_bf16.h>
#include <math.h>
#include <stdint.h>

#define NNODE   50000
#define NEDGE   800000
#define ET      850000      // NEDGE + NNODE self loops
#define ECAND   200000
#define MPAD    50048       // ceil(NNODE/128)*128
#define KMAX    384
#define NBLK    49          // ceil(NNODE/1024)

// ---------------- scratch (device globals; no allocation) ----------------
__device__ __align__(16) __nv_bfloat16 g_pAh[MPAD * KMAX];  // A hi plane
__device__ __align__(16) __nv_bfloat16 g_pAl[MPAD * KMAX];  // A lo plane
// packed W planes [N][K]: L1 @0 (384*256), L2 @98304 (256*64), L3 @114688 (64*128)
__device__ __align__(16) __nv_bfloat16 g_pBh[122880];
__device__ __align__(16) __nv_bfloat16 g_pBl[122880];
__device__ __align__(16) float  g_h[NNODE * 256];           // GEMM output (fp32)
// ping-pong alpha buffers: GEMM-L writes P, agg-L reads P and zeroes Q (next layer's)
__device__ float4 g_alpha_sA[NNODE];
__device__ float4 g_alpha_dA[NNODE];
__device__ float4 g_alpha_sB[NNODE];
__device__ float4 g_alpha_dB[NNODE];
__device__ int    g_esrc[ET];        // CSR: src node per edge, sorted by dst
__device__ int    g_rowoff[NNODE + 1];
__device__ int    g_cnt[NNODE];
__device__ int    g_cursor[NNODE];
__device__ int    g_bsum[64];
__device__ int    g_boff[64];
__device__ __align__(16) float g_z[NNODE * 32];
__device__ int    g_idx64_ei;
__device__ int    g_idx64_eli;

// ---------------- helpers ----------------
__device__ __forceinline__ float lrelu(float v) { return v > 0.f ? v : 0.2f * v; }

__device__ __forceinline__ float sel4(float4 v, int h) {
    return h < 2 ? (h == 0 ? v.x : v.y) : (h == 2 ? v.z : v.w);
}

__device__ __forceinline__ int load_idx(const void* p, int use64, long long pos) {
    return use64 ? (int)((const long long*)p)[pos] : ((const int*)p)[pos];
}

__device__ __forceinline__ void cvt_split(float v, __nv_bfloat16& h, __nv_bfloat16& l) {
    h = __float2bfloat16(v);
    l = __float2bfloat16(v - __bfloat162float(h));
}

__device__ __forceinline__ void cp16(const __nv_bfloat16* s, const __nv_bfloat16* g) {
    uint32_t sa = (uint32_t)__cvta_generic_to_shared(s);
    asm volatile("cp.async.cg.shared.global [%0], [%1], 16;\n" :: "r"(sa), "l"(g));
}

// pass A: per-head max of e over this dst's edges (lanes parallel over edges)
__device__ __forceinline__ float4 warp_head_max(const float4* __restrict__ a_s,
                                                int r0, int r1, int lane, float4 ad) {
    float m0 = -INFINITY, m1 = -INFINITY, m2 = -INFINITY, m3 = -INFINITY;
    for (int e = r0 + lane; e < r1; e += 32) {
        int src = g_esrc[e];
        float4 s = a_s[src];
        m0 = fmaxf(m0, lrelu(s.x + ad.x));
        m1 = fmaxf(m1, lrelu(s.y + ad.y));
        m2 = fmaxf(m2, lrelu(s.z + ad.z));
        m3 = fmaxf(m3, lrelu(s.w + ad.w));
    }
    #pragma unroll
    for (int o = 16; o; o >>= 1) {
        m0 = fmaxf(m0, __shfl_xor_sync(0xffffffffu, m0, o));
        m1 = fmaxf(m1, __shfl_xor_sync(0xffffffffu, m1, o));
        m2 = fmaxf(m2, __shfl_xor_sync(0xffffffffu, m2, o));
        m3 = fmaxf(m3, __shfl_xor_sync(0xffffffffu, m3, o));
    }
    return make_float4(m0, m1, m2, m3);
}

// pass B per-edge: ex for one head, computed warp-wide (lane L evals head L&3),
// fetched per-lane via shfl. Returns src by reference.
__device__ __forceinline__ float edge_ex(const float4* __restrict__ a_s,
                                         int e, float4 ad, float4 m, int myh,
                                         int want, int& src) {
    src = g_esrc[e];
    float4 s = a_s[src];
    float eh = sel4(make_float4(lrelu(s.x + ad.x), lrelu(s.y + ad.y),
                                lrelu(s.z + ad.z), lrelu(s.w + ad.w)), myh)
             - sel4(m, myh);
    float ex = __expf(eh);
    return __shfl_sync(0xffffffffu, ex, want);
}

__device__ __forceinline__ void edge_ex2(const float4* __restrict__ a_s,
                                         int e, float4 ad, float4 m, int myh,
                                         int w0, int w1, float& ex0, float& ex1, int& src) {
    src = g_esrc[e];
    float4 s = a_s[src];
    float eh = sel4(make_float4(lrelu(s.x + ad.x), lrelu(s.y + ad.y),
                                lrelu(s.z + ad.z), lrelu(s.w + ad.w)), myh)
             - sel4(m, myh);
    float ex = __expf(eh);
    ex0 = __shfl_sync(0xffffffffu, ex, w0);
    ex1 = __shfl_sync(0xffffffffu, ex, w1);
}

// ---------------- init: dtype detect + cnt=1 + alphaA zero ----------------
__global__ void init_detect(const int* __restrict__ ei, const int* __restrict__ eli) {
    int i = blockIdx.x * blockDim.x + threadIdx.x;
    if (i < NNODE) {
        g_cnt[i] = 1;   // self loop pre-counted
        g_alpha_sA[i] = make_float4(0, 0, 0, 0);
        g_alpha_dA[i] = make_float4(0, 0, 0, 0);
    }
    if (i == 0) {
        int ok = 1;
        #pragma unroll
        for (int j = 1; j < 64; j += 2) if (ei[j] != 0) { ok = 0; break; }
        g_idx64_ei = ok;
        ok = 1;
        #pragma unroll
        for (int j = 1; j < 64; j += 2) if (eli[j] != 0) { ok = 0; break; }
        g_idx64_eli = ok;
    }
}

// ================= operand splitting (x + all weights, one launch) =========
#define NX4 (NNODE * 384 / 4)
__global__ void split_all(const float* __restrict__ x, const float* __restrict__ W1,
                          const float* __restrict__ W2, const float* __restrict__ W3) {
    int t = blockIdx.x * blockDim.x + threadIdx.x;
    if (t < NX4) {
        long i = (long)t * 4;
        float4 v = *(const float4*)(x + i);
        __nv_bfloat16 h0, h1, h2, h3, l0, l1, l2, l3;
        cvt_split(v.x, h0, l0); cvt_split(v.y, h1, l1);
        cvt_split(v.z, h2, l2); cvt_split(v.w, h3, l3);
        *(__nv_bfloat162*)&g_pAh[i]     = __nv_bfloat162(h0, h1);
        *(__nv_bfloat162*)&g_pAh[i + 2] = __nv_bfloat162(h2, h3);
        *(__nv_bfloat162*)&g_pAl[i]     = __nv_bfloat162(l0, l1);
        *(__nv_bfloat162*)&g_pAl[i + 2] = __nv_bfloat162(l2, l3);
        return;
    }
    int i = t - NX4;
    const float* W; int K, N, off, li;
    if (i < 98304)       { W = W1; K = 384; N = 256; off = 0;      li = i; }
    else if (i < 114688) { W = W2; K = 256; N = 64;  off = 98304;  li = i - 98304; }
    else if (i < 122880) { W = W3; K = 64;  N = 128; off = 114688; li = i - 114688; }
    else return;
    int k = li / N, n = li % N;
    __nv_bfloat16 h, l;
    cvt_split(W[li], h, l);
    g_pBh[off + n * K + k] = h;
    g_pBl[off + n * K + k] = l;
}

// ================= CSR build (parallel scan) =================
__global__ void hist_edges(const void* __restrict__ ei) {
    int e = blockIdx.x * blockDim.x + threadIdx.x;
    if (e >= NEDGE) return;
    int dst = load_idx(ei, g_idx64_ei, (long long)NEDGE + e);
    atomicAdd(&g_cnt[dst], 1);
}

__global__ void csr_s1() {
    __shared__ int ws[32];
    int i = blockIdx.x * 1024 + threadIdx.x;
    int lane = threadIdx.x & 31, wid = threadIdx.x >> 5;
    int v = (i < NNODE) ? g_cnt[i] : 0;
    #pragma unroll
    for (int o = 16; o; o >>= 1) v += __shfl_xor_sync(0xffffffffu, v, o);
    if (lane == 0) ws[wid] = v;
    __syncthreads();
    if (threadIdx.x < 32) {
        int s = ws[threadIdx.x];
        #pragma unroll
        for (int o = 16; o; o >>= 1) s += __shfl_xor_sync(0xffffffffu, s, o);
        if (threadIdx.x == 0) g_bsum[blockIdx.x] = s;
    }
}

__global__ void csr_s2() {
    __shared__ int w0tot;
    int t = threadIdx.x;
    int lane = t & 31, w = t >> 5;
    int v = (t < NBLK) ? g_bsum[t] : 0;
    int x = v;
    #pragma unroll
    for (int o = 1; o < 32; o <<= 1) {
        int y = __shfl_up_sync(0xffffffffu, x, o);
        if (lane >= o) x += y;
    }
    if (t == 31) w0tot = x;
    __syncthreads();
    if (w == 1) x += w0tot;
    if (t < NBLK) g_boff[t] = x - v;
}

__global__ void csr_s3() {
    __shared__ int ws[32];
    int i = blockIdx.x * 1024 + threadIdx.x;
    int lane = threadIdx.x & 31, wid = threadIdx.x >> 5;
    int v = (i < NNODE) ? g_cnt[i] : 0;
    int x = v;
    #pragma unroll
    for (int o = 1; o < 32; o <<= 1) {
        int y = __shfl_up_sync(0xffffffffu, x, o);
        if (lane >= o) x += y;
    }
    if (lane == 31) ws[wid] = x;
    __syncthreads();
    if (wid == 0) {
        int s = ws[lane];
        #pragma unroll
        for (int o = 1; o < 32; o <<= 1) {
            int y = __shfl_up_sync(0xffffffffu, s, o);
            if (lane >= o) s += y;
        }
        ws[lane] = s;
    }
    __syncthreads();
    int ex = x - v + (wid ? ws[wid - 1] : 0) + g_boff[blockIdx.x];
    if (i < NNODE) {
        g_rowoff[i] = ex;
        g_cursor[i] = ex + 1;   // slot 0 of each row = self loop
        g_esrc[ex] = i;
        if (i == NNODE - 1) g_rowoff[NNODE] = ex + v;
    }
}

__global__ void scatter_edges(const void* __restrict__ ei) {
    int e = blockIdx.x * blockDim.x + threadIdx.x;
    if (e >= NEDGE) return;
    int use64 = g_idx64_ei;
    int src = load_idx(ei, use64, e);
    int dst = load_idx(ei, use64, (long long)NEDGE + e);
    int pos = atomicAdd(&g_cursor[dst], 1);
    g_esrc[pos] = src;
}

// ================= split-bf16 tensor-core GEMM + fused alpha epilogue =====
#define BKP 40
#define A_SZ (128 * BKP)
#define B_SZ (64 * BKP)
#define STG  (2 * A_SZ + 2 * B_SZ)
#define GEMM_SMEM (2 * STG * 2)   // bytes

__device__ __forceinline__ void mma16816(float* c, const uint32_t* a, const uint32_t* b) {
    asm volatile(
        "mma.sync.aligned.m16n8k16.row.col.f32.bf16.bf16.f32 "
        "{%0,%1,%2,%3}, {%4,%5,%6,%7}, {%8,%9}, {%0,%1,%2,%3};\n"
        : "+f"(c[0]), "+f"(c[1]), "+f"(c[2]), "+f"(c[3])
        : "r"(a[0]), "r"(a[1]), "r"(a[2]), "r"(a[3]), "r"(b[0]), "r"(b[1]));
}

__global__ __launch_bounds__(256) void gemm_tc(const __nv_bfloat16* __restrict__ Ah,
                                               const __nv_bfloat16* __restrict__ Al,
                                               const __nv_bfloat16* __restrict__ Bth,
                                               const __nv_bfloat16* __restrict__ Btl,
                                               float* __restrict__ C,
                                               const float* __restrict__ a_s,
                                               const float* __restrict__ a_d,
                                               float* __restrict__ alpha_s_out,
                                               float* __restrict__ alpha_d_out,
                                               int M, int N, int K, int Ch) {
    extern __shared__ __nv_bfloat16 sm[];
    const int tid  = threadIdx.x;
    const int lane = tid & 31;
    const int warp = tid >> 5;
    const int wm   = warp & 3;
    const int wn   = warp >> 2;
    const int tr   = lane >> 2;
    const int tc   = lane & 3;
    const int row0 = blockIdx.y * 128;
    const int col0 = blockIdx.x * 64;

    float acc[2][4][4] = {};

    auto stage_load = [&](int s, int k0) {
        __nv_bfloat16* sAh = sm + s * STG;
        __nv_bfloat16* sAl = sAh + A_SZ;
        __nv_bfloat16* sBh = sAl + A_SZ;
        __nv_bfloat16* sBl = sBh + B_SZ;
        #pragma unroll
        for (int i = 0; i < 2; i++) {
            int id = tid + i * 256;
            int row = id >> 2, c = id & 3;
            long gofs = (long)(row0 + row) * K + k0 + c * 8;
            cp16(sAh + row * BKP + c * 8, Ah + gofs);
            cp16(sAl + row * BKP + c * 8, Al + gofs);
        }
        {
            int n = tid >> 2, c = tid & 3;
            long gofs = (long)(col0 + n) * K + k0 + c * 8;
            cp16(sBh + n * BKP + c * 8, Bth + gofs);
            cp16(sBl + n * BKP + c * 8, Btl + gofs);
        }
        asm volatile("cp.async.commit_group;\n" ::: "memory");
    };

    auto compute = [&](int s) {
        const __nv_bfloat16* sAh = sm + s * STG;
        const __nv_bfloat16* sAl = sAh + A_SZ;
        const __nv_bfloat16* sBh = sAl + A_SZ;
        const __nv_bfloat16* sBl = sBh + B_SZ;
        #pragma unroll
        for (int ks = 0; ks < 32; ks += 16) {
            uint32_t ah[2][4], al[2][4], bh[4][2], bl[4][2];
            #pragma unroll
            for (int f = 0; f < 2; f++) {
                int r = wm * 32 + f * 16 + tr;
                int kk = ks + tc * 2;
                ah[f][0] = *(const uint32_t*)&sAh[r * BKP + kk];
                ah[f][1] = *(const uint32_t*)&sAh[(r + 8) * BKP + kk];
                ah[f][2] = *(const uint32_t*)&sAh[r * BKP + kk + 8];
                ah[f][3] = *(const uint32_t*)&sAh[(r + 8) * BKP + kk + 8];
                al[f][0] = *(const uint32_t*)&sAl[r * BKP + kk];
                al[f][1] = *(const uint32_t*)&sAl[(r + 8) * BKP + kk];
                al[f][2] = *(const uint32_t*)&sAl[r * BKP + kk + 8];
                al[f][3] = *(const uint32_t*)&sAl[(r + 8) * BKP + kk + 8];
            }
            #pragma unroll
            for (int g = 0; g < 4; g++) {
                int n = wn * 32 + g * 8 + tr;
                int kk = ks + tc * 2;
                bh[g][0] = *(const uint32_t*)&sBh[n * BKP + kk];
                bh[g][1] = *(const uint32_t*)&sBh[n * BKP + kk + 8];
                bl[g][0] = *(const uint32_t*)&sBl[n * BKP + kk];
                bl[g][1] = *(const uint32_t*)&sBl[n * BKP + kk + 8];
            }
            #pragma unroll
            for (int f = 0; f < 2; f++)
                #pragma unroll
                for (int g = 0; g < 4; g++) {
                    mma16816(acc[f][g], ah[f], bh[g]);
                    mma16816(acc[f][g], ah[f], bl[g]);
                    mma16816(acc[f][g], al[f], bh[g]);
                }
        }
    };

    const int KT = K / 32;
    stage_load(0, 0);
    asm volatile("cp.async.wait_group 0;\n" ::: "memory");
    __syncthreads();
    for (int kt = 0; kt < KT; kt++) {
        int cur = kt & 1;
        if (kt + 1 < KT) stage_load(cur ^ 1, (kt + 1) * 32);
        compute(cur);
        if (kt + 1 < KT) {
            asm volatile("cp.async.wait_group 0;\n" ::: "memory");
            __syncthreads();
        }
    }

    // ---- store C ----
    #pragma unroll
    for (int f = 0; f < 2; f++) {
        int r = row0 + wm * 32 + f * 16 + tr;
        #pragma unroll
        for (int g = 0; g < 4; g++) {
            int c = col0 + wn * 32 + g * 8 + tc * 2;
            if (r < M)
                *(float2*)&C[(long)r * N + c] = make_float2(acc[f][g][0], acc[f][g][1]);
            if (r + 8 < M)
                *(float2*)&C[(long)(r + 8) * N + c] = make_float2(acc[f][g][2], acc[f][g][3]);
        }
    }

    // ---- fused alpha epilogue ----
    float asv[8], adv[8];
    #pragma unroll
    for (int g = 0; g < 4; g++) {
        int colg = col0 + wn * 32 + g * 8 + tc * 2;
        asv[g * 2] = __ldg(&a_s[colg]); asv[g * 2 + 1] = __ldg(&a_s[colg + 1]);
        adv[g * 2] = __ldg(&a_d[colg]); adv[g * 2 + 1] = __ldg(&a_d[colg + 1]);
    }
    const int hlo = (col0 + wn * 32) / Ch;
    const bool two_heads = (Ch == 16);
    #pragma unroll
    for (int f = 0; f < 2; f++) {
        #pragma unroll
        for (int half = 0; half < 2; half++) {
            int row = row0 + wm * 32 + f * 16 + tr + half * 8;
            float psg[4], pdg[4];
            #pragma unroll
            for (int g = 0; g < 4; g++) {
                float a0 = acc[f][g][half * 2], a1 = acc[f][g][half * 2 + 1];
                psg[g] = a0 * asv[g * 2] + a1 * asv[g * 2 + 1];
                pdg[g] = a0 * adv[g * 2] + a1 * adv[g * 2 + 1];
            }
            float s0 = psg[0] + psg[1], s1 = psg[2] + psg[3];
            float d0 = pdg[0] + pdg[1], d1 = pdg[2] + pdg[3];
            #pragma unroll
            for (int o = 1; o <= 2; o <<= 1) {
                s0 += __shfl_xor_sync(0xffffffffu, s0, o);
                s1 += __shfl_xor_sync(0xffffffffu, s1, o);
                d0 += __shfl_xor_sync(0xffffffffu, d0, o);
                d1 += __shfl_xor_sync(0xffffffffu, d1, o);
            }
            if (tc == 0 && row < M) {
                if (two_heads) {
                    atomicAdd(&alpha_s_out[row * 4 + hlo], s0);
                    atomicAdd(&alpha_s_out[row * 4 + hlo + 1], s1);
                    atomicAdd(&alpha_d_out[row * 4 + hlo], d0);
                    atomicAdd(&alpha_d_out[row * 4 + hlo + 1], d1);
                } else {
                    atomicAdd(&alpha_s_out[row * 4 + hlo], s0 + s1);
                    atomicAdd(&alpha_d_out[row * 4 + hlo], d0 + d1);
                }
            }
        }
    }
}

// ========== fused softmax+aggregate kernels ==========
// Read alphas from (a_s, a_d); zero the OTHER buffer pair (next layer's target).

// Layer 1: F=256, C=64. Output: elu(out+bias) -> split bf16 planes.
__global__ void gat_agg_l1(const float* __restrict__ bias) {
    int dstN = (blockIdx.x * blockDim.x + threadIdx.x) >> 5;
    int lane = threadIdx.x & 31;
    if (dstN >= NNODE) return;
    int r0 = g_rowoff[dstN], r1 = g_rowoff[dstN + 1];
    const float4* a_s = g_alpha_sA;
    float4 ad = g_alpha_dA[dstN];
    float4 m = warp_head_max(a_s, r0, r1, lane, ad);

    const int myh = lane & 3;
    const int hd0 = lane >> 4;        // head of features lane*4   (C=64)
    const int hd1 = 2 + (lane >> 4);  // head of features lane*4+128
    float4 acc0 = make_float4(0, 0, 0, 0), acc1 = make_float4(0, 0, 0, 0);
    float den0 = 0.f, den1 = 0.f;

    int e = r0;
    for (; e + 1 < r1; e += 2) {
        int sA, sB; float xA0, xA1, xB0, xB1;
        edge_ex2(a_s, e,     ad, m, myh, hd0, hd1, xA0, xA1, sA);
        edge_ex2(a_s, e + 1, ad, m, myh, hd0, hd1, xB0, xB1, sB);
        const float4* hA = (const float4*)(g_h + (long)sA * 256);
        const float4* hB = (const float4*)(g_h + (long)sB * 256);
        float4 vA0 = hA[lane], vA1 = hA[lane + 32];
        float4 vB0 = hB[lane], vB1 = hB[lane + 32];
        acc0.x += vA0.x * xA0 + vB0.x * xB0;  acc0.y += vA0.y * xA0 + vB0.y * xB0;
        acc0.z += vA0.z * xA0 + vB0.z * xB0;  acc0.w += vA0.w * xA0 + vB0.w * xB0;
        acc1.x += vA1.x * xA1 + vB1.x * xB1;  acc1.y += vA1.y * xA1 + vB1.y * xB1;
        acc1.z += vA1.z * xA1 + vB1.z * xB1;  acc1.w += vA1.w * xA1 + vB1.w * xB1;
        den0 += xA0 + xB0;  den1 += xA1 + xB1;
    }
    if (e < r1) {
        int s; float x0, x1;
        edge_ex2(a_s, e, ad, m, myh, hd0, hd1, x0, x1, s);
        const float4* hp = (const float4*)(g_h + (long)s * 256);
        float4 v0 = hp[lane], v1 = hp[lane + 32];
        acc0.x += v0.x * x0; acc0.y += v0.y * x0; acc0.z += v0.z * x0; acc0.w += v0.w * x0;
        acc1.x += v1.x * x1; acc1.y += v1.y * x1; acc1.z += v1.z * x1; acc1.w += v1.w * x1;
        den0 += x0; den1 += x1;
    }

    float iv0 = 1.f / (den0 + 1e-16f), iv1 = 1.f / (den1 + 1e-16f);
    #pragma unroll
    for (int c = 0; c < 2; c++) {
        int f = lane * 4 + c * 128;
        float iv = c == 0 ? iv0 : iv1;
        float4 r = c == 0 ? acc0 : acc1;
        r.x = r.x * iv + bias[f];     r.y = r.y * iv + bias[f + 1];
        r.z = r.z * iv + bias[f + 2]; r.w = r.w * iv + bias[f + 3];
        r.x = r.x > 0.f ? r.x : expm1f(r.x);
        r.y = r.y > 0.f ? r.y : expm1f(r.y);
        r.z = r.z > 0.f ? r.z : expm1f(r.z);
        r.w = r.w > 0.f ? r.w : expm1f(r.w);
        __nv_bfloat16 h0, h1, h2, h3, l0, l1, l2, l3;
        cvt_split(r.x, h0, l0); cvt_split(r.y, h1, l1);
        cvt_split(r.z, h2, l2); cvt_split(r.w, h3, l3);
        long o = (long)dstN * 256 + f;
        *(__nv_bfloat162*)&g_pAh[o]     = __nv_bfloat162(h0, h1);
        *(__nv_bfloat162*)&g_pAh[o + 2] = __nv_bfloat162(h2, h3);
        *(__nv_bfloat162*)&g_pAl[o]     = __nv_bfloat162(l0, l1);
        *(__nv_bfloat162*)&g_pAl[o + 2] = __nv_bfloat162(l2, l3);
    }
    if (lane == 0) {   // zero buffer B for layer-2 GEMM accumulation (safe: B unread here)
        g_alpha_sB[dstN] = make_float4(0, 0, 0, 0);
        g_alpha_dB[dstN] = make_float4(0, 0, 0, 0);
    }
}

// Layer 2: F=64, C=16. Output: elu(out+bias) -> split bf16 planes.
__global__ void gat_agg_l2(const float* __restrict__ bias) {
    int dstN = (blockIdx.x * blockDim.x + threadIdx.x) >> 5;
    int lane = threadIdx.x & 31;
    if (dstN >= NNODE) return;
    int r0 = g_rowoff[dstN], r1 = g_rowoff[dstN + 1];
    const float4* a_s = g_alpha_sB;
    float4 ad = g_alpha_dB[dstN];
    float4 m = warp_head_max(a_s, r0, r1, lane, ad);

    const int myh = lane & 3;
    const int f = lane * 2;
    const int hd = lane >> 3;   // head of features lane*2 (C=16)
    float a0 = 0.f, a1 = 0.f, den = 0.f;

    int e = r0;
    for (; e + 1 < r1; e += 2) {
        int sA, sB;
        float xA = edge_ex(a_s, e,     ad, m, myh, hd, sA);
        float xB = edge_ex(a_s, e + 1, ad, m, myh, hd, sB);
        float2 hA = *(const float2*)(g_h + (long)sA * 64 + f);
        float2 hB = *(const float2*)(g_h + (long)sB * 64 + f);
        a0 += hA.x * xA + hB.x * xB;
        a1 += hA.y * xA + hB.y * xB;
        den += xA + xB;
    }
    if (e < r1) {
        int s;
        float x = edge_ex(a_s, e, ad, m, myh, hd, s);
        float2 hv = *(const float2*)(g_h + (long)s * 64 + f);
        a0 += hv.x * x; a1 += hv.y * x; den += x;
    }

    float iv = 1.f / (den + 1e-16f);
    a0 = a0 * iv + bias[f];
    a1 = a1 * iv + bias[f + 1];
    a0 = a0 > 0.f ? a0 : expm1f(a0);
    a1 = a1 > 0.f ? a1 : expm1f(a1);
    __nv_bfloat16 h0, h1, l0, l1;
    cvt_split(a0, h0, l0); cvt_split(a1, h1, l1);
    *(__nv_bfloat162*)&g_pAh[(long)dstN * 64 + f] = __nv_bfloat162(h0, h1);
    *(__nv_bfloat162*)&g_pAl[(long)dstN * 64 + f] = __nv_bfloat162(l0, l1);
    if (lane == 0) {   // zero buffer A for layer-3 GEMM accumulation
        g_alpha_sA[dstN] = make_float4(0, 0, 0, 0);
        g_alpha_dA[dstN] = make_float4(0, 0, 0, 0);
    }
}

// Layer 3: F=128, C=32, fused head-mean + b3 -> g_z.
__global__ void gat_agg_l3(const float* __restrict__ b3) {
    int dstN = (blockIdx.x * blockDim.x + threadIdx.x) >> 5;
    int lane = threadIdx.x & 31;
    if (dstN >= NNODE) return;
    int r0 = g_rowoff[dstN], r1 = g_rowoff[dstN + 1];
    const float4* a_s = g_alpha_sA;
    float4 ad = g_alpha_dA[dstN];
    float4 m = warp_head_max(a_s, r0, r1, lane, ad);

    const int myh = lane & 3;
    const int hd = lane >> 3;   // head of features lane*4 (C=32)
    float4 acc = make_float4(0, 0, 0, 0);
    float den = 0.f;

    int e = r0;
    for (; e + 1 < r1; e += 2) {
        int sA, sB;
        float xA = edge_ex(a_s, e,     ad, m, myh, hd, sA);
        float xB = edge_ex(a_s, e + 1, ad, m, myh, hd, sB);
        float4 vA = ((const float4*)(g_h + (long)sA * 128))[lane];
        float4 vB = ((const float4*)(g_h + (long)sB * 128))[lane];
        acc.x += vA.x * xA + vB.x * xB;  acc.y += vA.y * xA + vB.y * xB;
        acc.z += vA.z * xA + vB.z * xB;  acc.w += vA.w * xA + vB.w * xB;
        den += xA + xB;
    }
    if (e < r1) {
        int s;
        float x = edge_ex(a_s, e, ad, m, myh, hd, s);
        float4 v = ((const float4*)(g_h + (long)s * 128))[lane];
        acc.x += v.x * x; acc.y += v.y * x; acc.z += v.z * x; acc.w += v.w * x;
        den += x;
    }

    float iv = 1.f / (den + 1e-16f);
    acc.x *= iv; acc.y *= iv; acc.z *= iv; acc.w *= iv;
    #pragma unroll
    for (int o = 8; o <= 16; o <<= 1) {
        acc.x += __shfl_xor_sync(0xffffffffu, acc.x, o);
        acc.y += __shfl_xor_sync(0xffffffffu, acc.y, o);
        acc.z += __shfl_xor_sync(0xffffffffu, acc.z, o);
        acc.w += __shfl_xor_sync(0xffffffffu, acc.w, o);
    }
    if (lane < 8) {
        int c = lane * 4;
        float4 z = make_float4(0.25f * acc.x + b3[c],     0.25f * acc.y + b3[c + 1],
                               0.25f * acc.z + b3[c + 2], 0.25f * acc.w + b3[c + 3]);
        *(float4*)&g_z[(long)dstN * 32 + c] = z;
    }
}

// ---------------- logits: dot over 32 dims, warp per candidate edge ----------------
__global__ void dot_kernel(const void* __restrict__ eli, float* __restrict__ out) {
    int w = (blockIdx.x * blockDim.x + threadIdx.x) >> 5;
    int lane = threadIdx.x & 31;
    if (w >= ECAND) return;
    int use64 = g_idx64_eli;
    int s = load_idx(eli, use64, w);
    int d = load_idx(eli, use64, (long long)ECAND + w);
    float p = g_z[(long)s * 32 + lane] * g_z[(long)d * 32 + lane];
    #pragma unroll
    for (int o = 16; o; o >>= 1) p += __shfl_xor_sync(0xffffffffu, p, o);
    if (lane == 0) out[w] = p;
}

// ---------------- host launch ----------------
extern "C" void kernel_launch(void* const* d_in, const int* in_sizes, int n_in,
                              void* d_out, int out_size) {
    const float* x   = (const float*)d_in[0];
    const void*  ei  = d_in[1];
    const void*  eli = d_in[2];
    const float* W1  = (const float*)d_in[3];
    const float* a1s = (const float*)d_in[4];
    const float* a1d = (const float*)d_in[5];
    const float* b1  = (const float*)d_in[6];
    const float* W2  = (const float*)d_in[7];
    const float* a2s = (const float*)d_in[8];
    const float* a2d = (const float*)d_in[9];
    const float* b2  = (const float*)d_in[10];
    const float* W3  = (const float*)d_in[11];
    const float* a3s = (const float*)d_in[12];
    const float* a3d = (const float*)d_in[13];
    const float* b3  = (const float*)d_in[14];
    float* out = (float*)d_out;

    float* p_h;
    cudaGetSymbolAddress((void**)&p_h, g_h);
    __nv_bfloat16 *p_Ah, *p_Al, *p_Bh, *p_Bl;
    cudaGetSymbolAddress((void**)&p_Ah, g_pAh);
    cudaGetSymbolAddress((void**)&p_Al, g_pAl);
    cudaGetSymbolAddress((void**)&p_Bh, g_pBh);
    cudaGetSymbolAddress((void**)&p_Bl, g_pBl);
    float *p_asA, *p_adA, *p_asB, *p_adB;
    cudaGetSymbolAddress((void**)&p_asA, g_alpha_sA);
    cudaGetSymbolAddress((void**)&p_adA, g_alpha_dA);
    cudaGetSymbolAddress((void**)&p_asB, g_alpha_sB);
    cudaGetSymbolAddress((void**)&p_adB, g_alpha_dB);

    static bool attr_done = false;
    if (!attr_done) {
        cudaFuncSetAttribute(gemm_tc, cudaFuncAttributeMaxDynamicSharedMemorySize, GEMM_SMEM);
        attr_done = true;
    }

    const int TB = 256;
    const int nodeWarpBlocks = (NNODE * 32 + TB - 1) / TB;   // warp per node
    const int MB = (NNODE + 127) / 128;                      // GEMM row blocks

    // ---- init + CSR build ----
    init_detect<<<(NNODE + TB - 1) / TB, TB>>>((const int*)ei, (const int*)eli);
    hist_edges<<<(NEDGE + TB - 1) / TB, TB>>>(ei);
    csr_s1<<<NBLK, 1024>>>();
    csr_s2<<<1, 64>>>();
    csr_s3<<<NBLK, 1024>>>();
    scatter_edges<<<(NEDGE + TB - 1) / TB, TB>>>(ei);

    // ---- split x + all weights (one launch) ----
    split_all<<<(NX4 + 122880 + TB - 1) / TB, TB>>>(x, W1, W2, W3);

    // ---- Layer 1: GEMM -> alphaA; agg reads alphaA, zeroes alphaB ----
    gemm_tc<<<dim3(4, MB), 256, GEMM_SMEM>>>(p_Ah, p_Al, p_Bh, p_Bl, p_h,
                                             a1s, a1d, p_asA, p_adA, NNODE, 256, 384, 64);
    gat_agg_l1<<<nodeWarpBlocks, TB>>>(b1);

    // ---- Layer 2: GEMM -> alphaB; agg reads alphaB, zeroes alphaA ----
    gemm_tc<<<dim3(1, MB), 256, GEMM_SMEM>>>(p_Ah, p_Al, p_Bh + 98304, p_Bl + 98304, p_h,
                                             a2s, a2d, p_asB, p_adB, NNODE, 64, 256, 16);
    gat_agg_l2<<<nodeWarpBlocks, TB>>>(b2);

    // ---- Layer 3: GEMM -> alphaA; agg reads alphaA ----
    gemm_tc<<<dim3(2, MB), 256, GEMM_SMEM>>>(p_Ah, p_Al, p_Bh + 114688, p_Bl + 114688, p_h,
                                             a3s, a3d, p_asA, p_adA, NNODE, 128, 64, 32);
    gat_agg_l3<<<nodeWarpBlocks, TB>>>(b3);

    // ---- Candidate-edge logits ----
    dot_kernel<<<(ECAND * 32 + TB - 1) / TB, TB>>>(eli, out);
}

// round 10
// speedup vs baseline: 3.5943x; 1.0231x over previous
#include <cuda_runtime.h>
#include <cuda_bf16.h>
#include <math.h>
#include <stdint.h>

#define NNODE   50000
#define NEDGE   800000
#define ET      850000      // NEDGE + NNODE self loops
#define ECAND   200000
#define MPAD    50048       // ceil(NNODE/128)*128
#define KMAX    384
#define NBLK    49          // ceil(NNODE/1024)

// ---------------- scratch (device globals; no allocation) ----------------
__device__ __align__(16) __nv_bfloat16 g_pAh[MPAD * KMAX];  // A hi plane
__device__ __align__(16) __nv_bfloat16 g_pAl[MPAD * KMAX];  // A lo plane
// packed W planes [N][K]: L1 @0 (384*256), L2 @98304 (256*64), L3 @114688 (64*128)
__device__ __align__(16) __nv_bfloat16 g_pBh[122880];
__device__ __align__(16) __nv_bfloat16 g_pBl[122880];
__device__ __align__(16) float  g_h[NNODE * 256];           // GEMM output (fp32)
// ping-pong alpha buffers: GEMM-L writes P, agg-L reads P and zeroes Q (next layer's)
__device__ float4 g_alpha_sA[NNODE];
__device__ float4 g_alpha_dA[NNODE];
__device__ float4 g_alpha_sB[NNODE];
__device__ float4 g_alpha_dB[NNODE];
__device__ int    g_esrc[ET];        // CSR: src node per edge, sorted by dst
__device__ int    g_rowoff[NNODE + 1];
__device__ int    g_cnt[NNODE];
__device__ int    g_cursor[NNODE];
__device__ int    g_bsum[64];
__device__ int    g_boff[64];
__device__ __align__(16) float g_z[NNODE * 32];
__device__ int    g_idx64_ei;
__device__ int    g_idx64_eli;

// ---------------- helpers ----------------
__device__ __forceinline__ float lrelu(float v) { return v > 0.f ? v : 0.2f * v; }

__device__ __forceinline__ float sel4(float4 v, int h) {
    return h < 2 ? (h == 0 ? v.x : v.y) : (h == 2 ? v.z : v.w);
}

__device__ __forceinline__ int load_idx(const void* p, int use64, long long pos) {
    return use64 ? (int)((const long long*)p)[pos] : ((const int*)p)[pos];
}

__device__ __forceinline__ void cvt_split(float v, __nv_bfloat16& h, __nv_bfloat16& l) {
    h = __float2bfloat16(v);
    l = __float2bfloat16(v - __bfloat162float(h));
}

__device__ __forceinline__ void cp16(const __nv_bfloat16* s, const __nv_bfloat16* g) {
    uint32_t sa = (uint32_t)__cvta_generic_to_shared(s);
    asm volatile("cp.async.cg.shared.global [%0], [%1], 16;\n" :: "r"(sa), "l"(g));
}

// per-edge: ex for one head, computed warp-wide (lane L evals head L&3),
// fetched per-lane via shfl. No max subtraction (softmax is shift-invariant;
// |e| <~ 15 here so exp stays far from fp32 limits). Returns src by reference.
__device__ __forceinline__ float edge_ex(const float4* __restrict__ a_s,
                                         int e, float4 ad, int myh,
                                         int want, int& src) {
    src = g_esrc[e];
    float4 s = a_s[src];
    float eh = sel4(make_float4(lrelu(s.x + ad.x), lrelu(s.y + ad.y),
                                lrelu(s.z + ad.z), lrelu(s.w + ad.w)), myh);
    float ex = __expf(eh);
    return __shfl_sync(0xffffffffu, ex, want);
}

__device__ __forceinline__ void edge_ex2(const float4* __restrict__ a_s,
                                         int e, float4 ad, int myh,
                                         int w0, int w1, float& ex0, float& ex1, int& src) {
    src = g_esrc[e];
    float4 s = a_s[src];
    float eh = sel4(make_float4(lrelu(s.x + ad.x), lrelu(s.y + ad.y),
                                lrelu(s.z + ad.z), lrelu(s.w + ad.w)), myh);
    float ex = __expf(eh);
    ex0 = __shfl_sync(0xffffffffu, ex, w0);
    ex1 = __shfl_sync(0xffffffffu, ex, w1);
}

// ---------------- init: dtype detect + cnt=1 + alphaA zero ----------------
__global__ void init_detect(const int* __restrict__ ei, const int* __restrict__ eli) {
    int i = blockIdx.x * blockDim.x + threadIdx.x;
    if (i < NNODE) {
        g_cnt[i] = 1;   // self loop pre-counted
        g_alpha_sA[i] = make_float4(0, 0, 0, 0);
        g_alpha_dA[i] = make_float4(0, 0, 0, 0);
    }
    if (i == 0) {
        int ok = 1;
        #pragma unroll
        for (int j = 1; j < 64; j += 2) if (ei[j] != 0) { ok = 0; break; }
        g_idx64_ei = ok;
        ok = 1;
        #pragma unroll
        for (int j = 1; j < 64; j += 2) if (eli[j] != 0) { ok = 0; break; }
        g_idx64_eli = ok;
    }
}

// ================= operand splitting (x + all weights, one launch) =========
#define NX4 (NNODE * 384 / 4)
__global__ void split_all(const float* __restrict__ x, const float* __restrict__ W1,
                          const float* __restrict__ W2, const float* __restrict__ W3) {
    int t = blockIdx.x * blockDim.x + threadIdx.x;
    if (t < NX4) {
        long i = (long)t * 4;
        float4 v = *(const float4*)(x + i);
        __nv_bfloat16 h0, h1, h2, h3, l0, l1, l2, l3;
        cvt_split(v.x, h0, l0); cvt_split(v.y, h1, l1);
        cvt_split(v.z, h2, l2); cvt_split(v.w, h3, l3);
        *(__nv_bfloat162*)&g_pAh[i]     = __nv_bfloat162(h0, h1);
        *(__nv_bfloat162*)&g_pAh[i + 2] = __nv_bfloat162(h2, h3);
        *(__nv_bfloat162*)&g_pAl[i]     = __nv_bfloat162(l0, l1);
        *(__nv_bfloat162*)&g_pAl[i + 2] = __nv_bfloat162(l2, l3);
        return;
    }
    int i = t - NX4;
    const float* W; int K, N, off, li;
    if (i < 98304)       { W = W1; K = 384; N = 256; off = 0;      li = i; }
    else if (i < 114688) { W = W2; K = 256; N = 64;  off = 98304;  li = i - 98304; }
    else if (i < 122880) { W = W3; K = 64;  N = 128; off = 114688; li = i - 114688; }
    else return;
    int k = li / N, n = li % N;
    __nv_bfloat16 h, l;
    cvt_split(W[li], h, l);
    g_pBh[off + n * K + k] = h;
    g_pBl[off + n * K + k] = l;
}

// ================= CSR build (parallel scan) =================
__global__ void hist_edges(const void* __restrict__ ei) {
    int e = blockIdx.x * blockDim.x + threadIdx.x;
    if (e >= NEDGE) return;
    int dst = load_idx(ei, g_idx64_ei, (long long)NEDGE + e);
    atomicAdd(&g_cnt[dst], 1);
}

__global__ void csr_s1() {
    __shared__ int ws[32];
    int i = blockIdx.x * 1024 + threadIdx.x;
    int lane = threadIdx.x & 31, wid = threadIdx.x >> 5;
    int v = (i < NNODE) ? g_cnt[i] : 0;
    #pragma unroll
    for (int o = 16; o; o >>= 1) v += __shfl_xor_sync(0xffffffffu, v, o);
    if (lane == 0) ws[wid] = v;
    __syncthreads();
    if (threadIdx.x < 32) {
        int s = ws[threadIdx.x];
        #pragma unroll
        for (int o = 16; o; o >>= 1) s += __shfl_xor_sync(0xffffffffu, s, o);
        if (threadIdx.x == 0) g_bsum[blockIdx.x] = s;
    }
}

__global__ void csr_s2() {
    __shared__ int w0tot;
    int t = threadIdx.x;
    int lane = t & 31, w = t >> 5;
    int v = (t < NBLK) ? g_bsum[t] : 0;
    int x = v;
    #pragma unroll
    for (int o = 1; o < 32; o <<= 1) {
        int y = __shfl_up_sync(0xffffffffu, x, o);
        if (lane >= o) x += y;
    }
    if (t == 31) w0tot = x;
    __syncthreads();
    if (w == 1) x += w0tot;
    if (t < NBLK) g_boff[t] = x - v;
}

__global__ void csr_s3() {
    __shared__ int ws[32];
    int i = blockIdx.x * 1024 + threadIdx.x;
    int lane = threadIdx.x & 31, wid = threadIdx.x >> 5;
    int v = (i < NNODE) ? g_cnt[i] : 0;
    int x = v;
    #pragma unroll
    for (int o = 1; o < 32; o <<= 1) {
        int y = __shfl_up_sync(0xffffffffu, x, o);
        if (lane >= o) x += y;
    }
    if (lane == 31) ws[wid] = x;
    __syncthreads();
    if (wid == 0) {
        int s = ws[lane];
        #pragma unroll
        for (int o = 1; o < 32; o <<= 1) {
            int y = __shfl_up_sync(0xffffffffu, s, o);
            if (lane >= o) s += y;
        }
        ws[lane] = s;
    }
    __syncthreads();
    int ex = x - v + (wid ? ws[wid - 1] : 0) + g_boff[blockIdx.x];
    if (i < NNODE) {
        g_rowoff[i] = ex;
        g_cursor[i] = ex + 1;   // slot 0 of each row = self loop
        g_esrc[ex] = i;
        if (i == NNODE - 1) g_rowoff[NNODE] = ex + v;
    }
}

__global__ void scatter_edges(const void* __restrict__ ei) {
    int e = blockIdx.x * blockDim.x + threadIdx.x;
    if (e >= NEDGE) return;
    int use64 = g_idx64_ei;
    int src = load_idx(ei, use64, e);
    int dst = load_idx(ei, use64, (long long)NEDGE + e);
    int pos = atomicAdd(&g_cursor[dst], 1);
    g_esrc[pos] = src;
}

// ================= split-bf16 tensor-core GEMM + fused alpha epilogue =====
#define BKP 40
#define A_SZ (128 * BKP)
#define B_SZ (64 * BKP)
#define STG  (2 * A_SZ + 2 * B_SZ)
#define GEMM_SMEM (2 * STG * 2)   // bytes

__device__ __forceinline__ void mma16816(float* c, const uint32_t* a, const uint32_t* b) {
    asm volatile(
        "mma.sync.aligned.m16n8k16.row.col.f32.bf16.bf16.f32 "
        "{%0,%1,%2,%3}, {%4,%5,%6,%7}, {%8,%9}, {%0,%1,%2,%3};\n"
        : "+f"(c[0]), "+f"(c[1]), "+f"(c[2]), "+f"(c[3])
        : "r"(a[0]), "r"(a[1]), "r"(a[2]), "r"(a[3]), "r"(b[0]), "r"(b[1]));
}

__global__ __launch_bounds__(256) void gemm_tc(const __nv_bfloat16* __restrict__ Ah,
                                               const __nv_bfloat16* __restrict__ Al,
                                               const __nv_bfloat16* __restrict__ Bth,
                                               const __nv_bfloat16* __restrict__ Btl,
                                               float* __restrict__ C,
                                               const float* __restrict__ a_s,
                                               const float* __restrict__ a_d,
                                               float* __restrict__ alpha_s_out,
                                               float* __restrict__ alpha_d_out,
                                               int M, int N, int K, int Ch) {
    extern __shared__ __nv_bfloat16 sm[];
    const int tid  = threadIdx.x;
    const int lane = tid & 31;
    const int warp = tid >> 5;
    const int wm   = warp & 3;
    const int wn   = warp >> 2;
    const int tr   = lane >> 2;
    const int tc   = lane & 3;
    const int row0 = blockIdx.y * 128;
    const int col0 = blockIdx.x * 64;

    float acc[2][4][4] = {};

    auto stage_load = [&](int s, int k0) {
        __nv_bfloat16* sAh = sm + s * STG;
        __nv_bfloat16* sAl = sAh + A_SZ;
        __nv_bfloat16* sBh = sAl + A_SZ;
        __nv_bfloat16* sBl = sBh + B_SZ;
        #pragma unroll
        for (int i = 0; i < 2; i++) {
            int id = tid + i * 256;
            int row = id >> 2, c = id & 3;
            long gofs = (long)(row0 + row) * K + k0 + c * 8;
            cp16(sAh + row * BKP + c * 8, Ah + gofs);
            cp16(sAl + row * BKP + c * 8, Al + gofs);
        }
        {
            int n = tid >> 2, c = tid & 3;
            long gofs = (long)(col0 + n) * K + k0 + c * 8;
            cp16(sBh + n * BKP + c * 8, Bth + gofs);
            cp16(sBl + n * BKP + c * 8, Btl + gofs);
        }
        asm volatile("cp.async.commit_group;\n" ::: "memory");
    };

    auto compute = [&](int s) {
        const __nv_bfloat16* sAh = sm + s * STG;
        const __nv_bfloat16* sAl = sAh + A_SZ;
        const __nv_bfloat16* sBh = sAl + A_SZ;
        const __nv_bfloat16* sBl = sBh + B_SZ;
        #pragma unroll
        for (int ks = 0; ks < 32; ks += 16) {
            uint32_t ah[2][4], al[2][4], bh[4][2], bl[4][2];
            #pragma unroll
            for (int f = 0; f < 2; f++) {
                int r = wm * 32 + f * 16 + tr;
                int kk = ks + tc * 2;
                ah[f][0] = *(const uint32_t*)&sAh[r * BKP + kk];
                ah[f][1] = *(const uint32_t*)&sAh[(r + 8) * BKP + kk];
                ah[f][2] = *(const uint32_t*)&sAh[r * BKP + kk + 8];
                ah[f][3] = *(const uint32_t*)&sAh[(r + 8) * BKP + kk + 8];
                al[f][0] = *(const uint32_t*)&sAl[r * BKP + kk];
                al[f][1] = *(const uint32_t*)&sAl[(r + 8) * BKP + kk];
                al[f][2] = *(const uint32_t*)&sAl[r * BKP + kk + 8];
                al[f][3] = *(const uint32_t*)&sAl[(r + 8) * BKP + kk + 8];
            }
            #pragma unroll
            for (int g = 0; g < 4; g++) {
                int n = wn * 32 + g * 8 + tr;
                int kk = ks + tc * 2;
                bh[g][0] = *(const uint32_t*)&sBh[n * BKP + kk];
                bh[g][1] = *(const uint32_t*)&sBh[n * BKP + kk + 8];
                bl[g][0] = *(const uint32_t*)&sBl[n * BKP + kk];
                bl[g][1] = *(const uint32_t*)&sBl[n * BKP + kk + 8];
            }
            #pragma unroll
            for (int f = 0; f < 2; f++)
                #pragma unroll
                for (int g = 0; g < 4; g++) {
                    mma16816(acc[f][g], ah[f], bh[g]);
                    mma16816(acc[f][g], ah[f], bl[g]);
                    mma16816(acc[f][g], al[f], bh[g]);
                }
        }
    };

    const int KT = K / 32;
    stage_load(0, 0);
    asm volatile("cp.async.wait_group 0;\n" ::: "memory");
    __syncthreads();
    for (int kt = 0; kt < KT; kt++) {
        int cur = kt & 1;
        if (kt + 1 < KT) stage_load(cur ^ 1, (kt + 1) * 32);
        compute(cur);
        if (kt + 1 < KT) {
            asm volatile("cp.async.wait_group 0;\n" ::: "memory");
            __syncthreads();
        }
    }

    // ---- store C ----
    #pragma unroll
    for (int f = 0; f < 2; f++) {
        int r = row0 + wm * 32 + f * 16 + tr;
        #pragma unroll
        for (int g = 0; g < 4; g++) {
            int c = col0 + wn * 32 + g * 8 + tc * 2;
            if (r < M)
                *(float2*)&C[(long)r * N + c] = make_float2(acc[f][g][0], acc[f][g][1]);
            if (r + 8 < M)
                *(float2*)&C[(long)(r + 8) * N + c] = make_float2(acc[f][g][2], acc[f][g][3]);
        }
    }

    // ---- fused alpha epilogue ----
    float asv[8], adv[8];
    #pragma unroll
    for (int g = 0; g < 4; g++) {
        int colg = col0 + wn * 32 + g * 8 + tc * 2;
        asv[g * 2] = __ldg(&a_s[colg]); asv[g * 2 + 1] = __ldg(&a_s[colg + 1]);
        adv[g * 2] = __ldg(&a_d[colg]); adv[g * 2 + 1] = __ldg(&a_d[colg + 1]);
    }
    const int hlo = (col0 + wn * 32) / Ch;
    const bool two_heads = (Ch == 16);
    #pragma unroll
    for (int f = 0; f < 2; f++) {
        #pragma unroll
        for (int half = 0; half < 2; half++) {
            int row = row0 + wm * 32 + f * 16 + tr + half * 8;
            float psg[4], pdg[4];
            #pragma unroll
            for (int g = 0; g < 4; g++) {
                float a0 = acc[f][g][half * 2], a1 = acc[f][g][half * 2 + 1];
                psg[g] = a0 * asv[g * 2] + a1 * asv[g * 2 + 1];
                pdg[g] = a0 * adv[g * 2] + a1 * adv[g * 2 + 1];
            }
            float s0 = psg[0] + psg[1], s1 = psg[2] + psg[3];
            float d0 = pdg[0] + pdg[1], d1 = pdg[2] + pdg[3];
            #pragma unroll
            for (int o = 1; o <= 2; o <<= 1) {
                s0 += __shfl_xor_sync(0xffffffffu, s0, o);
                s1 += __shfl_xor_sync(0xffffffffu, s1, o);
                d0 += __shfl_xor_sync(0xffffffffu, d0, o);
                d1 += __shfl_xor_sync(0xffffffffu, d1, o);
            }
            if (tc == 0 && row < M) {
                if (two_heads) {
                    atomicAdd(&alpha_s_out[row * 4 + hlo], s0);
                    atomicAdd(&alpha_s_out[row * 4 + hlo + 1], s1);
                    atomicAdd(&alpha_d_out[row * 4 + hlo], d0);
                    atomicAdd(&alpha_d_out[row * 4 + hlo + 1], d1);
                } else {
                    atomicAdd(&alpha_s_out[row * 4 + hlo], s0 + s1);
                    atomicAdd(&alpha_d_out[row * 4 + hlo], d0 + d1);
                }
            }
        }
    }
}

// ========== fused softmax+aggregate kernels (single pass, no max) ==========
// Read alphas from one ping-pong buffer; zero the OTHER pair (next layer's).

// Layer 1: F=256, C=64. Output: elu(out+bias) -> split bf16 planes.
__global__ void gat_agg_l1(const float* __restrict__ bias) {
    int dstN = (blockIdx.x * blockDim.x + threadIdx.x) >> 5;
    int lane = threadIdx.x & 31;
    if (dstN >= NNODE) return;
    int r0 = g_rowoff[dstN], r1 = g_rowoff[dstN + 1];
    const float4* a_s = g_alpha_sA;
    float4 ad = g_alpha_dA[dstN];

    const int myh = lane & 3;
    const int hd0 = lane >> 4;        // head of features lane*4   (C=64)
    const int hd1 = 2 + (lane >> 4);  // head of features lane*4+128
    float4 acc0 = make_float4(0, 0, 0, 0), acc1 = make_float4(0, 0, 0, 0);
    float den0 = 0.f, den1 = 0.f;

    int e = r0;
    for (; e + 1 < r1; e += 2) {
        int sA, sB; float xA0, xA1, xB0, xB1;
        edge_ex2(a_s, e,     ad, myh, hd0, hd1, xA0, xA1, sA);
        edge_ex2(a_s, e + 1, ad, myh, hd0, hd1, xB0, xB1, sB);
        const float4* hA = (const float4*)(g_h + (long)sA * 256);
        const float4* hB = (const float4*)(g_h + (long)sB * 256);
        float4 vA0 = hA[lane], vA1 = hA[lane + 32];
        float4 vB0 = hB[lane], vB1 = hB[lane + 32];
        acc0.x += vA0.x * xA0 + vB0.x * xB0;  acc0.y += vA0.y * xA0 + vB0.y * xB0;
        acc0.z += vA0.z * xA0 + vB0.z * xB0;  acc0.w += vA0.w * xA0 + vB0.w * xB0;
        acc1.x += vA1.x * xA1 + vB1.x * xB1;  acc1.y += vA1.y * xA1 + vB1.y * xB1;
        acc1.z += vA1.z * xA1 + vB1.z * xB1;  acc1.w += vA1.w * xA1 + vB1.w * xB1;
        den0 += xA0 + xB0;  den1 += xA1 + xB1;
    }
    if (e < r1) {
        int s; float x0, x1;
        edge_ex2(a_s, e, ad, myh, hd0, hd1, x0, x1, s);
        const float4* hp = (const float4*)(g_h + (long)s * 256);
        float4 v0 = hp[lane], v1 = hp[lane + 32];
        acc0.x += v0.x * x0; acc0.y += v0.y * x0; acc0.z += v0.z * x0; acc0.w += v0.w * x0;
        acc1.x += v1.x * x1; acc1.y += v1.y * x1; acc1.z += v1.z * x1; acc1.w += v1.w * x1;
        den0 += x0; den1 += x1;
    }

    float iv0 = 1.f / (den0 + 1e-16f), iv1 = 1.f / (den1 + 1e-16f);
    #pragma unroll
    for (int c = 0; c < 2; c++) {
        int f = lane * 4 + c * 128;
        float iv = c == 0 ? iv0 : iv1;
        float4 r = c == 0 ? acc0 : acc1;
        r.x = r.x * iv + bias[f];     r.y = r.y * iv + bias[f + 1];
        r.z = r.z * iv + bias[f + 2]; r.w = r.w * iv + bias[f + 3];
        r.x = r.x > 0.f ? r.x : expm1f(r.x);
        r.y = r.y > 0.f ? r.y : expm1f(r.y);
        r.z = r.z > 0.f ? r.z : expm1f(r.z);
        r.w = r.w > 0.f ? r.w : expm1f(r.w);
        __nv_bfloat16 h0, h1, h2, h3, l0, l1, l2, l3;
        cvt_split(r.x, h0, l0); cvt_split(r.y, h1, l1);
        cvt_split(r.z, h2, l2); cvt_split(r.w, h3, l3);
        long o = (long)dstN * 256 + f;
        *(__nv_bfloat162*)&g_pAh[o]     = __nv_bfloat162(h0, h1);
        *(__nv_bfloat162*)&g_pAh[o + 2] = __nv_bfloat162(h2, h3);
        *(__nv_bfloat162*)&g_pAl[o]     = __nv_bfloat162(l0, l1);
        *(__nv_bfloat162*)&g_pAl[o + 2] = __nv_bfloat162(l2, l3);
    }
    if (lane == 0) {   // zero buffer B for layer-2 GEMM accumulation (safe: B unread here)
        g_alpha_sB[dstN] = make_float4(0, 0, 0, 0);
        g_alpha_dB[dstN] = make_float4(0, 0, 0, 0);
    }
}

// Layer 2: F=64, C=16. Output: elu(out+bias) -> split bf16 planes.
__global__ void gat_agg_l2(const float* __restrict__ bias) {
    int dstN = (blockIdx.x * blockDim.x + threadIdx.x) >> 5;
    int lane = threadIdx.x & 31;
    if (dstN >= NNODE) return;
    int r0 = g_rowoff[dstN], r1 = g_rowoff[dstN + 1];
    const float4* a_s = g_alpha_sB;
    float4 ad = g_alpha_dB[dstN];

    const int myh = lane & 3;
    const int f = lane * 2;
    const int hd = lane >> 3;   // head of features lane*2 (C=16)
    float a0 = 0.f, a1 = 0.f, den = 0.f;

    int e = r0;
    for (; e + 1 < r1; e += 2) {
        int sA, sB;
        float xA = edge_ex(a_s, e,     ad, myh, hd, sA);
        float xB = edge_ex(a_s, e + 1, ad, myh, hd, sB);
        float2 hA = *(const float2*)(g_h + (long)sA * 64 + f);
        float2 hB = *(const float2*)(g_h + (long)sB * 64 + f);
        a0 += hA.x * xA + hB.x * xB;
        a1 += hA.y * xA + hB.y * xB;
        den += xA + xB;
    }
    if (e < r1) {
        int s;
        float x = edge_ex(a_s, e, ad, myh, hd, s);
        float2 hv = *(const float2*)(g_h + (long)s * 64 + f);
        a0 += hv.x * x; a1 += hv.y * x; den += x;
    }

    float iv = 1.f / (den + 1e-16f);
    a0 = a0 * iv + bias[f];
    a1 = a1 * iv + bias[f + 1];
    a0 = a0 > 0.f ? a0 : expm1f(a0);
    a1 = a1 > 0.f ? a1 : expm1f(a1);
    __nv_bfloat16 h0, h1, l0, l1;
    cvt_split(a0, h0, l0); cvt_split(a1, h1, l1);
    *(__nv_bfloat162*)&g_pAh[(long)dstN * 64 + f] = __nv_bfloat162(h0, h1);
    *(__nv_bfloat162*)&g_pAl[(long)dstN * 64 + f] = __nv_bfloat162(l0, l1);
    if (lane == 0) {   // zero buffer A for layer-3 GEMM accumulation
        g_alpha_sA[dstN] = make_float4(0, 0, 0, 0);
        g_alpha_dA[dstN] = make_float4(0, 0, 0, 0);
    }
}

// Layer 3: F=128, C=32, fused head-mean + b3 -> g_z.
__global__ void gat_agg_l3(const float* __restrict__ b3) {
    int dstN = (blockIdx.x * blockDim.x + threadIdx.x) >> 5;
    int lane = threadIdx.x & 31;
    if (dstN >= NNODE) return;
    int r0 = g_rowoff[dstN], r1 = g_rowoff[dstN + 1];
    const float4* a_s = g_alpha_sA;
    float4 ad = g_alpha_dA[dstN];

    const int myh = lane & 3;
    const int hd = lane >> 3;   // head of features lane*4 (C=32)
    float4 acc = make_float4(0, 0, 0, 0);
    float den = 0.f;

    int e = r0;
    for (; e + 1 < r1; e += 2) {
        int sA, sB;
        float xA = edge_ex(a_s, e,     ad, myh, hd, sA);
        float xB = edge_ex(a_s, e + 1, ad, myh, hd, sB);
        float4 vA = ((const float4*)(g_h + (long)sA * 128))[lane];
        float4 vB = ((const float4*)(g_h + (long)sB * 128))[lane];
        acc.x += vA.x * xA + vB.x * xB;  acc.y += vA.y * xA + vB.y * xB;
        acc.z += vA.z * xA + vB.z * xB;  acc.w += vA.w * xA + vB.w * xB;
        den += xA + xB;
    }
    if (e < r1) {
        int s;
        float x = edge_ex(a_s, e, ad, myh, hd, s);
        float4 v = ((const float4*)(g_h + (long)s * 128))[lane];
        acc.x += v.x * x; acc.y += v.y * x; acc.z += v.z * x; acc.w += v.w * x;
        den += x;
    }

    float iv = 1.f / (den + 1e-16f);
    acc.x *= iv; acc.y *= iv; acc.z *= iv; acc.w *= iv;
    #pragma unroll
    for (int o = 8; o <= 16; o <<= 1) {
        acc.x += __shfl_xor_sync(0xffffffffu, acc.x, o);
        acc.y += __shfl_xor_sync(0xffffffffu, acc.y, o);
        acc.z += __shfl_xor_sync(0xffffffffu, acc.z, o);
        acc.w += __shfl_xor_sync(0xffffffffu, acc.w, o);
    }
    if (lane < 8) {
        int c = lane * 4;
        float4 z = make_float4(0.25f * acc.x + b3[c],     0.25f * acc.y + b3[c + 1],
                               0.25f * acc.z + b3[c + 2], 0.25f * acc.w + b3[c + 3]);
        *(float4*)&g_z[(long)dstN * 32 + c] = z;
    }
}

// ---------------- logits: dot over 32 dims, warp per candidate edge ----------------
__global__ void dot_kernel(const void* __restrict__ eli, float* __restrict__ out) {
    int w = (blockIdx.x * blockDim.x + threadIdx.x) >> 5;
    int lane = threadIdx.x & 31;
    if (w >= ECAND) return;
    int use64 = g_idx64_eli;
    int s = load_idx(eli, use64, w);
    int d = load_idx(eli, use64, (long long)ECAND + w);
    float p = g_z[(long)s * 32 + lane] * g_z[(long)d * 32 + lane];
    #pragma unroll
    for (int o = 16; o; o >>= 1) p += __shfl_xor_sync(0xffffffffu, p, o);
    if (lane == 0) out[w] = p;
}

// ---------------- host launch ----------------
extern "C" void kernel_launch(void* const* d_in, const int* in_sizes, int n_in,
                              void* d_out, int out_size) {
    const float* x   = (const float*)d_in[0];
    const void*  ei  = d_in[1];
    const void*  eli = d_in[2];
    const float* W1  = (const float*)d_in[3];
    const float* a1s = (const float*)d_in[4];
    const float* a1d = (const float*)d_in[5];
    const float* b1  = (const float*)d_in[6];
    const float* W2  = (const float*)d_in[7];
    const float* a2s = (const float*)d_in[8];
    const float* a2d = (const float*)d_in[9];
    const float* b2  = (const float*)d_in[10];
    const float* W3  = (const float*)d_in[11];
    const float* a3s = (const float*)d_in[12];
    const float* a3d = (const float*)d_in[13];
    const float* b3  = (const float*)d_in[14];
    float* out = (float*)d_out;

    float* p_h;
    cudaGetSymbolAddress((void**)&p_h, g_h);
    __nv_bfloat16 *p_Ah, *p_Al, *p_Bh, *p_Bl;
    cudaGetSymbolAddress((void**)&p_Ah, g_pAh);
    cudaGetSymbolAddress((void**)&p_Al, g_pAl);
    cudaGetSymbolAddress((void**)&p_Bh, g_pBh);
    cudaGetSymbolAddress((void**)&p_Bl, g_pBl);
    float *p_asA, *p_adA, *p_asB, *p_adB;
    cudaGetSymbolAddress((void**)&p_asA, g_alpha_sA);
    cudaGetSymbolAddress((void**)&p_adA, g_alpha_dA);
    cudaGetSymbolAddress((void**)&p_asB, g_alpha_sB);
    cudaGetSymbolAddress((void**)&p_adB, g_alpha_dB);

    static cudaStream_t sB = nullptr;
    static cudaEvent_t evFork = nullptr, evJoin = nullptr;
    static bool attr_done = false;
    if (!attr_done) {
        cudaFuncSetAttribute(gemm_tc, cudaFuncAttributeMaxDynamicSharedMemorySize, GEMM_SMEM);
        cudaStreamCreateWithFlags(&sB, cudaStreamNonBlocking);
        cudaEventCreateWithFlags(&evFork, cudaEventDisableTiming);
        cudaEventCreateWithFlags(&evJoin, cudaEventDisableTiming);
        attr_done = true;
    }

    const int TB = 256;
    const int nodeWarpBlocks = (NNODE * 32 + TB - 1) / TB;   // warp per node
    const int MB = (NNODE + 127) / 128;                      // GEMM row blocks

    // ---- init (flags + alphaA zero + cnt=1) on main stream ----
    init_detect<<<(NNODE + TB - 1) / TB, TB>>>((const int*)ei, (const int*)eli);
    cudaEventRecord(evFork, 0);

    // ---- fork: CSR build on side stream (depends only on init) ----
    cudaStreamWaitEvent(sB, evFork, 0);
    hist_edges<<<(NEDGE + TB - 1) / TB, TB, 0, sB>>>(ei);
    csr_s1<<<NBLK, 1024, 0, sB>>>();
    csr_s2<<<1, 64, 0, sB>>>();
    csr_s3<<<NBLK, 1024, 0, sB>>>();
    scatter_edges<<<(NEDGE + TB - 1) / TB, TB, 0, sB>>>(ei);
    cudaEventRecord(evJoin, sB);

    // ---- main stream: split + layer-1 GEMM run concurrently with CSR ----
    split_all<<<(NX4 + 122880 + TB - 1) / TB, TB>>>(x, W1, W2, W3);
    gemm_tc<<<dim3(4, MB), 256, GEMM_SMEM>>>(p_Ah, p_Al, p_Bh, p_Bl, p_h,
                                             a1s, a1d, p_asA, p_adA, NNODE, 256, 384, 64);

    // ---- join: aggregates need the CSR ----
    cudaStreamWaitEvent(0, evJoin, 0);
    gat_agg_l1<<<nodeWarpBlocks, TB>>>(b1);

    // ---- Layer 2 ----
    gemm_tc<<<dim3(1, MB), 256, GEMM_SMEM>>>(p_Ah, p_Al, p_Bh + 98304, p_Bl + 98304, p_h,
                                             a2s, a2d, p_asB, p_adB, NNODE, 64, 256, 16);
    gat_agg_l2<<<nodeWarpBlocks, TB>>>(b2);

    // ---- Layer 3 ----
    gemm_tc<<<dim3(2, MB), 256, GEMM_SMEM>>>(p_Ah, p_Al, p_Bh + 114688, p_Bl + 114688, p_h,
                                             a3s, a3d, p_asA, p_adA, NNODE, 128, 64, 32);
    gat_agg_l3<<<nodeWarpBlocks, TB>>>(b3);

    // ---- Candidate-edge logits ----
    dot_kernel<<<(ECAND * 32 + TB - 1) / TB, TB>>>(eli, out);
}

// round 12
// speedup vs baseline: 3.5975x; 1.0009x over previous
#include <cuda_runtime.h>
#include <cuda_bf16.h>
#include <math.h>
#include <stdint.h>

#define NNODE   50000
#define NEDGE   800000
#define ET      850000      // NEDGE + NNODE self loops
#define ECAND   200000
#define MPAD    50048       // ceil(NNODE/128)*128
#define KMAX    384
#define NBLK    49          // ceil(NNODE/1024)

// ---------------- scratch (device globals; no allocation) ----------------
__device__ __align__(16) __nv_bfloat16 g_pAh[MPAD * KMAX];  // A hi plane
__device__ __align__(16) __nv_bfloat16 g_pAl[MPAD * KMAX];  // A lo plane
// packed W planes [N][K]: L1 @0 (384*256), L2 @98304 (256*64), L3 @114688 (64*128)
__device__ __align__(16) __nv_bfloat16 g_pBh[122880];
__device__ __align__(16) __nv_bfloat16 g_pBl[122880];
__device__ __align__(16) float  g_h[NNODE * 256];           // GEMM output (fp32)
// ping-pong alpha buffers
__device__ float4 g_alpha_sA[NNODE];
__device__ float4 g_alpha_dA[NNODE];
__device__ float4 g_alpha_sB[NNODE];
__device__ float4 g_alpha_dB[NNODE];
__device__ int    g_esrc[ET];
__device__ int    g_rowoff[NNODE + 1];
__device__ int    g_cnt[NNODE];
__device__ int    g_cursor[NNODE];
__device__ int    g_bsum[64];
__device__ int    g_boff[64];
__device__ __align__(16) float g_z[NNODE * 32];
__device__ int    g_idx64_ei;
__device__ int    g_idx64_eli;

// ---------------- helpers ----------------
__device__ __forceinline__ float lrelu(float v) { return v > 0.f ? v : 0.2f * v; }

__device__ __forceinline__ float sel4(float4 v, int h) {
    return h < 2 ? (h == 0 ? v.x : v.y) : (h == 2 ? v.z : v.w);
}

__device__ __forceinline__ int load_idx(const void* p, int use64, long long pos) {
    return use64 ? (int)((const long long*)p)[pos] : ((const int*)p)[pos];
}

__device__ __forceinline__ void cvt_split(float v, __nv_bfloat16& h, __nv_bfloat16& l) {
    h = __float2bfloat16(v);
    l = __float2bfloat16(v - __bfloat162float(h));
}

__device__ __forceinline__ void cp16(const void* s, const void* g) {
    uint32_t sa = (uint32_t)__cvta_generic_to_shared(s);
    asm volatile("cp.async.cg.shared.global [%0], [%1], 16;\n" :: "r"(sa), "l"(g));
}

// per-edge: ex for one head, computed warp-wide (lane L evals head L&3),
// fetched per-lane via shfl. No max subtraction (softmax is shift-invariant;
// |e| <~ 15 here so exp stays far from fp32 limits).
__device__ __forceinline__ float edge_ex(const float4* __restrict__ a_s,
                                         int e, float4 ad, int myh,
                                         int want, int& src) {
    src = g_esrc[e];
    float4 s = a_s[src];
    float eh = sel4(make_float4(lrelu(s.x + ad.x), lrelu(s.y + ad.y),
                                lrelu(s.z + ad.z), lrelu(s.w + ad.w)), myh);
    float ex = __expf(eh);
    return __shfl_sync(0xffffffffu, ex, want);
}

__device__ __forceinline__ void edge_ex2(const float4* __restrict__ a_s,
                                         int e, float4 ad, int myh,
                                         int w0, int w1, float& ex0, float& ex1, int& src) {
    src = g_esrc[e];
    float4 s = a_s[src];
    float eh = sel4(make_float4(lrelu(s.x + ad.x), lrelu(s.y + ad.y),
                                lrelu(s.z + ad.z), lrelu(s.w + ad.w)), myh);
    float ex = __expf(eh);
    ex0 = __shfl_sync(0xffffffffu, ex, w0);
    ex1 = __shfl_sync(0xffffffffu, ex, w1);
}

// ---------------- init: dtype detect + cnt=1 + alphaA zero ----------------
__global__ void init_detect(const int* __restrict__ ei, const int* __restrict__ eli) {
    int i = blockIdx.x * blockDim.x + threadIdx.x;
    if (i < NNODE) {
        g_cnt[i] = 1;
        g_alpha_sA[i] = make_float4(0, 0, 0, 0);
        g_alpha_dA[i] = make_float4(0, 0, 0, 0);
    }
    if (i == 0) {
        int ok = 1;
        #pragma unroll
        for (int j = 1; j < 64; j += 2) if (ei[j] != 0) { ok = 0; break; }
        g_idx64_ei = ok;
        ok = 1;
        #pragma unroll
        for (int j = 1; j < 64; j += 2) if (eli[j] != 0) { ok = 0; break; }
        g_idx64_eli = ok;
    }
}

// ================= operand splitting (x + all weights, one launch) =========
#define NX4 (NNODE * 384 / 4)
__global__ void split_all(const float* __restrict__ x, const float* __restrict__ W1,
                          const float* __restrict__ W2, const float* __restrict__ W3) {
    int t = blockIdx.x * blockDim.x + threadIdx.x;
    if (t < NX4) {
        long i = (long)t * 4;
        float4 v = *(const float4*)(x + i);
        __nv_bfloat16 h0, h1, h2, h3, l0, l1, l2, l3;
        cvt_split(v.x, h0, l0); cvt_split(v.y, h1, l1);
        cvt_split(v.z, h2, l2); cvt_split(v.w, h3, l3);
        *(__nv_bfloat162*)&g_pAh[i]     = __nv_bfloat162(h0, h1);
        *(__nv_bfloat162*)&g_pAh[i + 2] = __nv_bfloat162(h2, h3);
        *(__nv_bfloat162*)&g_pAl[i]     = __nv_bfloat162(l0, l1);
        *(__nv_bfloat162*)&g_pAl[i + 2] = __nv_bfloat162(l2, l3);
        return;
    }
    int i = t - NX4;
    const float* W; int K, N, off, li;
    if (i < 98304)       { W = W1; K = 384; N = 256; off = 0;      li = i; }
    else if (i < 114688) { W = W2; K = 256; N = 64;  off = 98304;  li = i - 98304; }
    else if (i < 122880) { W = W3; K = 64;  N = 128; off = 114688; li = i - 114688; }
    else return;
    int k = li / N, n = li % N;
    __nv_bfloat16 h, l;
    cvt_split(W[li], h, l);
    g_pBh[off + n * K + k] = h;
    g_pBl[off + n * K + k] = l;
}

// ================= CSR build (parallel scan) =================
__global__ void hist_edges(const void* __restrict__ ei) {
    int e = blockIdx.x * blockDim.x + threadIdx.x;
    if (e >= NEDGE) return;
    int dst = load_idx(ei, g_idx64_ei, (long long)NEDGE + e);
    atomicAdd(&g_cnt[dst], 1);
}

__global__ void csr_s1() {
    __shared__ int ws[32];
    int i = blockIdx.x * 1024 + threadIdx.x;
    int lane = threadIdx.x & 31, wid = threadIdx.x >> 5;
    int v = (i < NNODE) ? g_cnt[i] : 0;
    #pragma unroll
    for (int o = 16; o; o >>= 1) v += __shfl_xor_sync(0xffffffffu, v, o);
    if (lane == 0) ws[wid] = v;
    __syncthreads();
    if (threadIdx.x < 32) {
        int s = ws[threadIdx.x];
        #pragma unroll
        for (int o = 16; o; o >>= 1) s += __shfl_xor_sync(0xffffffffu, s, o);
        if (threadIdx.x == 0) g_bsum[blockIdx.x] = s;
    }
}

__global__ void csr_s2() {
    __shared__ int w0tot;
    int t = threadIdx.x;
    int lane = t & 31, w = t >> 5;
    int v = (t < NBLK) ? g_bsum[t] : 0;
    int x = v;
    #pragma unroll
    for (int o = 1; o < 32; o <<= 1) {
        int y = __shfl_up_sync(0xffffffffu, x, o);
        if (lane >= o) x += y;
    }
    if (t == 31) w0tot = x;
    __syncthreads();
    if (w == 1) x += w0tot;
    if (t < NBLK) g_boff[t] = x - v;
}

__global__ void csr_s3() {
    __shared__ int ws[32];
    int i = blockIdx.x * 1024 + threadIdx.x;
    int lane = threadIdx.x & 31, wid = threadIdx.x >> 5;
    int v = (i < NNODE) ? g_cnt[i] : 0;
    int x = v;
    #pragma unroll
    for (int o = 1; o < 32; o <<= 1) {
        int y = __shfl_up_sync(0xffffffffu, x, o);
        if (lane >= o) x += y;
    }
    if (lane == 31) ws[wid] = x;
    __syncthreads();
    if (wid == 0) {
        int s = ws[lane];
        #pragma unroll
        for (int o = 1; o < 32; o <<= 1) {
            int y = __shfl_up_sync(0xffffffffu, s, o);
            if (lane >= o) s += y;
        }
        ws[lane] = s;
    }
    __syncthreads();
    int ex = x - v + (wid ? ws[wid - 1] : 0) + g_boff[blockIdx.x];
    if (i < NNODE) {
        g_rowoff[i] = ex;
        g_cursor[i] = ex + 1;
        g_esrc[ex] = i;
        if (i == NNODE - 1) g_rowoff[NNODE] = ex + v;
    }
}

__global__ void scatter_edges(const void* __restrict__ ei) {
    int e = blockIdx.x * blockDim.x + threadIdx.x;
    if (e >= NEDGE) return;
    int use64 = g_idx64_ei;
    int src = load_idx(ei, use64, e);
    int dst = load_idx(ei, use64, (long long)NEDGE + e);
    int pos = atomicAdd(&g_cursor[dst], 1);
    g_esrc[pos] = src;
}

// ======= split-bf16 mma.sync GEMM, 3-stage cp.async + fused alpha =========
#define BKP 40
#define A_SZ (128 * BKP)
#define B_SZ (64 * BKP)
#define STG  (2 * A_SZ + 2 * B_SZ)
#define NSTAGE 3
#define GEMM_SMEM (NSTAGE * STG * 2)   // 92160 bytes

__device__ __forceinline__ void mma16816(float* c, const uint32_t* a, const uint32_t* b) {
    asm volatile(
        "mma.sync.aligned.m16n8k16.row.col.f32.bf16.bf16.f32 "
        "{%0,%1,%2,%3}, {%4,%5,%6,%7}, {%8,%9}, {%0,%1,%2,%3};\n"
        : "+f"(c[0]), "+f"(c[1]), "+f"(c[2]), "+f"(c[3])
        : "r"(a[0]), "r"(a[1]), "r"(a[2]), "r"(a[3]), "r"(b[0]), "r"(b[1]));
}

__global__ __launch_bounds__(256) void gemm_tc(const __nv_bfloat16* __restrict__ Ah,
                                               const __nv_bfloat16* __restrict__ Al,
                                               const __nv_bfloat16* __restrict__ Bth,
                                               const __nv_bfloat16* __restrict__ Btl,
                                               float* __restrict__ C,
                                               const float* __restrict__ a_s,
                                               const float* __restrict__ a_d,
                                               float* __restrict__ alpha_s_out,
                                               float* __restrict__ alpha_d_out,
                                               int M, int N, int K, int Ch) {
    extern __shared__ __nv_bfloat16 sm[];
    const int tid  = threadIdx.x;
    const int lane = tid & 31;
    const int warp = tid >> 5;
    const int wm   = warp & 3;
    const int wn   = warp >> 2;
    const int tr   = lane >> 2;
    const int tc   = lane & 3;
    const int row0 = blockIdx.y * 128;
    const int col0 = blockIdx.x * 64;
    const int KT   = K / 32;

    float acc[2][4][4] = {};

    // issue loads for k-tile kt into stage s; ALWAYS commits exactly one group
    auto stage_load = [&](int s, int kt) {
        if (kt < KT) {
            int k0 = kt * 32;
            __nv_bfloat16* sAh = sm + s * STG;
            __nv_bfloat16* sAl = sAh + A_SZ;
            __nv_bfloat16* sBh = sAl + A_SZ;
            __nv_bfloat16* sBl = sBh + B_SZ;
            #pragma unroll
            for (int i = 0; i < 2; i++) {
                int id = tid + i * 256;
                int row = id >> 2, c = id & 3;
                long gofs = (long)(row0 + row) * K + k0 + c * 8;
                cp16(sAh + row * BKP + c * 8, Ah + gofs);
                cp16(sAl + row * BKP + c * 8, Al + gofs);
            }
            {
                int n = tid >> 2, c = tid & 3;
                long gofs = (long)(col0 + n) * K + k0 + c * 8;
                cp16(sBh + n * BKP + c * 8, Bth + gofs);
                cp16(sBl + n * BKP + c * 8, Btl + gofs);
            }
        }
        asm volatile("cp.async.commit_group;\n" ::: "memory");
    };

    auto compute = [&](int s) {
        const __nv_bfloat16* sAh = sm + s * STG;
        const __nv_bfloat16* sAl = sAh + A_SZ;
        const __nv_bfloat16* sBh = sAl + A_SZ;
        const __nv_bfloat16* sBl = sBh + B_SZ;
        #pragma unroll
        for (int ks = 0; ks < 32; ks += 16) {
            uint32_t ah[2][4], al[2][4], bh[4][2], bl[4][2];
            #pragma unroll
            for (int f = 0; f < 2; f++) {
                int r = wm * 32 + f * 16 + tr;
                int kk = ks + tc * 2;
                ah[f][0] = *(const uint32_t*)&sAh[r * BKP + kk];
                ah[f][1] = *(const uint32_t*)&sAh[(r + 8) * BKP + kk];
                ah[f][2] = *(const uint32_t*)&sAh[r * BKP + kk + 8];
                ah[f][3] = *(const uint32_t*)&sAh[(r + 8) * BKP + kk + 8];
                al[f][0] = *(const uint32_t*)&sAl[r * BKP + kk];
                al[f][1] = *(const uint32_t*)&sAl[(r + 8) * BKP + kk];
                al[f][2] = *(const uint32_t*)&sAl[r * BKP + kk + 8];
                al[f][3] = *(const uint32_t*)&sAl[(r + 8) * BKP + kk + 8];
            }
            #pragma unroll
            for (int g = 0; g < 4; g++) {
                int n = wn * 32 + g * 8 + tr;
                int kk = ks + tc * 2;
                bh[g][0] = *(const uint32_t*)&sBh[n * BKP + kk];
                bh[g][1] = *(const uint32_t*)&sBh[n * BKP + kk + 8];
                bl[g][0] = *(const uint32_t*)&sBl[n * BKP + kk];
                bl[g][1] = *(const uint32_t*)&sBl[n * BKP + kk + 8];
            }
            #pragma unroll
            for (int f = 0; f < 2; f++)
                #pragma unroll
                for (int g = 0; g < 4; g++) {
                    mma16816(acc[f][g], ah[f], bh[g]);
                    mma16816(acc[f][g], ah[f], bl[g]);
                    mma16816(acc[f][g], al[f], bh[g]);
                }
        }
    };

    // ---- 3-stage pipeline: prologue loads stages 0,1; loop waits depth-1 ----
    stage_load(0, 0);
    stage_load(1, 1);
    for (int kt = 0; kt < KT; kt++) {
        asm volatile("cp.async.wait_group 1;\n" ::: "memory");  // stage kt%3 ready
        __syncthreads();                                        // all warps past kt-1
        stage_load((kt + 2) % NSTAGE, kt + 2);                  // refill consumed buffer
        compute(kt % NSTAGE);
    }

    // ---- store C ----
    #pragma unroll
    for (int f = 0; f < 2; f++) {
        int r = row0 + wm * 32 + f * 16 + tr;
        #pragma unroll
        for (int g = 0; g < 4; g++) {
            int c = col0 + wn * 32 + g * 8 + tc * 2;
            if (r < M)
                *(float2*)&C[(long)r * N + c] = make_float2(acc[f][g][0], acc[f][g][1]);
            if (r + 8 < M)
                *(float2*)&C[(long)(r + 8) * N + c] = make_float2(acc[f][g][2], acc[f][g][3]);
        }
    }

    // ---- fused alpha epilogue ----
    float asv[8], adv[8];
    #pragma unroll
    for (int g = 0; g < 4; g++) {
        int colg = col0 + wn * 32 + g * 8 + tc * 2;
        asv[g * 2] = __ldg(&a_s[colg]); asv[g * 2 + 1] = __ldg(&a_s[colg + 1]);
        adv[g * 2] = __ldg(&a_d[colg]); adv[g * 2 + 1] = __ldg(&a_d[colg + 1]);
    }
    const int hlo = (col0 + wn * 32) / Ch;
    const bool two_heads = (Ch == 16);
    #pragma unroll
    for (int f = 0; f < 2; f++) {
        #pragma unroll
        for (int half = 0; half < 2; half++) {
            int row = row0 + wm * 32 + f * 16 + tr + half * 8;
            float psg[4], pdg[4];
            #pragma unroll
            for (int g = 0; g < 4; g++) {
                float a0 = acc[f][g][half * 2], a1 = acc[f][g][half * 2 + 1];
                psg[g] = a0 * asv[g * 2] + a1 * asv[g * 2 + 1];
                pdg[g] = a0 * adv[g * 2] + a1 * adv[g * 2 + 1];
            }
            float s0 = psg[0] + psg[1], s1 = psg[2] + psg[3];
            float d0 = pdg[0] + pdg[1], d1 = pdg[2] + pdg[3];
            #pragma unroll
            for (int o = 1; o <= 2; o <<= 1) {
                s0 += __shfl_xor_sync(0xffffffffu, s0, o);
                s1 += __shfl_xor_sync(0xffffffffu, s1, o);
                d0 += __shfl_xor_sync(0xffffffffu, d0, o);
                d1 += __shfl_xor_sync(0xffffffffu, d1, o);
            }
            if (tc == 0 && row < M) {
                if (two_heads) {
                    atomicAdd(&alpha_s_out[row * 4 + hlo], s0);
                    atomicAdd(&alpha_s_out[row * 4 + hlo + 1], s1);
                    atomicAdd(&alpha_d_out[row * 4 + hlo], d0);
                    atomicAdd(&alpha_d_out[row * 4 + hlo + 1], d1);
                } else {
                    atomicAdd(&alpha_s_out[row * 4 + hlo], s0 + s1);
                    atomicAdd(&alpha_d_out[row * 4 + hlo], d0 + d1);
                }
            }
        }
    }
}

// ========== fused softmax+aggregate kernels (single pass, no max) ==========

// Layer 1: F=256, C=64 -> elu(out+bias) -> split bf16 planes.
__global__ void gat_agg_l1(const float* __restrict__ bias) {
    int dstN = (blockIdx.x * blockDim.x + threadIdx.x) >> 5;
    int lane = threadIdx.x & 31;
    if (dstN >= NNODE) return;
    int r0 = g_rowoff[dstN], r1 = g_rowoff[dstN + 1];
    const float4* a_s = g_alpha_sA;
    float4 ad = g_alpha_dA[dstN];

    const int myh = lane & 3;
    const int hd0 = lane >> 4;
    const int hd1 = 2 + (lane >> 4);
    float4 acc0 = make_float4(0, 0, 0, 0), acc1 = make_float4(0, 0, 0, 0);
    float den0 = 0.f, den1 = 0.f;

    int e = r0;
    for (; e + 1 < r1; e += 2) {
        int sA, sB; float xA0, xA1, xB0, xB1;
        edge_ex2(a_s, e,     ad, myh, hd0, hd1, xA0, xA1, sA);
        edge_ex2(a_s, e + 1, ad, myh, hd0, hd1, xB0, xB1, sB);
        const float4* hA = (const float4*)(g_h + (long)sA * 256);
        const float4* hB = (const float4*)(g_h + (long)sB * 256);
        float4 vA0 = hA[lane], vA1 = hA[lane + 32];
        float4 vB0 = hB[lane], vB1 = hB[lane + 32];
        acc0.x += vA0.x * xA0 + vB0.x * xB0;  acc0.y += vA0.y * xA0 + vB0.y * xB0;
        acc0.z += vA0.z * xA0 + vB0.z * xB0;  acc0.w += vA0.w * xA0 + vB0.w * xB0;
        acc1.x += vA1.x * xA1 + vB1.x * xB1;  acc1.y += vA1.y * xA1 + vB1.y * xB1;
        acc1.z += vA1.z * xA1 + vB1.z * xB1;  acc1.w += vA1.w * xA1 + vB1.w * xB1;
        den0 += xA0 + xB0;  den1 += xA1 + xB1;
    }
    if (e < r1) {
        int s; float x0, x1;
        edge_ex2(a_s, e, ad, myh, hd0, hd1, x0, x1, s);
        const float4* hp = (const float4*)(g_h + (long)s * 256);
        float4 v0 = hp[lane], v1 = hp[lane + 32];
        acc0.x += v0.x * x0; acc0.y += v0.y * x0; acc0.z += v0.z * x0; acc0.w += v0.w * x0;
        acc1.x += v1.x * x1; acc1.y += v1.y * x1; acc1.z += v1.z * x1; acc1.w += v1.w * x1;
        den0 += x0; den1 += x1;
    }

    float iv0 = 1.f / (den0 + 1e-16f), iv1 = 1.f / (den1 + 1e-16f);
    #pragma unroll
    for (int c = 0; c < 2; c++) {
        int f = lane * 4 + c * 128;
        float iv = c == 0 ? iv0 : iv1;
        float4 r = c == 0 ? acc0 : acc1;
        r.x = r.x * iv + bias[f];     r.y = r.y * iv + bias[f + 1];
        r.z = r.z * iv + bias[f + 2]; r.w = r.w * iv + bias[f + 3];
        r.x = r.x > 0.f ? r.x : expm1f(r.x);
        r.y = r.y > 0.f ? r.y : expm1f(r.y);
        r.z = r.z > 0.f ? r.z : expm1f(r.z);
        r.w = r.w > 0.f ? r.w : expm1f(r.w);
        __nv_bfloat16 h0, h1, h2, h3, l0, l1, l2, l3;
        cvt_split(r.x, h0, l0); cvt_split(r.y, h1, l1);
        cvt_split(r.z, h2, l2); cvt_split(r.w, h3, l3);
        long o = (long)dstN * 256 + f;
        *(__nv_bfloat162*)&g_pAh[o]     = __nv_bfloat162(h0, h1);
        *(__nv_bfloat162*)&g_pAh[o + 2] = __nv_bfloat162(h2, h3);
        *(__nv_bfloat162*)&g_pAl[o]     = __nv_bfloat162(l0, l1);
        *(__nv_bfloat162*)&g_pAl[o + 2] = __nv_bfloat162(l2, l3);
    }
    if (lane == 0) {
        g_alpha_sB[dstN] = make_float4(0, 0, 0, 0);
        g_alpha_dB[dstN] = make_float4(0, 0, 0, 0);
    }
}

// Layer 2: F=64, C=16 -> elu(out+bias) -> split bf16 planes.
__global__ void gat_agg_l2(const float* __restrict__ bias) {
    int dstN = (blockIdx.x * blockDim.x + threadIdx.x) >> 5;
    int lane = threadIdx.x & 31;
    if (dstN >= NNODE) return;
    int r0 = g_rowoff[dstN], r1 = g_rowoff[dstN + 1];
    const float4* a_s = g_alpha_sB;
    float4 ad = g_alpha_dB[dstN];

    const int myh = lane & 3;
    const int f = lane * 2;
    const int hd = lane >> 3;
    float a0 = 0.f, a1 = 0.f, den = 0.f;

    int e = r0;
    for (; e + 1 < r1; e += 2) {
        int sA, sB;
        float xA = edge_ex(a_s, e,     ad, myh, hd, sA);
        float xB = edge_ex(a_s, e + 1, ad, myh, hd, sB);
        float2 hA = *(const float2*)(g_h + (long)sA * 64 + f);
        float2 hB = *(const float2*)(g_h + (long)sB * 64 + f);
        a0 += hA.x * xA + hB.x * xB;
        a1 += hA.y * xA + hB.y * xB;
        den += xA + xB;
    }
    if (e < r1) {
        int s;
        float x = edge_ex(a_s, e, ad, myh, hd, s);
        float2 hv = *(const float2*)(g_h + (long)s * 64 + f);
        a0 += hv.x * x; a1 += hv.y * x; den += x;
    }

    float iv = 1.f / (den + 1e-16f);
    a0 = a0 * iv + bias[f];
    a1 = a1 * iv + bias[f + 1];
    a0 = a0 > 0.f ? a0 : expm1f(a0);
    a1 = a1 > 0.f ? a1 : expm1f(a1);
    __nv_bfloat16 h0, h1, l0, l1;
    cvt_split(a0, h0, l0); cvt_split(a1, h1, l1);
    *(__nv_bfloat162*)&g_pAh[(long)dstN * 64 + f] = __nv_bfloat162(h0, h1);
    *(__nv_bfloat162*)&g_pAl[(long)dstN * 64 + f] = __nv_bfloat162(l0, l1);
    if (lane == 0) {
        g_alpha_sA[dstN] = make_float4(0, 0, 0, 0);
        g_alpha_dA[dstN] = make_float4(0, 0, 0, 0);
    }
}

// Layer 3: F=128, C=32, fused head-mean + b3 -> g_z.
__global__ void gat_agg_l3(const float* __restrict__ b3) {
    int dstN = (blockIdx.x * blockDim.x + threadIdx.x) >> 5;
    int lane = threadIdx.x & 31;
    if (dstN >= NNODE) return;
    int r0 = g_rowoff[dstN], r1 = g_rowoff[dstN + 1];
    const float4* a_s = g_alpha_sA;
    float4 ad = g_alpha_dA[dstN];

    const int myh = lane & 3;
    const int hd = lane >> 3;
    float4 acc = make_float4(0, 0, 0, 0);
    float den = 0.f;

    int e = r0;
    for (; e + 1 < r1; e += 2) {
        int sA, sB;
        float xA = edge_ex(a_s, e,     ad, myh, hd, sA);
        float xB = edge_ex(a_s, e + 1, ad, myh, hd, sB);
        float4 vA = ((const float4*)(g_h + (long)sA * 128))[lane];
        float4 vB = ((const float4*)(g_h + (long)sB * 128))[lane];
        acc.x += vA.x * xA + vB.x * xB;  acc.y += vA.y * xA + vB.y * xB;
        acc.z += vA.z * xA + vB.z * xB;  acc.w += vA.w * xA + vB.w * xB;
        den += xA + xB;
    }
    if (e < r1) {
        int s;
        float x = edge_ex(a_s, e, ad, myh, hd, s);
        float4 v = ((const float4*)(g_h + (long)s * 128))[lane];
        acc.x += v.x * x; acc.y += v.y * x; acc.z += v.z * x; acc.w += v.w * x;
        den += x;
    }

    float iv = 1.f / (den + 1e-16f);
    acc.x *= iv; acc.y *= iv; acc.z *= iv; acc.w *= iv;
    #pragma unroll
    for (int o = 8; o <= 16; o <<= 1) {
        acc.x += __shfl_xor_sync(0xffffffffu, acc.x, o);
        acc.y += __shfl_xor_sync(0xffffffffu, acc.y, o);
        acc.z += __shfl_xor_sync(0xffffffffu, acc.z, o);
        acc.w += __shfl_xor_sync(0xffffffffu, acc.w, o);
    }
    if (lane < 8) {
        int c = lane * 4;
        float4 z = make_float4(0.25f * acc.x + b3[c],     0.25f * acc.y + b3[c + 1],
                               0.25f * acc.z + b3[c + 2], 0.25f * acc.w + b3[c + 3]);
        *(float4*)&g_z[(long)dstN * 32 + c] = z;
    }
}

// ---------------- logits: dot over 32 dims, warp per candidate edge ----------------
__global__ void dot_kernel(const void* __restrict__ eli, float* __restrict__ out) {
    int w = (blockIdx.x * blockDim.x + threadIdx.x) >> 5;
    int lane = threadIdx.x & 31;
    if (w >= ECAND) return;
    int use64 = g_idx64_eli;
    int s = load_idx(eli, use64, w);
    int d = load_idx(eli, use64, (long long)ECAND + w);
    float p = g_z[(long)s * 32 + lane] * g_z[(long)d * 32 + lane];
    #pragma unroll
    for (int o = 16; o; o >>= 1) p += __shfl_xor_sync(0xffffffffu, p, o);
    if (lane == 0) out[w] = p;
}

// ---------------- host launch ----------------
extern "C" void kernel_launch(void* const* d_in, const int* in_sizes, int n_in,
                              void* d_out, int out_size) {
    const float* x   = (const float*)d_in[0];
    const void*  ei  = d_in[1];
    const void*  eli = d_in[2];
    const float* W1  = (const float*)d_in[3];
    const float* a1s = (const float*)d_in[4];
    const float* a1d = (const float*)d_in[5];
    const float* b1  = (const float*)d_in[6];
    const float* W2  = (const float*)d_in[7];
    const float* a2s = (const float*)d_in[8];
    const float* a2d = (const float*)d_in[9];
    const float* b2  = (const float*)d_in[10];
    const float* W3  = (const float*)d_in[11];
    const float* a3s = (const float*)d_in[12];
    const float* a3d = (const float*)d_in[13];
    const float* b3  = (const float*)d_in[14];
    float* out = (float*)d_out;

    float* p_h;
    cudaGetSymbolAddress((void**)&p_h, g_h);
    __nv_bfloat16 *p_Ah, *p_Al, *p_Bh, *p_Bl;
    cudaGetSymbolAddress((void**)&p_Ah, g_pAh);
    cudaGetSymbolAddress((void**)&p_Al, g_pAl);
    cudaGetSymbolAddress((void**)&p_Bh, g_pBh);
    cudaGetSymbolAddress((void**)&p_Bl, g_pBl);
    float *p_asA, *p_adA, *p_asB, *p_adB;
    cudaGetSymbolAddress((void**)&p_asA, g_alpha_sA);
    cudaGetSymbolAddress((void**)&p_adA, g_alpha_dA);
    cudaGetSymbolAddress((void**)&p_asB, g_alpha_sB);
    cudaGetSymbolAddress((void**)&p_adB, g_alpha_dB);

    static cudaStream_t sB = nullptr;
    static cudaEvent_t evFork = nullptr, evJoin = nullptr;
    static bool attr_done = false;
    if (!attr_done) {
        cudaFuncSetAttribute(gemm_tc, cudaFuncAttributeMaxDynamicSharedMemorySize, GEMM_SMEM);
        cudaStreamCreateWithFlags(&sB, cudaStreamNonBlocking);
        cudaEventCreateWithFlags(&evFork, cudaEventDisableTiming);
        cudaEventCreateWithFlags(&evJoin, cudaEventDisableTiming);
        attr_done = true;
    }

    const int TB = 256;
    const int nodeWarpBlocks = (NNODE * 32 + TB - 1) / TB;
    const int MB = (NNODE + 127) / 128;

    // ---- init on main stream ----
    init_detect<<<(NNODE + TB - 1) / TB, TB>>>((const int*)ei, (const int*)eli);
    cudaEventRecord(evFork, 0);

    // ---- fork: CSR build on side stream ----
    cudaStreamWaitEvent(sB, evFork, 0);
    hist_edges<<<(NEDGE + TB - 1) / TB, TB, 0, sB>>>(ei);
    csr_s1<<<NBLK, 1024, 0, sB>>>();
    csr_s2<<<1, 64, 0, sB>>>();
    csr_s3<<<NBLK, 1024, 0, sB>>>();
    scatter_edges<<<(NEDGE + TB - 1) / TB, TB, 0, sB>>>(ei);
    cudaEventRecord(evJoin, sB);

    // ---- main stream: split + layer-1 GEMM concurrently with CSR ----
    split_all<<<(NX4 + 122880 + TB - 1) / TB, TB>>>(x, W1, W2, W3);
    gemm_tc<<<dim3(4, MB), 256, GEMM_SMEM>>>(p_Ah, p_Al, p_Bh, p_Bl, p_h,
                                             a1s, a1d, p_asA, p_adA, NNODE, 256, 384, 64);

    // ---- join: aggregates need the CSR ----
    cudaStreamWaitEvent(0, evJoin, 0);
    gat_agg_l1<<<nodeWarpBlocks, TB>>>(b1);

    // ---- Layer 2 ----
    gemm_tc<<<dim3(1, MB), 256, GEMM_SMEM>>>(p_Ah, p_Al, p_Bh + 98304, p_Bl + 98304, p_h,
                                             a2s, a2d, p_asB, p_adB, NNODE, 64, 256, 16);
    gat_agg_l2<<<nodeWarpBlocks, TB>>>(b2);

    // ---- Layer 3 ----
    gemm_tc<<<dim3(2, MB), 256, GEMM_SMEM>>>(p_Ah, p_Al, p_Bh + 114688, p_Bl + 114688, p_h,
                                             a3s, a3d, p_asA, p_adA, NNODE, 128, 64, 32);
    gat_agg_l3<<<nodeWarpBlocks, TB>>>(b3);

    // ---- Candidate-edge logits ----
    dot_kernel<<<(ECAND * 32 + TB - 1) / TB, TB>>>(eli, out);
}